// round 1
// baseline (speedup 1.0000x reference)
#include <cuda_runtime.h>
#include <cuda_bf16.h>
#include <math.h>

#define BATCH 2
#define SEQ 2048
#define DMODEL 1024
#define DINNER 2048
#define DSTATE 16
#define DTRANK 64
#define DXL 96           // DT_RANK + 2*D_STATE
#define NROWS (BATCH*SEQ) // 4096

// ---------------- scratch (allocation-free: __device__ globals) ----------------
__device__ float g_xz[(size_t)NROWS * 2 * DINNER];      // 64 MB  (x | z)
__device__ float g_u[(size_t)NROWS * DINNER];           // 32 MB
__device__ float g_xdbl[(size_t)NROWS * DXL];           // 1.5 MB (dt | B | C)
__device__ float g_delta[(size_t)NROWS * DINNER];       // 32 MB
__device__ float g_y[(size_t)NROWS * DINNER];           // 32 MB

// ---------------- generic SGEMM: C[m][n] = sum_k A[m][k] * B[n][k] -------------
// EPI==0: none.  EPI==1: softplus(v + bias[n])
template <int EPI>
__global__ __launch_bounds__(256, 2)
void sgemm_nt(const float* __restrict__ A, int lda,
              const float* __restrict__ Bm, int ldb,
              float* __restrict__ C, int ldc,
              int M, int N, int K,
              const float* __restrict__ bias) {
    __shared__ float As[16][128 + 4];
    __shared__ float Bs[16][128 + 4];
    const int tid = threadIdx.x;
    const int bm = blockIdx.y * 128;
    const int bn = blockIdx.x * 128;
    const int tx = tid & 15;        // 0..15  -> col group
    const int ty = tid >> 4;        // 0..15  -> row group
    float acc[8][8];
#pragma unroll
    for (int i = 0; i < 8; i++)
#pragma unroll
        for (int j = 0; j < 8; j++) acc[i][j] = 0.f;

    for (int k0 = 0; k0 < K; k0 += 16) {
#pragma unroll
        for (int i = 0; i < 8; i++) {
            int idx = tid + i * 256;
            int mm = idx >> 4, kk = idx & 15;
            int gm = bm + mm, gk = k0 + kk;
            As[kk][mm] = (gm < M && gk < K) ? A[(size_t)gm * lda + gk] : 0.f;
        }
#pragma unroll
        for (int i = 0; i < 8; i++) {
            int idx = tid + i * 256;
            int nn = idx >> 4, kk = idx & 15;
            int gn = bn + nn, gk = k0 + kk;
            Bs[kk][nn] = (gn < N && gk < K) ? Bm[(size_t)gn * ldb + gk] : 0.f;
        }
        __syncthreads();
#pragma unroll
        for (int kk = 0; kk < 16; kk++) {
            float ar[8], br[8];
#pragma unroll
            for (int i = 0; i < 8; i++) ar[i] = As[kk][ty * 8 + i];
#pragma unroll
            for (int j = 0; j < 8; j++) br[j] = Bs[kk][tx * 8 + j];
#pragma unroll
            for (int i = 0; i < 8; i++)
#pragma unroll
                for (int j = 0; j < 8; j++) acc[i][j] += ar[i] * br[j];
        }
        __syncthreads();
    }

#pragma unroll
    for (int i = 0; i < 8; i++) {
        int gm = bm + ty * 8 + i;
        if (gm >= M) continue;
#pragma unroll
        for (int j = 0; j < 8; j++) {
            int gn = bn + tx * 8 + j;
            if (gn >= N) continue;
            float v = acc[i][j];
            if (EPI == 1) {
                v += bias[gn];
                v = (v > 20.f) ? v : log1pf(expf(v));   // softplus
            }
            C[(size_t)gm * ldc + gn] = v;
        }
    }
}

// ---------------- depthwise causal conv (d_conv=4) + SiLU -> u ------------------
__global__ void conv_silu_kernel(const float* __restrict__ xz,
                                 const float* __restrict__ w,
                                 const float* __restrict__ bias,
                                 float* __restrict__ u) {
    int idx = blockIdx.x * blockDim.x + threadIdx.x;
    if (idx >= NROWS * DINNER) return;
    int c = idx % DINNER;
    int row = idx / DINNER;        // b*SEQ + t
    int t = row % SEQ;
    int b = row / SEQ;
    float acc = bias[c];
#pragma unroll
    for (int k = 0; k < 4; k++) {
        int tt = t - 3 + k;
        if (tt >= 0)
            acc += xz[((size_t)(b * SEQ + tt)) * (2 * DINNER) + c] * w[c * 4 + k];
    }
    u[idx] = acc / (1.f + expf(-acc));   // silu
}

// ---------------- selective scan --------------------------------------------
// 128 threads = 8 channels x 16 states. Chunks of 64 timesteps staged in smem.
#define SCAN_T 64
__global__ __launch_bounds__(128, 8)
void scan_kernel(const float* __restrict__ delta,
                 const float* __restrict__ xdbl,
                 const float* __restrict__ u,
                 const float* __restrict__ xz,
                 const float* __restrict__ A_log,
                 const float* __restrict__ Dp,
                 float* __restrict__ y) {
    __shared__ float s_d[SCAN_T][8];
    __shared__ float s_u[SCAN_T][8];
    __shared__ float s_z[SCAN_T][8];
    __shared__ float s_B[SCAN_T][16];
    __shared__ float s_C[SCAN_T][16];

    const int b = blockIdx.y;
    const int d0 = blockIdx.x * 8;
    const int tid = threadIdx.x;
    const int ch = tid >> 4;     // 0..7
    const int n  = tid & 15;     // state index
    const int d  = d0 + ch;

    const float Areg = -expf(A_log[d * DSTATE + n]);
    const float Dreg = Dp[d];
    float h = 0.f;

    for (int t0 = 0; t0 < SEQ; t0 += SCAN_T) {
        // cooperative staging
        for (int i = tid; i < SCAN_T * 8; i += 128) {
            int tt = i >> 3, cc = i & 7;
            size_t base = (size_t)(b * SEQ + t0 + tt);
            s_d[tt][cc] = delta[base * DINNER + d0 + cc];
            s_u[tt][cc] = u[base * DINNER + d0 + cc];
            s_z[tt][cc] = xz[base * (2 * DINNER) + DINNER + d0 + cc];
        }
        for (int i = tid; i < SCAN_T * 16; i += 128) {
            int tt = i >> 4, nn = i & 15;
            size_t base = (size_t)(b * SEQ + t0 + tt);
            s_B[tt][nn] = xdbl[base * DXL + DTRANK + nn];
            s_C[tt][nn] = xdbl[base * DXL + DTRANK + DSTATE + nn];
        }
        __syncthreads();

#pragma unroll 4
        for (int tt = 0; tt < SCAN_T; tt++) {
            float dt = s_d[tt][ch];
            float ut = s_u[tt][ch];
            float dA = expf(dt * Areg);
            h = dA * h + dt * s_B[tt][n] * ut;
            float part = h * s_C[tt][n];
#pragma unroll
            for (int off = 8; off; off >>= 1)
                part += __shfl_xor_sync(0xFFFFFFFFu, part, off);
            if (n == 0) {
                float yv = part + ut * Dreg;
                float z = s_z[tt][ch];
                yv *= z / (1.f + expf(-z));
                y[((size_t)(b * SEQ + t0 + tt)) * DINNER + d] = yv;
            }
        }
        __syncthreads();
    }
}

// ---------------- launch -------------------------------------------------------
extern "C" void kernel_launch(void* const* d_in, const int* in_sizes, int n_in,
                              void* d_out, int out_size) {
    const float* hs    = (const float*)d_in[0];  // (B,L,1024)
    const float* inw   = (const float*)d_in[1];  // (4096,1024)
    const float* convw = (const float*)d_in[2];  // (2048,1,4)
    const float* convb = (const float*)d_in[3];  // (2048,)
    const float* xpw   = (const float*)d_in[4];  // (96,2048)
    const float* dtw   = (const float*)d_in[5];  // (2048,64)
    const float* dtb   = (const float*)d_in[6];  // (2048,)
    const float* alog  = (const float*)d_in[7];  // (2048,16)
    const float* Dp    = (const float*)d_in[8];  // (2048,)
    const float* outw  = (const float*)d_in[9];  // (1024,2048)
    float* out = (float*)d_out;

    float *xz, *u, *xdbl, *delta, *y;
    cudaGetSymbolAddress((void**)&xz,    g_xz);
    cudaGetSymbolAddress((void**)&u,     g_u);
    cudaGetSymbolAddress((void**)&xdbl,  g_xdbl);
    cudaGetSymbolAddress((void**)&delta, g_delta);
    cudaGetSymbolAddress((void**)&y,     g_y);

    // 1. in_proj: xz[m][e] = hs[m][.] . in_proj_w[e][.]   (4096 x 4096 x 1024)
    sgemm_nt<0><<<dim3(32, 32), 256>>>(hs, DMODEL, inw, DMODEL,
                                       xz, 2 * DINNER, NROWS, 2 * DINNER, DMODEL, nullptr);

    // 2. causal depthwise conv + silu -> u
    conv_silu_kernel<<<(NROWS * DINNER + 255) / 256, 256>>>(xz, convw, convb, u);

    // 3. x_proj: xdbl = u . x_proj_w^T    (4096 x 96 x 2048)
    sgemm_nt<0><<<dim3(1, 32), 256>>>(u, DINNER, xpw, DINNER,
                                      xdbl, DXL, NROWS, DXL, DINNER, nullptr);

    // 4. dt_proj + softplus: delta = softplus(dt . dt_proj_w^T + dt_b)  (4096 x 2048 x 64)
    sgemm_nt<1><<<dim3(16, 32), 256>>>(xdbl, DXL, dtw, DTRANK,
                                       delta, DINNER, NROWS, DINNER, DTRANK, dtb);

    // 5. selective scan + gating -> y
    scan_kernel<<<dim3(DINNER / 8, BATCH), 128>>>(delta, xdbl, u, xz, alog, Dp, y);

    // 6. out_proj: out = y . out_proj_w^T   (4096 x 1024 x 2048)
    sgemm_nt<0><<<dim3(8, 32), 256>>>(y, DINNER, outw, DINNER,
                                      out, DMODEL, NROWS, DMODEL, DINNER, nullptr);
}

// round 4
// speedup vs baseline: 1.1614x; 1.1614x over previous
#include <cuda_runtime.h>
#include <cuda_bf16.h>
#include <math.h>
#include <stdint.h>

#define BATCH 2
#define SEQ 2048
#define DMODEL 1024
#define DINNER 2048
#define DSTATE 16
#define DTRANK 64
#define DXL 96           // DT_RANK + 2*D_STATE
#define NROWS (BATCH*SEQ) // 4096

// ---------------- fp32 scratch ----------------
__device__ float g_xz[(size_t)NROWS * 2 * DINNER];
__device__ float g_u[(size_t)NROWS * DINNER];
__device__ float g_xdbl[(size_t)NROWS * DXL];
__device__ float g_delta[(size_t)NROWS * DINNER];
__device__ float g_y[(size_t)NROWS * DINNER];

// ---------------- bf16 hi/lo scratch ----------------
__device__ __nv_bfloat16 g_hs_hi[(size_t)NROWS * DMODEL];
__device__ __nv_bfloat16 g_hs_lo[(size_t)NROWS * DMODEL];
__device__ __nv_bfloat16 g_inw_hi[(size_t)2 * DINNER * DMODEL];
__device__ __nv_bfloat16 g_inw_lo[(size_t)2 * DINNER * DMODEL];
__device__ __nv_bfloat16 g_u_hi[(size_t)NROWS * DINNER];
__device__ __nv_bfloat16 g_u_lo[(size_t)NROWS * DINNER];
__device__ __nv_bfloat16 g_xpw_hi[(size_t)128 * DINNER];
__device__ __nv_bfloat16 g_xpw_lo[(size_t)128 * DINNER];
__device__ __nv_bfloat16 g_dt_hi[(size_t)NROWS * DTRANK];
__device__ __nv_bfloat16 g_dt_lo[(size_t)NROWS * DTRANK];
__device__ __nv_bfloat16 g_dtw_hi[(size_t)DINNER * DTRANK];
__device__ __nv_bfloat16 g_dtw_lo[(size_t)DINNER * DTRANK];
__device__ __nv_bfloat16 g_y_hi[(size_t)NROWS * DINNER];
__device__ __nv_bfloat16 g_y_lo[(size_t)NROWS * DINNER];
__device__ __nv_bfloat16 g_outw_hi[(size_t)DMODEL * DINNER];
__device__ __nv_bfloat16 g_outw_lo[(size_t)DMODEL * DINNER];

// ---------------- helpers ----------------
__device__ __forceinline__ uint32_t smem_u32(const void* p) {
    uint32_t a;
    asm("{ .reg .u64 t; cvta.to.shared.u64 t, %1; cvt.u32.u64 %0, t; }" : "=r"(a) : "l"(p));
    return a;
}

// ---------------- fp32 -> bf16 hi/lo conversion ----------------
__global__ void cvt_kernel(const float* __restrict__ src,
                           __nv_bfloat16* __restrict__ hi,
                           __nv_bfloat16* __restrict__ lo,
                           int Rp, int Cc, int srcStride, int Rvalid) {
    int idx = blockIdx.x * blockDim.x + threadIdx.x;
    if (idx >= Rp * Cc) return;
    int r = idx / Cc, c = idx % Cc;
    float v = (r < Rvalid) ? src[(size_t)r * srcStride + c] : 0.f;
    __nv_bfloat16 h = __float2bfloat16(v);
    float rem = v - __bfloat162float(h);
    hi[idx] = h;
    lo[idx] = __float2bfloat16(rem);
}

// ---------------- classic mma.sync GEMM, bf16x3 split ----------------
// C[m][n] = sum_k A[m][k] * B[n][k]
// Block tile 128x128, K staged 32 at a time, 8 warps (2x4), warp tile 64x32.
// smem row stride 40 bf16 (80B).
#define RS 40
#define TILE_ELEMS (128 * RS)          // 5120 bf16
#define TILE_BYTES (TILE_ELEMS * 2)    // 10240
#define STAGE_BYTES (4 * TILE_BYTES)   // 40960 (A_hi, A_lo, B_hi, B_lo)
#define GEMM_SMEM (2 * STAGE_BYTES)    // 81920

template <int EPI>
__global__ __launch_bounds__(256)
void gemm_mma(const __nv_bfloat16* __restrict__ Ahi, const __nv_bfloat16* __restrict__ Alo,
              const __nv_bfloat16* __restrict__ Bhi, const __nv_bfloat16* __restrict__ Blo,
              float* __restrict__ C, const float* __restrict__ bias,
              int K, int ldc, int Nvalid) {
    extern __shared__ char smem[];
    const uint32_t sb = smem_u32(smem);
    const int tid = threadIdx.x;
    const int wid = tid >> 5, lane = tid & 31;
    const int warp_m = wid >> 2, warp_n = wid & 3;   // 2 x 4
    const int bm = blockIdx.y * 128, bn = blockIdx.x * 128;
    const int NC = K >> 5;

    float acc[4][4][4];
#pragma unroll
    for (int i = 0; i < 4; i++)
#pragma unroll
        for (int j = 0; j < 4; j++)
#pragma unroll
            for (int q = 0; q < 4; q++) acc[i][j][q] = 0.f;

    auto load_stage = [&](int c) {
        uint32_t sbase = sb + (uint32_t)(c & 1) * STAGE_BYTES;
        size_t k0 = (size_t)c * 32;
#pragma unroll
        for (int it = 0; it < 8; it++) {
            int t = tid + it * 256;
            int tile = t >> 9;          // 0..3
            int s = t & 511;
            int row = s >> 2, seg = s & 3;
            const char* src;
            if (tile == 0)      src = (const char*)(Ahi + (size_t)(bm + row) * K + k0) + seg * 16;
            else if (tile == 1) src = (const char*)(Alo + (size_t)(bm + row) * K + k0) + seg * 16;
            else if (tile == 2) src = (const char*)(Bhi + (size_t)(bn + row) * K + k0) + seg * 16;
            else                src = (const char*)(Blo + (size_t)(bn + row) * K + k0) + seg * 16;
            uint32_t dst = sbase + (uint32_t)(tile * TILE_BYTES + row * (RS * 2) + seg * 16);
            asm volatile("cp.async.cg.shared.global [%0], [%1], 16;" :: "r"(dst), "l"(src) : "memory");
        }
        asm volatile("cp.async.commit_group;" ::: "memory");
    };

    load_stage(0);

    for (int c = 0; c < NC; c++) {
        if (c + 1 < NC) {
            load_stage(c + 1);
            asm volatile("cp.async.wait_group 1;" ::: "memory");
        } else {
            asm volatile("cp.async.wait_group 0;" ::: "memory");
        }
        __syncthreads();

        uint32_t sbase = sb + (uint32_t)(c & 1) * STAGE_BYTES;
        uint32_t aHiB = sbase;
        uint32_t aLoB = sbase + TILE_BYTES;
        uint32_t bHiB = sbase + 2 * TILE_BYTES;
        uint32_t bLoB = sbase + 3 * TILE_BYTES;

#pragma unroll
        for (int ks = 0; ks < 2; ks++) {
            const int kk = ks * 16;
            // ---- load fragments via ldmatrix ----
            uint32_t aH[4][4], aL[4][4], bH[4][2], bL[4][2];
            {
                int arow = (lane & 15);
                int acol = kk + ((lane >> 4) << 3);
#pragma unroll
                for (int mi = 0; mi < 4; mi++) {
                    int r = warp_m * 64 + mi * 16 + arow;
                    uint32_t off = (uint32_t)(r * (RS * 2) + acol * 2);
                    asm volatile("ldmatrix.sync.aligned.m8n8.x4.shared.b16 {%0,%1,%2,%3}, [%4];"
                                 : "=r"(aH[mi][0]), "=r"(aH[mi][1]), "=r"(aH[mi][2]), "=r"(aH[mi][3])
                                 : "r"(aHiB + off));
                    asm volatile("ldmatrix.sync.aligned.m8n8.x4.shared.b16 {%0,%1,%2,%3}, [%4];"
                                 : "=r"(aL[mi][0]), "=r"(aL[mi][1]), "=r"(aL[mi][2]), "=r"(aL[mi][3])
                                 : "r"(aLoB + off));
                }
                // B stored [n][k] row-major == col-major k x n: NON-trans ldmatrix
                int brow = (lane & 7);
                int bcol = kk + (((lane >> 3) & 1) << 3);
#pragma unroll
                for (int ni = 0; ni < 4; ni++) {
                    int r = warp_n * 32 + ni * 8 + brow;
                    uint32_t off = (uint32_t)(r * (RS * 2) + bcol * 2);
                    asm volatile("ldmatrix.sync.aligned.m8n8.x2.shared.b16 {%0,%1}, [%2];"
                                 : "=r"(bH[ni][0]), "=r"(bH[ni][1]) : "r"(bHiB + off));
                    asm volatile("ldmatrix.sync.aligned.m8n8.x2.shared.b16 {%0,%1}, [%2];"
                                 : "=r"(bL[ni][0]), "=r"(bL[ni][1]) : "r"(bLoB + off));
                }
            }
            // ---- 3 combo passes ----
#pragma unroll
            for (int mi = 0; mi < 4; mi++)
#pragma unroll
                for (int ni = 0; ni < 4; ni++) {
                    asm volatile("mma.sync.aligned.m16n8k16.row.col.f32.bf16.bf16.f32 "
                                 "{%0,%1,%2,%3}, {%4,%5,%6,%7}, {%8,%9}, {%0,%1,%2,%3};"
                                 : "+f"(acc[mi][ni][0]), "+f"(acc[mi][ni][1]),
                                   "+f"(acc[mi][ni][2]), "+f"(acc[mi][ni][3])
                                 : "r"(aH[mi][0]), "r"(aH[mi][1]), "r"(aH[mi][2]), "r"(aH[mi][3]),
                                   "r"(bH[ni][0]), "r"(bH[ni][1]));
                    asm volatile("mma.sync.aligned.m16n8k16.row.col.f32.bf16.bf16.f32 "
                                 "{%0,%1,%2,%3}, {%4,%5,%6,%7}, {%8,%9}, {%0,%1,%2,%3};"
                                 : "+f"(acc[mi][ni][0]), "+f"(acc[mi][ni][1]),
                                   "+f"(acc[mi][ni][2]), "+f"(acc[mi][ni][3])
                                 : "r"(aL[mi][0]), "r"(aL[mi][1]), "r"(aL[mi][2]), "r"(aL[mi][3]),
                                   "r"(bH[ni][0]), "r"(bH[ni][1]));
                    asm volatile("mma.sync.aligned.m16n8k16.row.col.f32.bf16.bf16.f32 "
                                 "{%0,%1,%2,%3}, {%4,%5,%6,%7}, {%8,%9}, {%0,%1,%2,%3};"
                                 : "+f"(acc[mi][ni][0]), "+f"(acc[mi][ni][1]),
                                   "+f"(acc[mi][ni][2]), "+f"(acc[mi][ni][3])
                                 : "r"(aH[mi][0]), "r"(aH[mi][1]), "r"(aH[mi][2]), "r"(aH[mi][3]),
                                   "r"(bL[ni][0]), "r"(bL[ni][1]));
                }
        }
        __syncthreads();
    }

    // ---- epilogue: registers -> C ----
#pragma unroll
    for (int mi = 0; mi < 4; mi++) {
        int row0 = bm + warp_m * 64 + mi * 16 + (lane >> 2);
#pragma unroll
        for (int ni = 0; ni < 4; ni++) {
            int col0 = bn + warp_n * 32 + ni * 8 + ((lane & 3) << 1);
            if (col0 < Nvalid) {
#pragma unroll
                for (int half = 0; half < 2; half++) {
                    int r = row0 + half * 8;
                    float v0 = acc[mi][ni][half * 2 + 0];
                    float v1 = acc[mi][ni][half * 2 + 1];
                    if (EPI == 1) {
                        v0 += bias[col0];
                        v1 += bias[col0 + 1];
                        v0 = (v0 > 20.f) ? v0 : log1pf(expf(v0));
                        v1 = (v1 > 20.f) ? v1 : log1pf(expf(v1));
                    }
                    float2 st = make_float2(v0, v1);
                    *(float2*)(C + (size_t)r * ldc + col0) = st;
                }
            }
        }
    }
}

// ---------------- depthwise causal conv (d_conv=4) + SiLU -> u ------------------
__global__ void conv_silu_kernel(const float* __restrict__ xz,
                                 const float* __restrict__ w,
                                 const float* __restrict__ bias,
                                 float* __restrict__ u) {
    int idx = blockIdx.x * blockDim.x + threadIdx.x;
    if (idx >= NROWS * DINNER) return;
    int c = idx % DINNER;
    int row = idx / DINNER;
    int t = row % SEQ;
    int b = row / SEQ;
    float acc = bias[c];
#pragma unroll
    for (int k = 0; k < 4; k++) {
        int tt = t - 3 + k;
        if (tt >= 0)
            acc += xz[((size_t)(b * SEQ + tt)) * (2 * DINNER) + c] * w[c * 4 + k];
    }
    u[idx] = acc / (1.f + expf(-acc));
}

// ---------------- selective scan --------------------------------------------
#define SCAN_T 64
__global__ __launch_bounds__(128, 8)
void scan_kernel(const float* __restrict__ delta,
                 const float* __restrict__ xdbl,
                 const float* __restrict__ u,
                 const float* __restrict__ xz,
                 const float* __restrict__ A_log,
                 const float* __restrict__ Dp,
                 float* __restrict__ y) {
    __shared__ float s_d[SCAN_T][8];
    __shared__ float s_u[SCAN_T][8];
    __shared__ float s_z[SCAN_T][8];
    __shared__ float s_B[SCAN_T][16];
    __shared__ float s_C[SCAN_T][16];

    const int b = blockIdx.y;
    const int d0 = blockIdx.x * 8;
    const int tid = threadIdx.x;
    const int ch = tid >> 4;
    const int n  = tid & 15;
    const int d  = d0 + ch;

    const float Areg = -expf(A_log[d * DSTATE + n]);
    const float Dreg = Dp[d];
    float h = 0.f;

    for (int t0 = 0; t0 < SEQ; t0 += SCAN_T) {
        for (int i = tid; i < SCAN_T * 8; i += 128) {
            int tt = i >> 3, cc = i & 7;
            size_t base = (size_t)(b * SEQ + t0 + tt);
            s_d[tt][cc] = delta[base * DINNER + d0 + cc];
            s_u[tt][cc] = u[base * DINNER + d0 + cc];
            s_z[tt][cc] = xz[base * (2 * DINNER) + DINNER + d0 + cc];
        }
        for (int i = tid; i < SCAN_T * 16; i += 128) {
            int tt = i >> 4, nn = i & 15;
            size_t base = (size_t)(b * SEQ + t0 + tt);
            s_B[tt][nn] = xdbl[base * DXL + DTRANK + nn];
            s_C[tt][nn] = xdbl[base * DXL + DTRANK + DSTATE + nn];
        }
        __syncthreads();

#pragma unroll 4
        for (int tt = 0; tt < SCAN_T; tt++) {
            float dt = s_d[tt][ch];
            float ut = s_u[tt][ch];
            float dA = expf(dt * Areg);
            h = dA * h + dt * s_B[tt][n] * ut;
            float part = h * s_C[tt][n];
#pragma unroll
            for (int off = 8; off; off >>= 1)
                part += __shfl_xor_sync(0xFFFFFFFFu, part, off);
            if (n == 0) {
                float yv = part + ut * Dreg;
                float z = s_z[tt][ch];
                yv *= z / (1.f + expf(-z));
                y[((size_t)(b * SEQ + t0 + tt)) * DINNER + d] = yv;
            }
        }
        __syncthreads();
    }
}

// ---------------- launch -------------------------------------------------------
extern "C" void kernel_launch(void* const* d_in, const int* in_sizes, int n_in,
                              void* d_out, int out_size) {
    const float* hs    = (const float*)d_in[0];
    const float* inw   = (const float*)d_in[1];
    const float* convw = (const float*)d_in[2];
    const float* convb = (const float*)d_in[3];
    const float* xpw   = (const float*)d_in[4];
    const float* dtw   = (const float*)d_in[5];
    const float* dtb   = (const float*)d_in[6];
    const float* alog  = (const float*)d_in[7];
    const float* Dp    = (const float*)d_in[8];
    const float* outw  = (const float*)d_in[9];
    float* out = (float*)d_out;

    float *xz, *u, *xdbl, *delta, *y;
    cudaGetSymbolAddress((void**)&xz,    g_xz);
    cudaGetSymbolAddress((void**)&u,     g_u);
    cudaGetSymbolAddress((void**)&xdbl,  g_xdbl);
    cudaGetSymbolAddress((void**)&delta, g_delta);
    cudaGetSymbolAddress((void**)&y,     g_y);

    __nv_bfloat16 *hs_hi, *hs_lo, *inw_hi, *inw_lo, *u_hi, *u_lo, *xpw_hi, *xpw_lo;
    __nv_bfloat16 *dt_hi, *dt_lo, *dtw_hi, *dtw_lo, *y_hi, *y_lo, *outw_hi, *outw_lo;
    cudaGetSymbolAddress((void**)&hs_hi,  g_hs_hi);   cudaGetSymbolAddress((void**)&hs_lo,  g_hs_lo);
    cudaGetSymbolAddress((void**)&inw_hi, g_inw_hi);  cudaGetSymbolAddress((void**)&inw_lo, g_inw_lo);
    cudaGetSymbolAddress((void**)&u_hi,   g_u_hi);    cudaGetSymbolAddress((void**)&u_lo,   g_u_lo);
    cudaGetSymbolAddress((void**)&xpw_hi, g_xpw_hi);  cudaGetSymbolAddress((void**)&xpw_lo, g_xpw_lo);
    cudaGetSymbolAddress((void**)&dt_hi,  g_dt_hi);   cudaGetSymbolAddress((void**)&dt_lo,  g_dt_lo);
    cudaGetSymbolAddress((void**)&dtw_hi, g_dtw_hi);  cudaGetSymbolAddress((void**)&dtw_lo, g_dtw_lo);
    cudaGetSymbolAddress((void**)&y_hi,   g_y_hi);    cudaGetSymbolAddress((void**)&y_lo,   g_y_lo);
    cudaGetSymbolAddress((void**)&outw_hi,g_outw_hi); cudaGetSymbolAddress((void**)&outw_lo,g_outw_lo);

    cudaFuncSetAttribute(gemm_mma<0>, cudaFuncAttributeMaxDynamicSharedMemorySize, GEMM_SMEM);
    cudaFuncSetAttribute(gemm_mma<1>, cudaFuncAttributeMaxDynamicSharedMemorySize, GEMM_SMEM);

    const int CT = 256;
    // ---- in_proj ----
    cvt_kernel<<<(NROWS * DMODEL + CT - 1) / CT, CT>>>(hs,  hs_hi,  hs_lo,  NROWS, DMODEL, DMODEL, NROWS);
    cvt_kernel<<<(2 * DINNER * DMODEL + CT - 1) / CT, CT>>>(inw, inw_hi, inw_lo, 2 * DINNER, DMODEL, DMODEL, 2 * DINNER);
    gemm_mma<0><<<dim3(32, 32), 256, GEMM_SMEM>>>(hs_hi, hs_lo, inw_hi, inw_lo,
                                                  xz, nullptr, DMODEL, 2 * DINNER, 2 * DINNER);
    // ---- conv + silu ----
    conv_silu_kernel<<<(NROWS * DINNER + CT - 1) / CT, CT>>>(xz, convw, convb, u);
    // ---- x_proj ----
    cvt_kernel<<<(NROWS * DINNER + CT - 1) / CT, CT>>>(u, u_hi, u_lo, NROWS, DINNER, DINNER, NROWS);
    cvt_kernel<<<(128 * DINNER + CT - 1) / CT, CT>>>(xpw, xpw_hi, xpw_lo, 128, DINNER, DINNER, DXL);
    gemm_mma<0><<<dim3(1, 32), 256, GEMM_SMEM>>>(u_hi, u_lo, xpw_hi, xpw_lo,
                                                 xdbl, nullptr, DINNER, DXL, DXL);
    // ---- dt_proj + softplus ----
    cvt_kernel<<<(NROWS * DTRANK + CT - 1) / CT, CT>>>(xdbl, dt_hi, dt_lo, NROWS, DTRANK, DXL, NROWS);
    cvt_kernel<<<(DINNER * DTRANK + CT - 1) / CT, CT>>>(dtw, dtw_hi, dtw_lo, DINNER, DTRANK, DTRANK, DINNER);
    gemm_mma<1><<<dim3(16, 32), 256, GEMM_SMEM>>>(dt_hi, dt_lo, dtw_hi, dtw_lo,
                                                  delta, dtb, DTRANK, DINNER, DINNER);
    // ---- selective scan ----
    scan_kernel<<<dim3(DINNER / 8, BATCH), 128>>>(delta, xdbl, u, xz, alog, Dp, y);
    // ---- out_proj ----
    cvt_kernel<<<(NROWS * DINNER + CT - 1) / CT, CT>>>(y, y_hi, y_lo, NROWS, DINNER, DINNER, NROWS);
    cvt_kernel<<<(DMODEL * DINNER + CT - 1) / CT, CT>>>(outw, outw_hi, outw_lo, DMODEL, DINNER, DINNER, DMODEL);
    gemm_mma<0><<<dim3(8, 32), 256, GEMM_SMEM>>>(y_hi, y_lo, outw_hi, outw_lo,
                                                 out, nullptr, DINNER, DMODEL, DMODEL);
}

// round 5
// speedup vs baseline: 2.0028x; 1.7244x over previous
#include <cuda_runtime.h>
#include <cuda_bf16.h>
#include <math.h>
#include <stdint.h>

#define BATCH 2
#define SEQ 2048
#define DMODEL 1024
#define DINNER 2048
#define DSTATE 16
#define DTRANK 64
#define DXL 96           // DT_RANK + 2*D_STATE
#define NROWS (BATCH*SEQ) // 4096
#define KSPLIT 4

// ---------------- fp32 scratch ----------------
__device__ float g_xz[(size_t)NROWS * 2 * DINNER];
__device__ float g_u[(size_t)NROWS * DINNER];
__device__ float g_xdbl[(size_t)NROWS * DXL];
__device__ float g_part[(size_t)KSPLIT * NROWS * DXL];
__device__ float g_delta[(size_t)NROWS * DINNER];
__device__ float g_y[(size_t)NROWS * DINNER];

// ---------------- bf16 hi/lo scratch ----------------
__device__ __nv_bfloat16 g_hs_hi[(size_t)NROWS * DMODEL];
__device__ __nv_bfloat16 g_hs_lo[(size_t)NROWS * DMODEL];
__device__ __nv_bfloat16 g_inw_hi[(size_t)2 * DINNER * DMODEL];
__device__ __nv_bfloat16 g_inw_lo[(size_t)2 * DINNER * DMODEL];
__device__ __nv_bfloat16 g_u_hi[(size_t)NROWS * DINNER];
__device__ __nv_bfloat16 g_u_lo[(size_t)NROWS * DINNER];
__device__ __nv_bfloat16 g_xpw_hi[(size_t)128 * DINNER];
__device__ __nv_bfloat16 g_xpw_lo[(size_t)128 * DINNER];
__device__ __nv_bfloat16 g_dt_hi[(size_t)NROWS * DTRANK];
__device__ __nv_bfloat16 g_dt_lo[(size_t)NROWS * DTRANK];
__device__ __nv_bfloat16 g_dtw_hi[(size_t)DINNER * DTRANK];
__device__ __nv_bfloat16 g_dtw_lo[(size_t)DINNER * DTRANK];
__device__ __nv_bfloat16 g_y_hi[(size_t)NROWS * DINNER];
__device__ __nv_bfloat16 g_y_lo[(size_t)NROWS * DINNER];
__device__ __nv_bfloat16 g_outw_hi[(size_t)DMODEL * DINNER];
__device__ __nv_bfloat16 g_outw_lo[(size_t)DMODEL * DINNER];

// ---------------- helpers ----------------
__device__ __forceinline__ uint32_t smem_u32(const void* p) {
    uint32_t a;
    asm("{ .reg .u64 t; cvta.to.shared.u64 t, %1; cvt.u32.u64 %0, t; }" : "=r"(a) : "l"(p));
    return a;
}
__device__ __forceinline__ void split_bf16(float v, __nv_bfloat16& h, __nv_bfloat16& l) {
    h = __float2bfloat16(v);
    l = __float2bfloat16(v - __bfloat162float(h));
}

// ---------------- fp32 -> bf16 hi/lo conversion ----------------
__global__ void cvt_kernel(const float* __restrict__ src,
                           __nv_bfloat16* __restrict__ hi,
                           __nv_bfloat16* __restrict__ lo,
                           int Rp, int Cc, int srcStride, int Rvalid) {
    int idx = blockIdx.x * blockDim.x + threadIdx.x;
    if (idx >= Rp * Cc) return;
    int r = idx / Cc, c = idx % Cc;
    float v = (r < Rvalid) ? src[(size_t)r * srcStride + c] : 0.f;
    __nv_bfloat16 h, l;
    split_bf16(v, h, l);
    hi[idx] = h; lo[idx] = l;
}

// ---------------- classic mma.sync GEMM, bf16x3 split ----------------
#define RS 40
#define TILE_ELEMS (128 * RS)
#define TILE_BYTES (TILE_ELEMS * 2)    // 10240
#define STAGE_BYTES (4 * TILE_BYTES)   // 40960
#define GEMM_SMEM (2 * STAGE_BYTES)    // 81920

#define MMA_OP(ACC, AF, BF) \
    asm volatile("mma.sync.aligned.m16n8k16.row.col.f32.bf16.bf16.f32 " \
                 "{%0,%1,%2,%3}, {%4,%5,%6,%7}, {%8,%9}, {%0,%1,%2,%3};" \
                 : "+f"((ACC)[0]), "+f"((ACC)[1]), "+f"((ACC)[2]), "+f"((ACC)[3]) \
                 : "r"((AF)[0]), "r"((AF)[1]), "r"((AF)[2]), "r"((AF)[3]), \
                   "r"((BF)[0]), "r"((BF)[1]))

template <int EPI>
__global__ __launch_bounds__(256, 2)
void gemm_mma(const __nv_bfloat16* __restrict__ Ahi, const __nv_bfloat16* __restrict__ Alo,
              const __nv_bfloat16* __restrict__ Bhi, const __nv_bfloat16* __restrict__ Blo,
              float* __restrict__ C, const float* __restrict__ bias,
              int K, int ldc, int Nvalid, int Kloop, size_t partStride) {
    extern __shared__ char smem[];
    const uint32_t sb = smem_u32(smem);
    const int tid = threadIdx.x;
    const int wid = tid >> 5, lane = tid & 31;
    const int warp_m = wid >> 2, warp_n = wid & 3;
    const int bm = blockIdx.y * 128, bn = blockIdx.x * 128;
    const int koff = blockIdx.z * Kloop;
    const int NC = Kloop >> 5;

    float acc[4][4][4];
#pragma unroll
    for (int i = 0; i < 4; i++)
#pragma unroll
        for (int j = 0; j < 4; j++)
#pragma unroll
            for (int q = 0; q < 4; q++) acc[i][j][q] = 0.f;

    auto load_stage = [&](int c) {
        uint32_t sbase = sb + (uint32_t)(c & 1) * STAGE_BYTES;
        size_t k0 = (size_t)koff + (size_t)c * 32;
#pragma unroll
        for (int it = 0; it < 8; it++) {
            int t = tid + it * 256;
            int tile = t >> 9;
            int s = t & 511;
            int row = s >> 2, seg = s & 3;
            const char* src;
            if (tile == 0)      src = (const char*)(Ahi + (size_t)(bm + row) * K + k0) + seg * 16;
            else if (tile == 1) src = (const char*)(Alo + (size_t)(bm + row) * K + k0) + seg * 16;
            else if (tile == 2) src = (const char*)(Bhi + (size_t)(bn + row) * K + k0) + seg * 16;
            else                src = (const char*)(Blo + (size_t)(bn + row) * K + k0) + seg * 16;
            uint32_t dst = sbase + (uint32_t)(tile * TILE_BYTES + row * (RS * 2) + seg * 16);
            asm volatile("cp.async.cg.shared.global [%0], [%1], 16;" :: "r"(dst), "l"(src) : "memory");
        }
        asm volatile("cp.async.commit_group;" ::: "memory");
    };

    load_stage(0);

    for (int c = 0; c < NC; c++) {
        if (c + 1 < NC) {
            load_stage(c + 1);
            asm volatile("cp.async.wait_group 1;" ::: "memory");
        } else {
            asm volatile("cp.async.wait_group 0;" ::: "memory");
        }
        __syncthreads();

        uint32_t sbase = sb + (uint32_t)(c & 1) * STAGE_BYTES;
        uint32_t aHiB = sbase;
        uint32_t aLoB = sbase + TILE_BYTES;
        uint32_t bHiB = sbase + 2 * TILE_BYTES;
        uint32_t bLoB = sbase + 3 * TILE_BYTES;

#pragma unroll
        for (int ks = 0; ks < 2; ks++) {
            const int kk = ks * 16;
            const int arow = (lane & 15);
            const int acol = kk + ((lane >> 4) << 3);
            const int brow = (lane & 7);
            const int bcol = kk + (((lane >> 3) & 1) << 3);

            uint32_t aH[4][4], bH[4][2];
#pragma unroll
            for (int mi = 0; mi < 4; mi++) {
                int r = warp_m * 64 + mi * 16 + arow;
                uint32_t off = (uint32_t)(r * (RS * 2) + acol * 2);
                asm volatile("ldmatrix.sync.aligned.m8n8.x4.shared.b16 {%0,%1,%2,%3}, [%4];"
                             : "=r"(aH[mi][0]), "=r"(aH[mi][1]), "=r"(aH[mi][2]), "=r"(aH[mi][3])
                             : "r"(aHiB + off));
            }
#pragma unroll
            for (int ni = 0; ni < 4; ni++) {
                int r = warp_n * 32 + ni * 8 + brow;
                uint32_t off = (uint32_t)(r * (RS * 2) + bcol * 2);
                asm volatile("ldmatrix.sync.aligned.m8n8.x2.shared.b16 {%0,%1}, [%2];"
                             : "=r"(bH[ni][0]), "=r"(bH[ni][1]) : "r"(bHiB + off));
            }
            // pass 1: aH * bH
#pragma unroll
            for (int mi = 0; mi < 4; mi++)
#pragma unroll
                for (int ni = 0; ni < 4; ni++) MMA_OP(acc[mi][ni], aH[mi], bH[ni]);

            // pass 2: aH * bL
            {
                uint32_t bL[4][2];
#pragma unroll
                for (int ni = 0; ni < 4; ni++) {
                    int r = warp_n * 32 + ni * 8 + brow;
                    uint32_t off = (uint32_t)(r * (RS * 2) + bcol * 2);
                    asm volatile("ldmatrix.sync.aligned.m8n8.x2.shared.b16 {%0,%1}, [%2];"
                                 : "=r"(bL[ni][0]), "=r"(bL[ni][1]) : "r"(bLoB + off));
                }
#pragma unroll
                for (int mi = 0; mi < 4; mi++)
#pragma unroll
                    for (int ni = 0; ni < 4; ni++) MMA_OP(acc[mi][ni], aH[mi], bL[ni]);
            }
            // pass 3: aL * bH
            {
                uint32_t aL[4][4];
#pragma unroll
                for (int mi = 0; mi < 4; mi++) {
                    int r = warp_m * 64 + mi * 16 + arow;
                    uint32_t off = (uint32_t)(r * (RS * 2) + acol * 2);
                    asm volatile("ldmatrix.sync.aligned.m8n8.x4.shared.b16 {%0,%1,%2,%3}, [%4];"
                                 : "=r"(aL[mi][0]), "=r"(aL[mi][1]), "=r"(aL[mi][2]), "=r"(aL[mi][3])
                                 : "r"(aLoB + off));
                }
#pragma unroll
                for (int mi = 0; mi < 4; mi++)
#pragma unroll
                    for (int ni = 0; ni < 4; ni++) MMA_OP(acc[mi][ni], aL[mi], bH[ni]);
            }
        }
        __syncthreads();
    }

    // ---- epilogue ----
    float* Cz = C + partStride * blockIdx.z;
#pragma unroll
    for (int mi = 0; mi < 4; mi++) {
        int row0 = bm + warp_m * 64 + mi * 16 + (lane >> 2);
#pragma unroll
        for (int ni = 0; ni < 4; ni++) {
            int col0 = bn + warp_n * 32 + ni * 8 + ((lane & 3) << 1);
            if (col0 < Nvalid) {
#pragma unroll
                for (int half = 0; half < 2; half++) {
                    int r = row0 + half * 8;
                    float v0 = acc[mi][ni][half * 2 + 0];
                    float v1 = acc[mi][ni][half * 2 + 1];
                    if (EPI == 1) {
                        v0 += bias[col0];
                        v1 += bias[col0 + 1];
                        v0 = (v0 > 20.f) ? v0 : log1pf(expf(v0));
                        v1 = (v1 > 20.f) ? v1 : log1pf(expf(v1));
                    }
                    *(float2*)(Cz + (size_t)r * ldc + col0) = make_float2(v0, v1);
                }
            }
        }
    }
}

// ---------------- conv + SiLU + bf16 split -> u, u_hi, u_lo ------------------
__global__ void conv_silu_kernel(const float* __restrict__ xz,
                                 const float* __restrict__ w,
                                 const float* __restrict__ bias,
                                 float* __restrict__ u,
                                 __nv_bfloat16* __restrict__ u_hi,
                                 __nv_bfloat16* __restrict__ u_lo) {
    int idx = blockIdx.x * blockDim.x + threadIdx.x;
    if (idx >= NROWS * DINNER) return;
    int c = idx % DINNER;
    int row = idx / DINNER;
    int t = row % SEQ;
    int b = row / SEQ;
    float acc = bias[c];
#pragma unroll
    for (int k = 0; k < 4; k++) {
        int tt = t - 3 + k;
        if (tt >= 0)
            acc += xz[((size_t)(b * SEQ + tt)) * (2 * DINNER) + c] * w[c * 4 + k];
    }
    float v = acc / (1.f + expf(-acc));
    u[idx] = v;
    __nv_bfloat16 h, l;
    split_bf16(v, h, l);
    u_hi[idx] = h; u_lo[idx] = l;
}

// ---------------- split-K reduce for x_proj + dt split ----------------
__global__ void reduce_xdbl_kernel(const float* __restrict__ part,
                                   float* __restrict__ xdbl,
                                   __nv_bfloat16* __restrict__ dt_hi,
                                   __nv_bfloat16* __restrict__ dt_lo) {
    int idx = blockIdx.x * blockDim.x + threadIdx.x;
    if (idx >= NROWS * DXL) return;
    float v = 0.f;
#pragma unroll
    for (int z = 0; z < KSPLIT; z++) v += part[(size_t)z * NROWS * DXL + idx];
    xdbl[idx] = v;
    int c = idx % DXL;
    if (c < DTRANK) {
        int r = idx / DXL;
        __nv_bfloat16 h, l;
        split_bf16(v, h, l);
        dt_hi[r * DTRANK + c] = h;
        dt_lo[r * DTRANK + c] = l;
    }
}

// ---------------- selective scan (+ fused y bf16 split) ----------------------
#define SCAN_T 64
__global__ __launch_bounds__(128, 8)
void scan_kernel(const float* __restrict__ delta,
                 const float* __restrict__ xdbl,
                 const float* __restrict__ u,
                 const float* __restrict__ xz,
                 const float* __restrict__ A_log,
                 const float* __restrict__ Dp,
                 float* __restrict__ y,
                 __nv_bfloat16* __restrict__ y_hi,
                 __nv_bfloat16* __restrict__ y_lo) {
    __shared__ float s_d[SCAN_T][8];
    __shared__ float s_u[SCAN_T][8];
    __shared__ float s_z[SCAN_T][8];
    __shared__ float s_B[SCAN_T][16];
    __shared__ float s_C[SCAN_T][16];

    const int b = blockIdx.y;
    const int d0 = blockIdx.x * 8;
    const int tid = threadIdx.x;
    const int ch = tid >> 4;
    const int n  = tid & 15;
    const int d  = d0 + ch;

    const float Areg = -expf(A_log[d * DSTATE + n]);
    const float Dreg = Dp[d];
    float h = 0.f;

    for (int t0 = 0; t0 < SEQ; t0 += SCAN_T) {
        for (int i = tid; i < SCAN_T * 8; i += 128) {
            int tt = i >> 3, cc = i & 7;
            size_t base = (size_t)(b * SEQ + t0 + tt);
            s_d[tt][cc] = delta[base * DINNER + d0 + cc];
            s_u[tt][cc] = u[base * DINNER + d0 + cc];
            s_z[tt][cc] = xz[base * (2 * DINNER) + DINNER + d0 + cc];
        }
        for (int i = tid; i < SCAN_T * 16; i += 128) {
            int tt = i >> 4, nn = i & 15;
            size_t base = (size_t)(b * SEQ + t0 + tt);
            s_B[tt][nn] = xdbl[base * DXL + DTRANK + nn];
            s_C[tt][nn] = xdbl[base * DXL + DTRANK + DSTATE + nn];
        }
        __syncthreads();

#pragma unroll 4
        for (int tt = 0; tt < SCAN_T; tt++) {
            float dt = s_d[tt][ch];
            float ut = s_u[tt][ch];
            float dA = expf(dt * Areg);
            h = dA * h + dt * s_B[tt][n] * ut;
            float part = h * s_C[tt][n];
#pragma unroll
            for (int off = 8; off; off >>= 1)
                part += __shfl_xor_sync(0xFFFFFFFFu, part, off);
            if (n == 0) {
                float yv = part + ut * Dreg;
                float z = s_z[tt][ch];
                yv *= z / (1.f + expf(-z));
                size_t oidx = ((size_t)(b * SEQ + t0 + tt)) * DINNER + d;
                y[oidx] = yv;
                __nv_bfloat16 hh, ll;
                split_bf16(yv, hh, ll);
                y_hi[oidx] = hh; y_lo[oidx] = ll;
            }
        }
        __syncthreads();
    }
}

// ---------------- launch -------------------------------------------------------
extern "C" void kernel_launch(void* const* d_in, const int* in_sizes, int n_in,
                              void* d_out, int out_size) {
    const float* hs    = (const float*)d_in[0];
    const float* inw   = (const float*)d_in[1];
    const float* convw = (const float*)d_in[2];
    const float* convb = (const float*)d_in[3];
    const float* xpw   = (const float*)d_in[4];
    const float* dtw   = (const float*)d_in[5];
    const float* dtb   = (const float*)d_in[6];
    const float* alog  = (const float*)d_in[7];
    const float* Dp    = (const float*)d_in[8];
    const float* outw  = (const float*)d_in[9];
    float* out = (float*)d_out;

    float *xz, *u, *xdbl, *part, *delta, *y;
    cudaGetSymbolAddress((void**)&xz,    g_xz);
    cudaGetSymbolAddress((void**)&u,     g_u);
    cudaGetSymbolAddress((void**)&xdbl,  g_xdbl);
    cudaGetSymbolAddress((void**)&part,  g_part);
    cudaGetSymbolAddress((void**)&delta, g_delta);
    cudaGetSymbolAddress((void**)&y,     g_y);

    __nv_bfloat16 *hs_hi, *hs_lo, *inw_hi, *inw_lo, *u_hi, *u_lo, *xpw_hi, *xpw_lo;
    __nv_bfloat16 *dt_hi, *dt_lo, *dtw_hi, *dtw_lo, *y_hi, *y_lo, *outw_hi, *outw_lo;
    cudaGetSymbolAddress((void**)&hs_hi,  g_hs_hi);   cudaGetSymbolAddress((void**)&hs_lo,  g_hs_lo);
    cudaGetSymbolAddress((void**)&inw_hi, g_inw_hi);  cudaGetSymbolAddress((void**)&inw_lo, g_inw_lo);
    cudaGetSymbolAddress((void**)&u_hi,   g_u_hi);    cudaGetSymbolAddress((void**)&u_lo,   g_u_lo);
    cudaGetSymbolAddress((void**)&xpw_hi, g_xpw_hi);  cudaGetSymbolAddress((void**)&xpw_lo, g_xpw_lo);
    cudaGetSymbolAddress((void**)&dt_hi,  g_dt_hi);   cudaGetSymbolAddress((void**)&dt_lo,  g_dt_lo);
    cudaGetSymbolAddress((void**)&dtw_hi, g_dtw_hi);  cudaGetSymbolAddress((void**)&dtw_lo, g_dtw_lo);
    cudaGetSymbolAddress((void**)&y_hi,   g_y_hi);    cudaGetSymbolAddress((void**)&y_lo,   g_y_lo);
    cudaGetSymbolAddress((void**)&outw_hi,g_outw_hi); cudaGetSymbolAddress((void**)&outw_lo,g_outw_lo);

    cudaFuncSetAttribute(gemm_mma<0>, cudaFuncAttributeMaxDynamicSharedMemorySize, GEMM_SMEM);
    cudaFuncSetAttribute(gemm_mma<1>, cudaFuncAttributeMaxDynamicSharedMemorySize, GEMM_SMEM);

    const int CT = 256;
    // ---- in_proj ----
    cvt_kernel<<<(NROWS * DMODEL + CT - 1) / CT, CT>>>(hs,  hs_hi,  hs_lo,  NROWS, DMODEL, DMODEL, NROWS);
    cvt_kernel<<<(2 * DINNER * DMODEL + CT - 1) / CT, CT>>>(inw, inw_hi, inw_lo, 2 * DINNER, DMODEL, DMODEL, 2 * DINNER);
    gemm_mma<0><<<dim3(32, 32), 256, GEMM_SMEM>>>(hs_hi, hs_lo, inw_hi, inw_lo,
                                                  xz, nullptr, DMODEL, 2 * DINNER, 2 * DINNER, DMODEL, 0);
    // ---- conv + silu (+u split) ----
    conv_silu_kernel<<<(NROWS * DINNER + CT - 1) / CT, CT>>>(xz, convw, convb, u, u_hi, u_lo);
    // ---- x_proj: split-K=4 ----
    cvt_kernel<<<(128 * DINNER + CT - 1) / CT, CT>>>(xpw, xpw_hi, xpw_lo, 128, DINNER, DINNER, DXL);
    gemm_mma<0><<<dim3(1, 32, KSPLIT), 256, GEMM_SMEM>>>(u_hi, u_lo, xpw_hi, xpw_lo,
                                                         part, nullptr, DINNER, DXL, DXL,
                                                         DINNER / KSPLIT, (size_t)NROWS * DXL);
    reduce_xdbl_kernel<<<(NROWS * DXL + CT - 1) / CT, CT>>>(part, xdbl, dt_hi, dt_lo);
    // ---- dt_proj + softplus ----
    cvt_kernel<<<(DINNER * DTRANK + CT - 1) / CT, CT>>>(dtw, dtw_hi, dtw_lo, DINNER, DTRANK, DTRANK, DINNER);
    gemm_mma<1><<<dim3(16, 32), 256, GEMM_SMEM>>>(dt_hi, dt_lo, dtw_hi, dtw_lo,
                                                  delta, dtb, DTRANK, DINNER, DINNER, DTRANK, 0);
    // ---- selective scan (+y split) ----
    scan_kernel<<<dim3(DINNER / 8, BATCH), 128>>>(delta, xdbl, u, xz, alog, Dp, y, y_hi, y_lo);
    // ---- out_proj ----
    cvt_kernel<<<(DMODEL * DINNER + CT - 1) / CT, CT>>>(outw, outw_hi, outw_lo, DMODEL, DINNER, DINNER, DMODEL);
    gemm_mma<0><<<dim3(8, 32), 256, GEMM_SMEM>>>(y_hi, y_lo, outw_hi, outw_lo,
                                                 out, nullptr, DINNER, DMODEL, DMODEL, DINNER, 0);
}

// round 6
// speedup vs baseline: 2.2611x; 1.1290x over previous
#include <cuda_runtime.h>
#include <cuda_bf16.h>
#include <cuda_fp16.h>
#include <math.h>
#include <stdint.h>

#define BATCH 2
#define SEQ 2048
#define DMODEL 1024
#define DINNER 2048
#define DSTATE 16
#define DTRANK 64
#define DXL 96           // DT_RANK + 2*D_STATE
#define NROWS (BATCH*SEQ) // 4096
#define KSPLIT 4

// ---------------- fp32 scratch ----------------
__device__ float g_xz[(size_t)NROWS * 2 * DINNER];
__device__ float g_u[(size_t)NROWS * DINNER];
__device__ float g_xdbl[(size_t)NROWS * DXL];
__device__ float g_part[(size_t)KSPLIT * NROWS * DXL];
__device__ float g_delta[(size_t)NROWS * DINNER];
__device__ float g_y[(size_t)NROWS * DINNER];

// ---------------- fp16 hi/lo scratch ----------------
__device__ __half g_hs_hi[(size_t)NROWS * DMODEL];
__device__ __half g_hs_lo[(size_t)NROWS * DMODEL];
__device__ __half g_inw_hi[(size_t)2 * DINNER * DMODEL];
__device__ __half g_inw_lo[(size_t)2 * DINNER * DMODEL];
__device__ __half g_u_hi[(size_t)NROWS * DINNER];
__device__ __half g_u_lo[(size_t)NROWS * DINNER];
__device__ __half g_xpw_hi[(size_t)128 * DINNER];
__device__ __half g_xpw_lo[(size_t)128 * DINNER];
__device__ __half g_dt_hi[(size_t)NROWS * DTRANK];
__device__ __half g_dt_lo[(size_t)NROWS * DTRANK];
__device__ __half g_dtw_hi[(size_t)DINNER * DTRANK];
__device__ __half g_dtw_lo[(size_t)DINNER * DTRANK];
__device__ __half g_y_hi[(size_t)NROWS * DINNER];
__device__ __half g_y_lo[(size_t)NROWS * DINNER];
__device__ __half g_outw_hi[(size_t)DMODEL * DINNER];
__device__ __half g_outw_lo[(size_t)DMODEL * DINNER];

// ---------------- helpers ----------------
__device__ __forceinline__ uint32_t smem_u32(const void* p) {
    uint32_t a;
    asm("{ .reg .u64 t; cvta.to.shared.u64 t, %1; cvt.u32.u64 %0, t; }" : "=r"(a) : "l"(p));
    return a;
}
__device__ __forceinline__ void split_fp16(float v, __half& h, __half& l) {
    h = __float2half(v);
    l = __float2half(v - __half2float(h));
}

// ---------------- fp32 -> fp16 hi/lo conversion ----------------
__global__ void cvt_kernel(const float* __restrict__ src,
                           __half* __restrict__ hi,
                           __half* __restrict__ lo,
                           int Rp, int Cc, int srcStride, int Rvalid) {
    int idx = blockIdx.x * blockDim.x + threadIdx.x;
    if (idx >= Rp * Cc) return;
    int r = idx / Cc, c = idx % Cc;
    float v = (r < Rvalid) ? src[(size_t)r * srcStride + c] : 0.f;
    __half h, l;
    split_fp16(v, h, l);
    hi[idx] = h; lo[idx] = l;
}

// ---------------- classic mma.sync GEMM, fp16 split ----------------
// NPASS==2: C = (Ah+Al)*Bh     (err ~1e-4, tiles 0..2)
// NPASS==3: C = Ah*Bh + Ah*Bl + Al*Bh (err ~1e-6, tiles 0..3)
#define RS 40
#define TILE_ELEMS (128 * RS)
#define TILE_BYTES (TILE_ELEMS * 2)    // 10240
#define STAGE_BYTES (4 * TILE_BYTES)   // 40960
#define GEMM_SMEM (2 * STAGE_BYTES)    // 81920

#define MMA_OP(ACC, AF, BF) \
    asm volatile("mma.sync.aligned.m16n8k16.row.col.f32.f16.f16.f32 " \
                 "{%0,%1,%2,%3}, {%4,%5,%6,%7}, {%8,%9}, {%0,%1,%2,%3};" \
                 : "+f"((ACC)[0]), "+f"((ACC)[1]), "+f"((ACC)[2]), "+f"((ACC)[3]) \
                 : "r"((AF)[0]), "r"((AF)[1]), "r"((AF)[2]), "r"((AF)[3]), \
                   "r"((BF)[0]), "r"((BF)[1]))

// B fragment loads for all 4 ni (both k-halves) in 2 ldmatrix.x4 ops.
#define LDB_X4(DST, BASE, KK) \
    { \
        _Pragma("unroll") \
        for (int p = 0; p < 2; p++) { \
            int r = warp_n * 32 + p * 16 + ((lane >> 4) << 3) + (lane & 7); \
            int ccol = (KK) + (((lane >> 3) & 1) << 3); \
            uint32_t off = (uint32_t)(r * (RS * 2) + ccol * 2); \
            asm volatile("ldmatrix.sync.aligned.m8n8.x4.shared.b16 {%0,%1,%2,%3}, [%4];" \
                         : "=r"((DST)[2*p][0]), "=r"((DST)[2*p][1]), \
                           "=r"((DST)[2*p+1][0]), "=r"((DST)[2*p+1][1]) \
                         : "r"((BASE) + off)); \
        } \
    }

template <int EPI, int NPASS>
__global__ __launch_bounds__(256, 2)
void gemm_mma(const __half* __restrict__ Ahi, const __half* __restrict__ Alo,
              const __half* __restrict__ Bhi, const __half* __restrict__ Blo,
              float* __restrict__ C, const float* __restrict__ bias,
              int K, int ldc, int Nvalid, int Kloop, size_t partStride) {
    extern __shared__ char smem[];
    const uint32_t sb = smem_u32(smem);
    const int tid = threadIdx.x;
    const int wid = tid >> 5, lane = tid & 31;
    const int warp_m = wid >> 2, warp_n = wid & 3;
    const int bm = blockIdx.y * 128, bn = blockIdx.x * 128;
    const int koff = blockIdx.z * Kloop;
    const int NC = Kloop >> 5;

    float acc[4][4][4];
#pragma unroll
    for (int i = 0; i < 4; i++)
#pragma unroll
        for (int j = 0; j < 4; j++)
#pragma unroll
            for (int q = 0; q < 4; q++) acc[i][j][q] = 0.f;

    auto load_stage = [&](int c) {
        uint32_t sbase = sb + (uint32_t)(c & 1) * STAGE_BYTES;
        size_t k0 = (size_t)koff + (size_t)c * 32;
        const int NIT = (NPASS == 2) ? 6 : 8;   // skip B_lo tile for 2-pass
#pragma unroll
        for (int it = 0; it < NIT; it++) {
            int t = tid + it * 256;
            int tile = t >> 9;
            int s = t & 511;
            int row = s >> 2, seg = s & 3;
            const char* src;
            if (tile == 0)      src = (const char*)(Ahi + (size_t)(bm + row) * K + k0) + seg * 16;
            else if (tile == 1) src = (const char*)(Alo + (size_t)(bm + row) * K + k0) + seg * 16;
            else if (tile == 2) src = (const char*)(Bhi + (size_t)(bn + row) * K + k0) + seg * 16;
            else                src = (const char*)(Blo + (size_t)(bn + row) * K + k0) + seg * 16;
            uint32_t dst = sbase + (uint32_t)(tile * TILE_BYTES + row * (RS * 2) + seg * 16);
            asm volatile("cp.async.cg.shared.global [%0], [%1], 16;" :: "r"(dst), "l"(src) : "memory");
        }
        asm volatile("cp.async.commit_group;" ::: "memory");
    };

    load_stage(0);

    for (int c = 0; c < NC; c++) {
        if (c + 1 < NC) {
            load_stage(c + 1);
            asm volatile("cp.async.wait_group 1;" ::: "memory");
        } else {
            asm volatile("cp.async.wait_group 0;" ::: "memory");
        }
        __syncthreads();

        uint32_t sbase = sb + (uint32_t)(c & 1) * STAGE_BYTES;
        uint32_t aHiB = sbase;
        uint32_t aLoB = sbase + TILE_BYTES;
        uint32_t bHiB = sbase + 2 * TILE_BYTES;
        uint32_t bLoB = sbase + 3 * TILE_BYTES;

#pragma unroll
        for (int ks = 0; ks < 2; ks++) {
            const int kk = ks * 16;
            const int arow = (lane & 15);
            const int acol = kk + ((lane >> 4) << 3);

            uint32_t aH[4][4], bH[4][2];
#pragma unroll
            for (int mi = 0; mi < 4; mi++) {
                int r = warp_m * 64 + mi * 16 + arow;
                uint32_t off = (uint32_t)(r * (RS * 2) + acol * 2);
                asm volatile("ldmatrix.sync.aligned.m8n8.x4.shared.b16 {%0,%1,%2,%3}, [%4];"
                             : "=r"(aH[mi][0]), "=r"(aH[mi][1]), "=r"(aH[mi][2]), "=r"(aH[mi][3])
                             : "r"(aHiB + off));
            }
            LDB_X4(bH, bHiB, kk);

            // pass 1: aH * bH
#pragma unroll
            for (int mi = 0; mi < 4; mi++)
#pragma unroll
                for (int ni = 0; ni < 4; ni++) MMA_OP(acc[mi][ni], aH[mi], bH[ni]);

            if (NPASS == 3) {
                // pass 2: aH * bL
                uint32_t bL[4][2];
                LDB_X4(bL, bLoB, kk);
#pragma unroll
                for (int mi = 0; mi < 4; mi++)
#pragma unroll
                    for (int ni = 0; ni < 4; ni++) MMA_OP(acc[mi][ni], aH[mi], bL[ni]);
            }
            // final pass: aL * bH
            {
                uint32_t aL[4][4];
#pragma unroll
                for (int mi = 0; mi < 4; mi++) {
                    int r = warp_m * 64 + mi * 16 + arow;
                    uint32_t off = (uint32_t)(r * (RS * 2) + acol * 2);
                    asm volatile("ldmatrix.sync.aligned.m8n8.x4.shared.b16 {%0,%1,%2,%3}, [%4];"
                                 : "=r"(aL[mi][0]), "=r"(aL[mi][1]), "=r"(aL[mi][2]), "=r"(aL[mi][3])
                                 : "r"(aLoB + off));
                }
#pragma unroll
                for (int mi = 0; mi < 4; mi++)
#pragma unroll
                    for (int ni = 0; ni < 4; ni++) MMA_OP(acc[mi][ni], aL[mi], bH[ni]);
            }
        }
        __syncthreads();
    }

    // ---- epilogue ----
    float* Cz = C + partStride * blockIdx.z;
#pragma unroll
    for (int mi = 0; mi < 4; mi++) {
        int row0 = bm + warp_m * 64 + mi * 16 + (lane >> 2);
#pragma unroll
        for (int ni = 0; ni < 4; ni++) {
            int col0 = bn + warp_n * 32 + ni * 8 + ((lane & 3) << 1);
            if (col0 < Nvalid) {
#pragma unroll
                for (int half = 0; half < 2; half++) {
                    int r = row0 + half * 8;
                    float v0 = acc[mi][ni][half * 2 + 0];
                    float v1 = acc[mi][ni][half * 2 + 1];
                    if (EPI == 1) {
                        v0 += bias[col0];
                        v1 += bias[col0 + 1];
                        v0 = (v0 > 20.f) ? v0 : log1pf(expf(v0));
                        v1 = (v1 > 20.f) ? v1 : log1pf(expf(v1));
                    }
                    *(float2*)(Cz + (size_t)r * ldc + col0) = make_float2(v0, v1);
                }
            }
        }
    }
}

// ---------------- conv + SiLU + fp16 split -> u, u_hi, u_lo ------------------
__global__ void conv_silu_kernel(const float* __restrict__ xz,
                                 const float* __restrict__ w,
                                 const float* __restrict__ bias,
                                 float* __restrict__ u,
                                 __half* __restrict__ u_hi,
                                 __half* __restrict__ u_lo) {
    int idx = blockIdx.x * blockDim.x + threadIdx.x;
    if (idx >= NROWS * DINNER) return;
    int c = idx % DINNER;
    int row = idx / DINNER;
    int t = row % SEQ;
    int b = row / SEQ;
    float acc = bias[c];
#pragma unroll
    for (int k = 0; k < 4; k++) {
        int tt = t - 3 + k;
        if (tt >= 0)
            acc += xz[((size_t)(b * SEQ + tt)) * (2 * DINNER) + c] * w[c * 4 + k];
    }
    float v = acc / (1.f + expf(-acc));
    u[idx] = v;
    __half h, l;
    split_fp16(v, h, l);
    u_hi[idx] = h; u_lo[idx] = l;
}

// ---------------- split-K reduce for x_proj + dt split ----------------
__global__ void reduce_xdbl_kernel(const float* __restrict__ part,
                                   float* __restrict__ xdbl,
                                   __half* __restrict__ dt_hi,
                                   __half* __restrict__ dt_lo) {
    int idx = blockIdx.x * blockDim.x + threadIdx.x;
    if (idx >= NROWS * DXL) return;
    float v = 0.f;
#pragma unroll
    for (int z = 0; z < KSPLIT; z++) v += part[(size_t)z * NROWS * DXL + idx];
    xdbl[idx] = v;
    int c = idx % DXL;
    if (c < DTRANK) {
        int r = idx / DXL;
        __half h, l;
        split_fp16(v, h, l);
        dt_hi[r * DTRANK + c] = h;
        dt_lo[r * DTRANK + c] = l;
    }
}

// ---------------- selective scan (+ fused y fp16 split) ----------------------
#define SCAN_T 64
__global__ __launch_bounds__(128, 8)
void scan_kernel(const float* __restrict__ delta,
                 const float* __restrict__ xdbl,
                 const float* __restrict__ u,
                 const float* __restrict__ xz,
                 const float* __restrict__ A_log,
                 const float* __restrict__ Dp,
                 float* __restrict__ y,
                 __half* __restrict__ y_hi,
                 __half* __restrict__ y_lo) {
    __shared__ float s_d[SCAN_T][8];
    __shared__ float s_u[SCAN_T][8];
    __shared__ float s_z[SCAN_T][8];
    __shared__ float s_B[SCAN_T][16];
    __shared__ float s_C[SCAN_T][16];

    const int b = blockIdx.y;
    const int d0 = blockIdx.x * 8;
    const int tid = threadIdx.x;
    const int ch = tid >> 4;
    const int n  = tid & 15;
    const int d  = d0 + ch;

    const float Areg = -expf(A_log[d * DSTATE + n]);
    const float Dreg = Dp[d];
    float h = 0.f;

    for (int t0 = 0; t0 < SEQ; t0 += SCAN_T) {
        for (int i = tid; i < SCAN_T * 8; i += 128) {
            int tt = i >> 3, cc = i & 7;
            size_t base = (size_t)(b * SEQ + t0 + tt);
            s_d[tt][cc] = delta[base * DINNER + d0 + cc];
            s_u[tt][cc] = u[base * DINNER + d0 + cc];
            s_z[tt][cc] = xz[base * (2 * DINNER) + DINNER + d0 + cc];
        }
        for (int i = tid; i < SCAN_T * 16; i += 128) {
            int tt = i >> 4, nn = i & 15;
            size_t base = (size_t)(b * SEQ + t0 + tt);
            s_B[tt][nn] = xdbl[base * DXL + DTRANK + nn];
            s_C[tt][nn] = xdbl[base * DXL + DTRANK + DSTATE + nn];
        }
        __syncthreads();

#pragma unroll 4
        for (int tt = 0; tt < SCAN_T; tt++) {
            float dt = s_d[tt][ch];
            float ut = s_u[tt][ch];
            float dA = expf(dt * Areg);
            h = dA * h + dt * s_B[tt][n] * ut;
            float part = h * s_C[tt][n];
#pragma unroll
            for (int off = 8; off; off >>= 1)
                part += __shfl_xor_sync(0xFFFFFFFFu, part, off);
            if (n == 0) {
                float yv = part + ut * Dreg;
                float z = s_z[tt][ch];
                yv *= z / (1.f + expf(-z));
                size_t oidx = ((size_t)(b * SEQ + t0 + tt)) * DINNER + d;
                y[oidx] = yv;
                __half hh, ll;
                split_fp16(yv, hh, ll);
                y_hi[oidx] = hh; y_lo[oidx] = ll;
            }
        }
        __syncthreads();
    }
}

// ---------------- launch -------------------------------------------------------
extern "C" void kernel_launch(void* const* d_in, const int* in_sizes, int n_in,
                              void* d_out, int out_size) {
    const float* hs    = (const float*)d_in[0];
    const float* inw   = (const float*)d_in[1];
    const float* convw = (const float*)d_in[2];
    const float* convb = (const float*)d_in[3];
    const float* xpw   = (const float*)d_in[4];
    const float* dtw   = (const float*)d_in[5];
    const float* dtb   = (const float*)d_in[6];
    const float* alog  = (const float*)d_in[7];
    const float* Dp    = (const float*)d_in[8];
    const float* outw  = (const float*)d_in[9];
    float* out = (float*)d_out;

    float *xz, *u, *xdbl, *part, *delta, *y;
    cudaGetSymbolAddress((void**)&xz,    g_xz);
    cudaGetSymbolAddress((void**)&u,     g_u);
    cudaGetSymbolAddress((void**)&xdbl,  g_xdbl);
    cudaGetSymbolAddress((void**)&part,  g_part);
    cudaGetSymbolAddress((void**)&delta, g_delta);
    cudaGetSymbolAddress((void**)&y,     g_y);

    __half *hs_hi, *hs_lo, *inw_hi, *inw_lo, *u_hi, *u_lo, *xpw_hi, *xpw_lo;
    __half *dt_hi, *dt_lo, *dtw_hi, *dtw_lo, *y_hi, *y_lo, *outw_hi, *outw_lo;
    cudaGetSymbolAddress((void**)&hs_hi,  g_hs_hi);   cudaGetSymbolAddress((void**)&hs_lo,  g_hs_lo);
    cudaGetSymbolAddress((void**)&inw_hi, g_inw_hi);  cudaGetSymbolAddress((void**)&inw_lo, g_inw_lo);
    cudaGetSymbolAddress((void**)&u_hi,   g_u_hi);    cudaGetSymbolAddress((void**)&u_lo,   g_u_lo);
    cudaGetSymbolAddress((void**)&xpw_hi, g_xpw_hi);  cudaGetSymbolAddress((void**)&xpw_lo, g_xpw_lo);
    cudaGetSymbolAddress((void**)&dt_hi,  g_dt_hi);   cudaGetSymbolAddress((void**)&dt_lo,  g_dt_lo);
    cudaGetSymbolAddress((void**)&dtw_hi, g_dtw_hi);  cudaGetSymbolAddress((void**)&dtw_lo, g_dtw_lo);
    cudaGetSymbolAddress((void**)&y_hi,   g_y_hi);    cudaGetSymbolAddress((void**)&y_lo,   g_y_lo);
    cudaGetSymbolAddress((void**)&outw_hi,g_outw_hi); cudaGetSymbolAddress((void**)&outw_lo,g_outw_lo);

    cudaFuncSetAttribute((const void*)gemm_mma<0,2>, cudaFuncAttributeMaxDynamicSharedMemorySize, GEMM_SMEM);
    cudaFuncSetAttribute((const void*)gemm_mma<0,3>, cudaFuncAttributeMaxDynamicSharedMemorySize, GEMM_SMEM);
    cudaFuncSetAttribute((const void*)gemm_mma<1,3>, cudaFuncAttributeMaxDynamicSharedMemorySize, GEMM_SMEM);

    const int CT = 256;
    // ---- in_proj (2-pass fp16) ----
    cvt_kernel<<<(NROWS * DMODEL + CT - 1) / CT, CT>>>(hs,  hs_hi,  hs_lo,  NROWS, DMODEL, DMODEL, NROWS);
    cvt_kernel<<<(2 * DINNER * DMODEL + CT - 1) / CT, CT>>>(inw, inw_hi, inw_lo, 2 * DINNER, DMODEL, DMODEL, 2 * DINNER);
    gemm_mma<0,2><<<dim3(32, 32), 256, GEMM_SMEM>>>(hs_hi, hs_lo, inw_hi, inw_lo,
                                                    xz, nullptr, DMODEL, 2 * DINNER, 2 * DINNER, DMODEL, 0);
    // ---- conv + silu (+u split) ----
    conv_silu_kernel<<<(NROWS * DINNER + CT - 1) / CT, CT>>>(xz, convw, convb, u, u_hi, u_lo);
    // ---- x_proj: split-K=4 (3-pass) ----
    cvt_kernel<<<(128 * DINNER + CT - 1) / CT, CT>>>(xpw, xpw_hi, xpw_lo, 128, DINNER, DINNER, DXL);
    gemm_mma<0,3><<<dim3(1, 32, KSPLIT), 256, GEMM_SMEM>>>(u_hi, u_lo, xpw_hi, xpw_lo,
                                                           part, nullptr, DINNER, DXL, DXL,
                                                           DINNER / KSPLIT, (size_t)NROWS * DXL);
    reduce_xdbl_kernel<<<(NROWS * DXL + CT - 1) / CT, CT>>>(part, xdbl, dt_hi, dt_lo);
    // ---- dt_proj + softplus (3-pass) ----
    cvt_kernel<<<(DINNER * DTRANK + CT - 1) / CT, CT>>>(dtw, dtw_hi, dtw_lo, DINNER, DTRANK, DTRANK, DINNER);
    gemm_mma<1,3><<<dim3(16, 32), 256, GEMM_SMEM>>>(dt_hi, dt_lo, dtw_hi, dtw_lo,
                                                    delta, dtb, DTRANK, DINNER, DINNER, DTRANK, 0);
    // ---- selective scan (+y split) ----
    scan_kernel<<<dim3(DINNER / 8, BATCH), 128>>>(delta, xdbl, u, xz, alog, Dp, y, y_hi, y_lo);
    // ---- out_proj (2-pass fp16) ----
    cvt_kernel<<<(DMODEL * DINNER + CT - 1) / CT, CT>>>(outw, outw_hi, outw_lo, DMODEL, DINNER, DINNER, DMODEL);
    gemm_mma<0,2><<<dim3(8, 32), 256, GEMM_SMEM>>>(y_hi, y_lo, outw_hi, outw_lo,
                                                   out, nullptr, DINNER, DMODEL, DMODEL, DINNER, 0);
}

// round 10
// speedup vs baseline: 2.3344x; 1.0324x over previous
#include <cuda_runtime.h>
#include <cuda_bf16.h>
#include <cuda_fp16.h>
#include <math.h>
#include <stdint.h>

#define BATCH 2
#define SEQ 2048
#define DMODEL 1024
#define DINNER 2048
#define DSTATE 16
#define DTRANK 64
#define DXL 96           // DT_RANK + 2*D_STATE
#define NROWS (BATCH*SEQ) // 4096
#define KSPLIT 4

// ---------------- fp32 scratch ----------------
__device__ float g_xz[(size_t)NROWS * 2 * DINNER];
__device__ float g_u[(size_t)NROWS * DINNER];
__device__ float g_xdbl[(size_t)NROWS * DXL];
__device__ float g_part[(size_t)KSPLIT * NROWS * DXL];
__device__ float g_delta[(size_t)NROWS * DINNER];
__device__ float g_y[(size_t)NROWS * DINNER];

// ---------------- fp16 hi/lo scratch ----------------
__device__ __half g_hs_hi[(size_t)NROWS * DMODEL];
__device__ __half g_hs_lo[(size_t)NROWS * DMODEL];
__device__ __half g_inw_hi[(size_t)2 * DINNER * DMODEL];
__device__ __half g_inw_lo[(size_t)2 * DINNER * DMODEL];
__device__ __half g_u_hi[(size_t)NROWS * DINNER];
__device__ __half g_u_lo[(size_t)NROWS * DINNER];
__device__ __half g_xpw_hi[(size_t)128 * DINNER];
__device__ __half g_xpw_lo[(size_t)128 * DINNER];
__device__ __half g_dt_hi[(size_t)NROWS * DTRANK];
__device__ __half g_dt_lo[(size_t)NROWS * DTRANK];
__device__ __half g_dtw_hi[(size_t)DINNER * DTRANK];
__device__ __half g_dtw_lo[(size_t)DINNER * DTRANK];
__device__ __half g_y_hi[(size_t)NROWS * DINNER];
__device__ __half g_y_lo[(size_t)NROWS * DINNER];
__device__ __half g_outw_hi[(size_t)DMODEL * DINNER];
__device__ __half g_outw_lo[(size_t)DMODEL * DINNER];

// ---------------- helpers ----------------
__device__ __forceinline__ uint32_t smem_u32(const void* p) {
    uint32_t a;
    asm("{ .reg .u64 t; cvta.to.shared.u64 t, %1; cvt.u32.u64 %0, t; }" : "=r"(a) : "l"(p));
    return a;
}
__device__ __forceinline__ void split_fp16(float v, __half& h, __half& l) {
    h = __float2half(v);
    l = __float2half(v - __half2float(h));
}

// ---------------- fp32 -> fp16 hi/lo conversion (vectorized x4) ----------------
__global__ void cvt_kernel(const float* __restrict__ src,
                           __half* __restrict__ hi,
                           __half* __restrict__ lo,
                           int Rp, int Cc, int srcStride, int Rvalid) {
    int idx4 = (blockIdx.x * blockDim.x + threadIdx.x) * 4;
    if (idx4 >= Rp * Cc) return;
    int r = idx4 / Cc, c = idx4 % Cc;
    float4 v;
    if (r < Rvalid) v = *(const float4*)(src + (size_t)r * srcStride + c);
    else            v = make_float4(0.f, 0.f, 0.f, 0.f);
    __half h0, l0, h1, l1, h2, l2, h3, l3;
    split_fp16(v.x, h0, l0); split_fp16(v.y, h1, l1);
    split_fp16(v.z, h2, l2); split_fp16(v.w, h3, l3);
    *(__half2*)(hi + idx4)     = __halves2half2(h0, h1);
    *(__half2*)(hi + idx4 + 2) = __halves2half2(h2, h3);
    *(__half2*)(lo + idx4)     = __halves2half2(l0, l1);
    *(__half2*)(lo + idx4 + 2) = __halves2half2(l2, l3);
}

// ---------------- classic mma.sync GEMM, fp16 split ----------------
// NPASS==2: C = (Ah+Al)*Bh ; NPASS==3: C = Ah*Bh + Ah*Bl + Al*Bh
#define RS 40
#define TILE_ELEMS (128 * RS)
#define TILE_BYTES (TILE_ELEMS * 2)    // 10240
#define STAGE_BYTES (4 * TILE_BYTES)   // 40960
#define GEMM_SMEM (2 * STAGE_BYTES)    // 81920

#define MMA_OP(ACC, AF, BF) \
    asm volatile("mma.sync.aligned.m16n8k16.row.col.f32.f16.f16.f32 " \
                 "{%0,%1,%2,%3}, {%4,%5,%6,%7}, {%8,%9}, {%0,%1,%2,%3};" \
                 : "+f"((ACC)[0]), "+f"((ACC)[1]), "+f"((ACC)[2]), "+f"((ACC)[3]) \
                 : "r"((AF)[0]), "r"((AF)[1]), "r"((AF)[2]), "r"((AF)[3]), \
                   "r"((BF)[0]), "r"((BF)[1]))

#define LDSM_X4(R0, R1, R2, R3, ADDR) \
    asm volatile("ldmatrix.sync.aligned.m8n8.x4.shared.b16 {%0,%1,%2,%3}, [%4];" \
                 : "=r"(R0), "=r"(R1), "=r"(R2), "=r"(R3) : "r"(ADDR))

template <int EPI, int NPASS>
__global__ __launch_bounds__(256, 2)
void gemm_mma(const __half* __restrict__ Ahi, const __half* __restrict__ Alo,
              const __half* __restrict__ Bhi, const __half* __restrict__ Blo,
              float* __restrict__ C, const float* __restrict__ bias,
              int K, int ldc, int Nvalid, int Kloop, size_t partStride) {
    extern __shared__ char smem[];
    const uint32_t sb = smem_u32(smem);
    const int tid = threadIdx.x;
    const int wid = tid >> 5, lane = tid & 31;
    const int warp_m = wid >> 2, warp_n = wid & 3;
    const int bm = blockIdx.y * 128, bn = blockIdx.x * 128;
    const int koff = blockIdx.z * Kloop;
    const int NC = Kloop >> 5;

    // --- precomputed ldmatrix offsets (loop-invariant) ---
    uint32_t offA[4], offB[2];
    {
        const int arow = lane & 15;
        const int acol = (lane >> 4) << 3;
#pragma unroll
        for (int mi = 0; mi < 4; mi++)
            offA[mi] = (uint32_t)((warp_m * 64 + mi * 16 + arow) * (RS * 2) + acol * 2);
        const int bcol = ((lane >> 3) & 1) << 3;
#pragma unroll
        for (int p = 0; p < 2; p++) {
            int r = warp_n * 32 + p * 16 + ((lane >> 4) << 3) + (lane & 7);
            offB[p] = (uint32_t)(r * (RS * 2) + bcol * 2);
        }
    }

    float acc[4][4][4];
#pragma unroll
    for (int i = 0; i < 4; i++)
#pragma unroll
        for (int j = 0; j < 4; j++)
#pragma unroll
            for (int q = 0; q < 4; q++) acc[i][j][q] = 0.f;

    auto load_stage = [&](int c) {
        uint32_t sbase = sb + (uint32_t)(c & 1) * STAGE_BYTES;
        size_t k0 = (size_t)koff + (size_t)c * 32;
        const int NIT = (NPASS == 2) ? 6 : 8;
#pragma unroll
        for (int it = 0; it < NIT; it++) {
            int t = tid + it * 256;
            int tile = t >> 9;
            int s = t & 511;
            int row = s >> 2, seg = s & 3;
            const char* src;
            if (tile == 0)      src = (const char*)(Ahi + (size_t)(bm + row) * K + k0) + seg * 16;
            else if (tile == 1) src = (const char*)(Alo + (size_t)(bm + row) * K + k0) + seg * 16;
            else if (tile == 2) src = (const char*)(Bhi + (size_t)(bn + row) * K + k0) + seg * 16;
            else                src = (const char*)(Blo + (size_t)(bn + row) * K + k0) + seg * 16;
            uint32_t dst = sbase + (uint32_t)(tile * TILE_BYTES + row * (RS * 2) + seg * 16);
            asm volatile("cp.async.cg.shared.global [%0], [%1], 16;" :: "r"(dst), "l"(src) : "memory");
        }
        asm volatile("cp.async.commit_group;" ::: "memory");
    };

    load_stage(0);

    for (int c = 0; c < NC; c++) {
        if (c + 1 < NC) {
            load_stage(c + 1);
            asm volatile("cp.async.wait_group 1;" ::: "memory");
        } else {
            asm volatile("cp.async.wait_group 0;" ::: "memory");
        }
        __syncthreads();

        const uint32_t sbase = sb + (uint32_t)(c & 1) * STAGE_BYTES;
        const uint32_t aHiB = sbase;
        const uint32_t aLoB = sbase + TILE_BYTES;
        const uint32_t bHiB = sbase + 2 * TILE_BYTES;
        const uint32_t bLoB = sbase + 3 * TILE_BYTES;

#pragma unroll
        for (int ks = 0; ks < 2; ks++) {
            const uint32_t kb = (uint32_t)(ks * 32);   // 16 halves = 32 bytes

            uint32_t aH[4][4], bH[4][2];
#pragma unroll
            for (int mi = 0; mi < 4; mi++)
                LDSM_X4(aH[mi][0], aH[mi][1], aH[mi][2], aH[mi][3], aHiB + offA[mi] + kb);
#pragma unroll
            for (int p = 0; p < 2; p++)
                LDSM_X4(bH[2*p][0], bH[2*p][1], bH[2*p+1][0], bH[2*p+1][1], bHiB + offB[p] + kb);

            // pass 1: aH * bH
#pragma unroll
            for (int mi = 0; mi < 4; mi++)
#pragma unroll
                for (int ni = 0; ni < 4; ni++) MMA_OP(acc[mi][ni], aH[mi], bH[ni]);

            if (NPASS == 3) {
                uint32_t bL[4][2];
#pragma unroll
                for (int p = 0; p < 2; p++)
                    LDSM_X4(bL[2*p][0], bL[2*p][1], bL[2*p+1][0], bL[2*p+1][1], bLoB + offB[p] + kb);
#pragma unroll
                for (int mi = 0; mi < 4; mi++)
#pragma unroll
                    for (int ni = 0; ni < 4; ni++) MMA_OP(acc[mi][ni], aH[mi], bL[ni]);
            }
            {
                uint32_t aL[4][4];
#pragma unroll
                for (int mi = 0; mi < 4; mi++)
                    LDSM_X4(aL[mi][0], aL[mi][1], aL[mi][2], aL[mi][3], aLoB + offA[mi] + kb);
#pragma unroll
                for (int mi = 0; mi < 4; mi++)
#pragma unroll
                    for (int ni = 0; ni < 4; ni++) MMA_OP(acc[mi][ni], aL[mi], bH[ni]);
            }
        }
        __syncthreads();
    }

    // ---- epilogue ----
    float* Cz = C + partStride * blockIdx.z;
#pragma unroll
    for (int mi = 0; mi < 4; mi++) {
        int row0 = bm + warp_m * 64 + mi * 16 + (lane >> 2);
#pragma unroll
        for (int ni = 0; ni < 4; ni++) {
            int col0 = bn + warp_n * 32 + ni * 8 + ((lane & 3) << 1);
            if (col0 < Nvalid) {
#pragma unroll
                for (int half = 0; half < 2; half++) {
                    int r = row0 + half * 8;
                    float v0 = acc[mi][ni][half * 2 + 0];
                    float v1 = acc[mi][ni][half * 2 + 1];
                    if (EPI == 1) {
                        v0 += bias[col0];
                        v1 += bias[col0 + 1];
                        v0 = (v0 > 20.f) ? v0 : log1pf(expf(v0));
                        v1 = (v1 > 20.f) ? v1 : log1pf(expf(v1));
                    }
                    *(float2*)(Cz + (size_t)r * ldc + col0) = make_float2(v0, v1);
                }
            }
        }
    }
}

// ---------------- conv + SiLU + fp16 split -> u, u_hi, u_lo ------------------
__global__ void conv_silu_kernel(const float* __restrict__ xz,
                                 const float* __restrict__ w,
                                 const float* __restrict__ bias,
                                 float* __restrict__ u,
                                 __half* __restrict__ u_hi,
                                 __half* __restrict__ u_lo) {
    int idx = blockIdx.x * blockDim.x + threadIdx.x;
    if (idx >= NROWS * DINNER) return;
    int c = idx % DINNER;
    int row = idx / DINNER;
    int t = row % SEQ;
    int b = row / SEQ;
    float acc = bias[c];
#pragma unroll
    for (int k = 0; k < 4; k++) {
        int tt = t - 3 + k;
        if (tt >= 0)
            acc += xz[((size_t)(b * SEQ + tt)) * (2 * DINNER) + c] * w[c * 4 + k];
    }
    float v = acc / (1.f + expf(-acc));
    u[idx] = v;
    __half h, l;
    split_fp16(v, h, l);
    u_hi[idx] = h; u_lo[idx] = l;
}

// ---------------- split-K reduce for x_proj + dt split ----------------
__global__ void reduce_xdbl_kernel(const float* __restrict__ part,
                                   float* __restrict__ xdbl,
                                   __half* __restrict__ dt_hi,
                                   __half* __restrict__ dt_lo) {
    int idx = blockIdx.x * blockDim.x + threadIdx.x;
    if (idx >= NROWS * DXL) return;
    float v = 0.f;
#pragma unroll
    for (int z = 0; z < KSPLIT; z++) v += part[(size_t)z * NROWS * DXL + idx];
    xdbl[idx] = v;
    int c = idx % DXL;
    if (c < DTRANK) {
        int r = idx / DXL;
        __half h, l;
        split_fp16(v, h, l);
        dt_hi[r * DTRANK + c] = h;
        dt_lo[r * DTRANK + c] = l;
    }
}

// ---------------- selective scan (+ fused y fp16 split) ----------------------
#define SCAN_T 64
__global__ __launch_bounds__(128, 8)
void scan_kernel(const float* __restrict__ delta,
                 const float* __restrict__ xdbl,
                 const float* __restrict__ u,
                 const float* __restrict__ xz,
                 const float* __restrict__ A_log,
                 const float* __restrict__ Dp,
                 float* __restrict__ y,
                 __half* __restrict__ y_hi,
                 __half* __restrict__ y_lo) {
    __shared__ float s_d[SCAN_T][8];
    __shared__ float s_u[SCAN_T][8];
    __shared__ float s_z[SCAN_T][8];
    __shared__ float s_B[SCAN_T][16];
    __shared__ float s_C[SCAN_T][16];

    const int b = blockIdx.y;
    const int d0 = blockIdx.x * 8;
    const int tid = threadIdx.x;
    const int ch = tid >> 4;
    const int n  = tid & 15;
    const int d  = d0 + ch;

    const float Areg = -expf(A_log[d * DSTATE + n]);
    const float Dreg = Dp[d];
    float h = 0.f;

    for (int t0 = 0; t0 < SEQ; t0 += SCAN_T) {
        for (int i = tid; i < SCAN_T * 8; i += 128) {
            int tt = i >> 3, cc = i & 7;
            size_t base = (size_t)(b * SEQ + t0 + tt);
            s_d[tt][cc] = delta[base * DINNER + d0 + cc];
            s_u[tt][cc] = u[base * DINNER + d0 + cc];
            s_z[tt][cc] = xz[base * (2 * DINNER) + DINNER + d0 + cc];
        }
        for (int i = tid; i < SCAN_T * 16; i += 128) {
            int tt = i >> 4, nn = i & 15;
            size_t base = (size_t)(b * SEQ + t0 + tt);
            s_B[tt][nn] = xdbl[base * DXL + DTRANK + nn];
            s_C[tt][nn] = xdbl[base * DXL + DTRANK + DSTATE + nn];
        }
        __syncthreads();

#pragma unroll 4
        for (int tt = 0; tt < SCAN_T; tt++) {
            float dt = s_d[tt][ch];
            float ut = s_u[tt][ch];
            float dA = expf(dt * Areg);
            h = dA * h + dt * s_B[tt][n] * ut;
            float part = h * s_C[tt][n];
#pragma unroll
            for (int off = 8; off; off >>= 1)
                part += __shfl_xor_sync(0xFFFFFFFFu, part, off);
            if (n == 0) {
                float yv = part + ut * Dreg;
                float z = s_z[tt][ch];
                yv *= z / (1.f + expf(-z));
                size_t oidx = ((size_t)(b * SEQ + t0 + tt)) * DINNER + d;
                y[oidx] = yv;
                __half hh, ll;
                split_fp16(yv, hh, ll);
                y_hi[oidx] = hh; y_lo[oidx] = ll;
            }
        }
        __syncthreads();
    }
}

// ---------------- launch -------------------------------------------------------
extern "C" void kernel_launch(void* const* d_in, const int* in_sizes, int n_in,
                              void* d_out, int out_size) {
    const float* hs    = (const float*)d_in[0];
    const float* inw   = (const float*)d_in[1];
    const float* convw = (const float*)d_in[2];
    const float* convb = (const float*)d_in[3];
    const float* xpw   = (const float*)d_in[4];
    const float* dtw   = (const float*)d_in[5];
    const float* dtb   = (const float*)d_in[6];
    const float* alog  = (const float*)d_in[7];
    const float* Dp    = (const float*)d_in[8];
    const float* outw  = (const float*)d_in[9];
    float* out = (float*)d_out;

    float *xz, *u, *xdbl, *part, *delta, *y;
    cudaGetSymbolAddress((void**)&xz,    g_xz);
    cudaGetSymbolAddress((void**)&u,     g_u);
    cudaGetSymbolAddress((void**)&xdbl,  g_xdbl);
    cudaGetSymbolAddress((void**)&part,  g_part);
    cudaGetSymbolAddress((void**)&delta, g_delta);
    cudaGetSymbolAddress((void**)&y,     g_y);

    __half *hs_hi, *hs_lo, *inw_hi, *inw_lo, *u_hi, *u_lo, *xpw_hi, *xpw_lo;
    __half *dt_hi, *dt_lo, *dtw_hi, *dtw_lo, *y_hi, *y_lo, *outw_hi, *outw_lo;
    cudaGetSymbolAddress((void**)&hs_hi,  g_hs_hi);   cudaGetSymbolAddress((void**)&hs_lo,  g_hs_lo);
    cudaGetSymbolAddress((void**)&inw_hi, g_inw_hi);  cudaGetSymbolAddress((void**)&inw_lo, g_inw_lo);
    cudaGetSymbolAddress((void**)&u_hi,   g_u_hi);    cudaGetSymbolAddress((void**)&u_lo,   g_u_lo);
    cudaGetSymbolAddress((void**)&xpw_hi, g_xpw_hi);  cudaGetSymbolAddress((void**)&xpw_lo, g_xpw_lo);
    cudaGetSymbolAddress((void**)&dt_hi,  g_dt_hi);   cudaGetSymbolAddress((void**)&dt_lo,  g_dt_lo);
    cudaGetSymbolAddress((void**)&dtw_hi, g_dtw_hi);  cudaGetSymbolAddress((void**)&dtw_lo, g_dtw_lo);
    cudaGetSymbolAddress((void**)&y_hi,   g_y_hi);    cudaGetSymbolAddress((void**)&y_lo,   g_y_lo);
    cudaGetSymbolAddress((void**)&outw_hi,g_outw_hi); cudaGetSymbolAddress((void**)&outw_lo,g_outw_lo);

    cudaFuncSetAttribute((const void*)gemm_mma<0,2>, cudaFuncAttributeMaxDynamicSharedMemorySize, GEMM_SMEM);
    cudaFuncSetAttribute((const void*)gemm_mma<0,3>, cudaFuncAttributeMaxDynamicSharedMemorySize, GEMM_SMEM);
    cudaFuncSetAttribute((const void*)gemm_mma<1,3>, cudaFuncAttributeMaxDynamicSharedMemorySize, GEMM_SMEM);

    const int CT = 256;
    // ---- in_proj (2-pass fp16) ----
    cvt_kernel<<<(NROWS * DMODEL / 4 + CT - 1) / CT, CT>>>(hs,  hs_hi,  hs_lo,  NROWS, DMODEL, DMODEL, NROWS);
    cvt_kernel<<<(2 * DINNER * DMODEL / 4 + CT - 1) / CT, CT>>>(inw, inw_hi, inw_lo, 2 * DINNER, DMODEL, DMODEL, 2 * DINNER);
    gemm_mma<0,2><<<dim3(32, 32), 256, GEMM_SMEM>>>(hs_hi, hs_lo, inw_hi, inw_lo,
                                                    xz, nullptr, DMODEL, 2 * DINNER, 2 * DINNER, DMODEL, 0);
    // ---- conv + silu (+u split) ----
    conv_silu_kernel<<<(NROWS * DINNER + CT - 1) / CT, CT>>>(xz, convw, convb, u, u_hi, u_lo);
    // ---- x_proj: split-K=4 (3-pass) ----
    cvt_kernel<<<(128 * DINNER / 4 + CT - 1) / CT, CT>>>(xpw, xpw_hi, xpw_lo, 128, DINNER, DINNER, DXL);
    gemm_mma<0,3><<<dim3(1, 32, KSPLIT), 256, GEMM_SMEM>>>(u_hi, u_lo, xpw_hi, xpw_lo,
                                                           part, nullptr, DINNER, DXL, DXL,
                                                           DINNER / KSPLIT, (size_t)NROWS * DXL);
    reduce_xdbl_kernel<<<(NROWS * DXL + CT - 1) / CT, CT>>>(part, xdbl, dt_hi, dt_lo);
    // ---- dt_proj + softplus (3-pass) ----
    cvt_kernel<<<(DINNER * DTRANK / 4 + CT - 1) / CT, CT>>>(dtw, dtw_hi, dtw_lo, DINNER, DTRANK, DTRANK, DINNER);
    gemm_mma<1,3><<<dim3(16, 32), 256, GEMM_SMEM>>>(dt_hi, dt_lo, dtw_hi, dtw_lo,
                                                    delta, dtb, DTRANK, DINNER, DINNER, DTRANK, 0);
    // ---- selective scan (+y split) ----
    scan_kernel<<<dim3(DINNER / 8, BATCH), 128>>>(delta, xdbl, u, xz, alog, Dp, y, y_hi, y_lo);
    // ---- out_proj (2-pass fp16) ----
    cvt_kernel<<<(DMODEL * DINNER / 4 + CT - 1) / CT, CT>>>(outw, outw_hi, outw_lo, DMODEL, DINNER, DINNER, DMODEL);
    gemm_mma<0,2><<<dim3(8, 32), 256, GEMM_SMEM>>>(y_hi, y_lo, outw_hi, outw_lo,
                                                   out, nullptr, DINNER, DMODEL, DMODEL, DINNER, 0);
}

// round 11
// speedup vs baseline: 2.3561x; 1.0093x over previous
#include <cuda_runtime.h>
#include <cuda_bf16.h>
#include <cuda_fp16.h>
#include <math.h>
#include <stdint.h>

#define BATCH 2
#define SEQ 2048
#define DMODEL 1024
#define DINNER 2048
#define DSTATE 16
#define DTRANK 64
#define DXL 96           // DT_RANK + 2*D_STATE
#define NROWS (BATCH*SEQ) // 4096
#define KSPLIT 4

// ---------------- fp32 scratch ----------------
__device__ float g_xz[(size_t)NROWS * 2 * DINNER];
__device__ float g_u[(size_t)NROWS * DINNER];
__device__ float g_xdbl[(size_t)NROWS * DXL];
__device__ float g_part[(size_t)KSPLIT * NROWS * DXL];
__device__ float g_delta[(size_t)NROWS * DINNER];
__device__ float g_y[(size_t)NROWS * DINNER];

// ---------------- fp16 hi/lo scratch ----------------
__device__ __half g_hs_hi[(size_t)NROWS * DMODEL];
__device__ __half g_hs_lo[(size_t)NROWS * DMODEL];
__device__ __half g_inw_hi[(size_t)2 * DINNER * DMODEL];
__device__ __half g_inw_lo[(size_t)2 * DINNER * DMODEL];
__device__ __half g_u_hi[(size_t)NROWS * DINNER];
__device__ __half g_u_lo[(size_t)NROWS * DINNER];
__device__ __half g_xpw_hi[(size_t)128 * DINNER];
__device__ __half g_xpw_lo[(size_t)128 * DINNER];
__device__ __half g_dt_hi[(size_t)NROWS * DTRANK];
__device__ __half g_dt_lo[(size_t)NROWS * DTRANK];
__device__ __half g_dtw_hi[(size_t)DINNER * DTRANK];
__device__ __half g_dtw_lo[(size_t)DINNER * DTRANK];
__device__ __half g_y_hi[(size_t)NROWS * DINNER];
__device__ __half g_y_lo[(size_t)NROWS * DINNER];
__device__ __half g_outw_hi[(size_t)DMODEL * DINNER];
__device__ __half g_outw_lo[(size_t)DMODEL * DINNER];

// ---------------- helpers ----------------
__device__ __forceinline__ uint32_t smem_u32(const void* p) {
    uint32_t a;
    asm("{ .reg .u64 t; cvta.to.shared.u64 t, %1; cvt.u32.u64 %0, t; }" : "=r"(a) : "l"(p));
    return a;
}
__device__ __forceinline__ void split_fp16(float v, __half& h, __half& l) {
    h = __float2half(v);
    l = __float2half(v - __half2float(h));
}

// ---------------- fp32 -> fp16 hi/lo conversion (vectorized x4) ----------------
__global__ void cvt_kernel(const float* __restrict__ src,
                           __half* __restrict__ hi,
                           __half* __restrict__ lo,
                           int Rp, int Cc, int srcStride, int Rvalid) {
    int idx4 = (blockIdx.x * blockDim.x + threadIdx.x) * 4;
    if (idx4 >= Rp * Cc) return;
    int r = idx4 / Cc, c = idx4 % Cc;
    float4 v;
    if (r < Rvalid) v = *(const float4*)(src + (size_t)r * srcStride + c);
    else            v = make_float4(0.f, 0.f, 0.f, 0.f);
    __half h0, l0, h1, l1, h2, l2, h3, l3;
    split_fp16(v.x, h0, l0); split_fp16(v.y, h1, l1);
    split_fp16(v.z, h2, l2); split_fp16(v.w, h3, l3);
    *(__half2*)(hi + idx4)     = __halves2half2(h0, h1);
    *(__half2*)(hi + idx4 + 2) = __halves2half2(h2, h3);
    *(__half2*)(lo + idx4)     = __halves2half2(l0, l1);
    *(__half2*)(lo + idx4 + 2) = __halves2half2(l2, l3);
}

// ---------------- classic mma.sync GEMM, fp16 split ----------------
// NPASS==2: C = (Ah+Al)*Bh   -> 3 tiles/stage, 3-stage pipeline, 1 barrier/chunk
// NPASS==3: C = Ah*Bh + Ah*Bl + Al*Bh -> 4 tiles/stage, 2-stage pipeline
#define RS 40
#define TILE_ELEMS (128 * RS)
#define TILE_BYTES (TILE_ELEMS * 2)    // 10240
#define SMEM_P2 (3 * 3 * TILE_BYTES)   // 92160  (3 stages x 3 tiles)
#define SMEM_P3 (2 * 4 * TILE_BYTES)   // 81920  (2 stages x 4 tiles)

#define MMA_OP(ACC, AF, BF) \
    asm volatile("mma.sync.aligned.m16n8k16.row.col.f32.f16.f16.f32 " \
                 "{%0,%1,%2,%3}, {%4,%5,%6,%7}, {%8,%9}, {%0,%1,%2,%3};" \
                 : "+f"((ACC)[0]), "+f"((ACC)[1]), "+f"((ACC)[2]), "+f"((ACC)[3]) \
                 : "r"((AF)[0]), "r"((AF)[1]), "r"((AF)[2]), "r"((AF)[3]), \
                   "r"((BF)[0]), "r"((BF)[1]))

#define LDSM_X4(R0, R1, R2, R3, ADDR) \
    asm volatile("ldmatrix.sync.aligned.m8n8.x4.shared.b16 {%0,%1,%2,%3}, [%4];" \
                 : "=r"(R0), "=r"(R1), "=r"(R2), "=r"(R3) : "r"(ADDR))

template <int EPI, int NPASS>
__global__ __launch_bounds__(256, 2)
void gemm_mma(const __half* __restrict__ Ahi, const __half* __restrict__ Alo,
              const __half* __restrict__ Bhi, const __half* __restrict__ Blo,
              float* __restrict__ C, const float* __restrict__ bias,
              int K, int ldc, int Nvalid, int Kloop, size_t partStride) {
    extern __shared__ char smem[];
    const uint32_t sb = smem_u32(smem);
    const int tid = threadIdx.x;
    const int wid = tid >> 5, lane = tid & 31;
    const int warp_m = wid >> 2, warp_n = wid & 3;
    const int bm = blockIdx.y * 128, bn = blockIdx.x * 128;
    const int koff = blockIdx.z * Kloop;
    const int NC = Kloop >> 5;

    constexpr int NT = (NPASS == 2) ? 3 : 4;            // tiles per stage
    constexpr uint32_t SBYTES = (uint32_t)NT * TILE_BYTES;

    // --- precomputed ldmatrix offsets (loop-invariant) ---
    uint32_t offA[4], offB[2];
    {
        const int arow = lane & 15;
        const int acol = (lane >> 4) << 3;
#pragma unroll
        for (int mi = 0; mi < 4; mi++)
            offA[mi] = (uint32_t)((warp_m * 64 + mi * 16 + arow) * (RS * 2) + acol * 2);
        const int bcol = ((lane >> 3) & 1) << 3;
#pragma unroll
        for (int p = 0; p < 2; p++) {
            int r = warp_n * 32 + p * 16 + ((lane >> 4) << 3) + (lane & 7);
            offB[p] = (uint32_t)(r * (RS * 2) + bcol * 2);
        }
    }

    float acc[4][4][4];
#pragma unroll
    for (int i = 0; i < 4; i++)
#pragma unroll
        for (int j = 0; j < 4; j++)
#pragma unroll
            for (int q = 0; q < 4; q++) acc[i][j][q] = 0.f;

    auto load_stage = [&](int c, uint32_t sbase) {
        size_t k0 = (size_t)koff + (size_t)c * 32;
        const int NIT = (NPASS == 2) ? 6 : 8;           // 2 cp.asyncs per tile
#pragma unroll
        for (int it = 0; it < NIT; it++) {
            int t = tid + it * 256;
            int tile = t >> 9;
            int s = t & 511;
            int row = s >> 2, seg = s & 3;
            const char* src;
            if (tile == 0)      src = (const char*)(Ahi + (size_t)(bm + row) * K + k0) + seg * 16;
            else if (tile == 1) src = (const char*)(Alo + (size_t)(bm + row) * K + k0) + seg * 16;
            else if (tile == 2) src = (const char*)(Bhi + (size_t)(bn + row) * K + k0) + seg * 16;
            else                src = (const char*)(Blo + (size_t)(bn + row) * K + k0) + seg * 16;
            uint32_t dst = sbase + (uint32_t)(tile * TILE_BYTES + row * (RS * 2) + seg * 16);
            asm volatile("cp.async.cg.shared.global [%0], [%1], 16;" :: "r"(dst), "l"(src) : "memory");
        }
        asm volatile("cp.async.commit_group;" ::: "memory");
    };

    auto compute_chunk = [&](uint32_t sbase) {
        const uint32_t aHiB = sbase;
        const uint32_t aLoB = sbase + TILE_BYTES;
        const uint32_t bHiB = sbase + 2 * TILE_BYTES;
        const uint32_t bLoB = sbase + 3 * TILE_BYTES;   // NPASS==3 only
#pragma unroll
        for (int ks = 0; ks < 2; ks++) {
            const uint32_t kb = (uint32_t)(ks * 32);

            uint32_t aH[4][4], bH[4][2];
#pragma unroll
            for (int mi = 0; mi < 4; mi++)
                LDSM_X4(aH[mi][0], aH[mi][1], aH[mi][2], aH[mi][3], aHiB + offA[mi] + kb);
#pragma unroll
            for (int p = 0; p < 2; p++)
                LDSM_X4(bH[2*p][0], bH[2*p][1], bH[2*p+1][0], bH[2*p+1][1], bHiB + offB[p] + kb);

            if (NPASS == 2) {
                // hoist aL loads so their latency hides under pass-1 MMAs
                uint32_t aL[4][4];
#pragma unroll
                for (int mi = 0; mi < 4; mi++)
                    LDSM_X4(aL[mi][0], aL[mi][1], aL[mi][2], aL[mi][3], aLoB + offA[mi] + kb);
#pragma unroll
                for (int mi = 0; mi < 4; mi++)
#pragma unroll
                    for (int ni = 0; ni < 4; ni++) MMA_OP(acc[mi][ni], aH[mi], bH[ni]);
#pragma unroll
                for (int mi = 0; mi < 4; mi++)
#pragma unroll
                    for (int ni = 0; ni < 4; ni++) MMA_OP(acc[mi][ni], aL[mi], bH[ni]);
            } else {
#pragma unroll
                for (int mi = 0; mi < 4; mi++)
#pragma unroll
                    for (int ni = 0; ni < 4; ni++) MMA_OP(acc[mi][ni], aH[mi], bH[ni]);
                {
                    uint32_t bL[4][2];
#pragma unroll
                    for (int p = 0; p < 2; p++)
                        LDSM_X4(bL[2*p][0], bL[2*p][1], bL[2*p+1][0], bL[2*p+1][1], bLoB + offB[p] + kb);
#pragma unroll
                    for (int mi = 0; mi < 4; mi++)
#pragma unroll
                        for (int ni = 0; ni < 4; ni++) MMA_OP(acc[mi][ni], aH[mi], bL[ni]);
                }
                {
                    uint32_t aL[4][4];
#pragma unroll
                    for (int mi = 0; mi < 4; mi++)
                        LDSM_X4(aL[mi][0], aL[mi][1], aL[mi][2], aL[mi][3], aLoB + offA[mi] + kb);
#pragma unroll
                    for (int mi = 0; mi < 4; mi++)
#pragma unroll
                        for (int ni = 0; ni < 4; ni++) MMA_OP(acc[mi][ni], aL[mi], bH[ni]);
                }
            }
        }
    };

    if (NPASS == 2) {
        // ---- 3-stage pipeline, one barrier per chunk ----
        load_stage(0, sb);
        if (NC > 1) load_stage(1, sb + SBYTES);
        int buf = 0;  // = c % 3
        for (int c = 0; c < NC; c++) {
            if (c + 1 < NC) { asm volatile("cp.async.wait_group 1;" ::: "memory"); }
            else            { asm volatile("cp.async.wait_group 0;" ::: "memory"); }
            __syncthreads();   // publishes stage c; separates chunk c-1 reads from stage c+2 writes
            if (c + 2 < NC) {
                int wb = buf + 2; if (wb >= 3) wb -= 3;
                load_stage(c + 2, sb + (uint32_t)wb * SBYTES);
            }
            compute_chunk(sb + (uint32_t)buf * SBYTES);
            if (++buf == 3) buf = 0;
        }
    } else {
        // ---- 2-stage pipeline (two barriers per chunk) ----
        load_stage(0, sb);
        for (int c = 0; c < NC; c++) {
            if (c + 1 < NC) {
                load_stage(c + 1, sb + (uint32_t)((c + 1) & 1) * SBYTES);
                asm volatile("cp.async.wait_group 1;" ::: "memory");
            } else {
                asm volatile("cp.async.wait_group 0;" ::: "memory");
            }
            __syncthreads();
            compute_chunk(sb + (uint32_t)(c & 1) * SBYTES);
            __syncthreads();
        }
    }

    // ---- epilogue ----
    float* Cz = C + partStride * blockIdx.z;
#pragma unroll
    for (int mi = 0; mi < 4; mi++) {
        int row0 = bm + warp_m * 64 + mi * 16 + (lane >> 2);
#pragma unroll
        for (int ni = 0; ni < 4; ni++) {
            int col0 = bn + warp_n * 32 + ni * 8 + ((lane & 3) << 1);
            if (col0 < Nvalid) {
#pragma unroll
                for (int half = 0; half < 2; half++) {
                    int r = row0 + half * 8;
                    float v0 = acc[mi][ni][half * 2 + 0];
                    float v1 = acc[mi][ni][half * 2 + 1];
                    if (EPI == 1) {
                        v0 += bias[col0];
                        v1 += bias[col0 + 1];
                        v0 = (v0 > 20.f) ? v0 : log1pf(expf(v0));
                        v1 = (v1 > 20.f) ? v1 : log1pf(expf(v1));
                    }
                    *(float2*)(Cz + (size_t)r * ldc + col0) = make_float2(v0, v1);
                }
            }
        }
    }
}

// ---------------- conv + SiLU + fp16 split -> u, u_hi, u_lo ------------------
__global__ void conv_silu_kernel(const float* __restrict__ xz,
                                 const float* __restrict__ w,
                                 const float* __restrict__ bias,
                                 float* __restrict__ u,
                                 __half* __restrict__ u_hi,
                                 __half* __restrict__ u_lo) {
    int idx = blockIdx.x * blockDim.x + threadIdx.x;
    if (idx >= NROWS * DINNER) return;
    int c = idx % DINNER;
    int row = idx / DINNER;
    int t = row % SEQ;
    int b = row / SEQ;
    float acc = bias[c];
#pragma unroll
    for (int k = 0; k < 4; k++) {
        int tt = t - 3 + k;
        if (tt >= 0)
            acc += xz[((size_t)(b * SEQ + tt)) * (2 * DINNER) + c] * w[c * 4 + k];
    }
    float v = acc / (1.f + expf(-acc));
    u[idx] = v;
    __half h, l;
    split_fp16(v, h, l);
    u_hi[idx] = h; u_lo[idx] = l;
}

// ---------------- split-K reduce for x_proj + dt split ----------------
__global__ void reduce_xdbl_kernel(const float* __restrict__ part,
                                   float* __restrict__ xdbl,
                                   __half* __restrict__ dt_hi,
                                   __half* __restrict__ dt_lo) {
    int idx = blockIdx.x * blockDim.x + threadIdx.x;
    if (idx >= NROWS * DXL) return;
    float v = 0.f;
#pragma unroll
    for (int z = 0; z < KSPLIT; z++) v += part[(size_t)z * NROWS * DXL + idx];
    xdbl[idx] = v;
    int c = idx % DXL;
    if (c < DTRANK) {
        int r = idx / DXL;
        __half h, l;
        split_fp16(v, h, l);
        dt_hi[r * DTRANK + c] = h;
        dt_lo[r * DTRANK + c] = l;
    }
}

// ---------------- selective scan (+ fused y fp16 split) ----------------------
#define SCAN_T 64
__global__ __launch_bounds__(128, 8)
void scan_kernel(const float* __restrict__ delta,
                 const float* __restrict__ xdbl,
                 const float* __restrict__ u,
                 const float* __restrict__ xz,
                 const float* __restrict__ A_log,
                 const float* __restrict__ Dp,
                 float* __restrict__ y,
                 __half* __restrict__ y_hi,
                 __half* __restrict__ y_lo) {
    __shared__ float s_d[SCAN_T][8];
    __shared__ float s_u[SCAN_T][8];
    __shared__ float s_z[SCAN_T][8];
    __shared__ float s_B[SCAN_T][16];
    __shared__ float s_C[SCAN_T][16];

    const int b = blockIdx.y;
    const int d0 = blockIdx.x * 8;
    const int tid = threadIdx.x;
    const int ch = tid >> 4;
    const int n  = tid & 15;
    const int d  = d0 + ch;

    const float Areg = -expf(A_log[d * DSTATE + n]);
    const float Dreg = Dp[d];
    float h = 0.f;

    for (int t0 = 0; t0 < SEQ; t0 += SCAN_T) {
        for (int i = tid; i < SCAN_T * 8; i += 128) {
            int tt = i >> 3, cc = i & 7;
            size_t base = (size_t)(b * SEQ + t0 + tt);
            s_d[tt][cc] = delta[base * DINNER + d0 + cc];
            s_u[tt][cc] = u[base * DINNER + d0 + cc];
            s_z[tt][cc] = xz[base * (2 * DINNER) + DINNER + d0 + cc];
        }
        for (int i = tid; i < SCAN_T * 16; i += 128) {
            int tt = i >> 4, nn = i & 15;
            size_t base = (size_t)(b * SEQ + t0 + tt);
            s_B[tt][nn] = xdbl[base * DXL + DTRANK + nn];
            s_C[tt][nn] = xdbl[base * DXL + DTRANK + DSTATE + nn];
        }
        __syncthreads();

#pragma unroll 4
        for (int tt = 0; tt < SCAN_T; tt++) {
            float dt = s_d[tt][ch];
            float ut = s_u[tt][ch];
            float dA = expf(dt * Areg);
            h = dA * h + dt * s_B[tt][n] * ut;
            float part = h * s_C[tt][n];
#pragma unroll
            for (int off = 8; off; off >>= 1)
                part += __shfl_xor_sync(0xFFFFFFFFu, part, off);
            if (n == 0) {
                float yv = part + ut * Dreg;
                float z = s_z[tt][ch];
                yv *= z / (1.f + expf(-z));
                size_t oidx = ((size_t)(b * SEQ + t0 + tt)) * DINNER + d;
                y[oidx] = yv;
                __half hh, ll;
                split_fp16(yv, hh, ll);
                y_hi[oidx] = hh; y_lo[oidx] = ll;
            }
        }
        __syncthreads();
    }
}

// ---------------- launch -------------------------------------------------------
extern "C" void kernel_launch(void* const* d_in, const int* in_sizes, int n_in,
                              void* d_out, int out_size) {
    const float* hs    = (const float*)d_in[0];
    const float* inw   = (const float*)d_in[1];
    const float* convw = (const float*)d_in[2];
    const float* convb = (const float*)d_in[3];
    const float* xpw   = (const float*)d_in[4];
    const float* dtw   = (const float*)d_in[5];
    const float* dtb   = (const float*)d_in[6];
    const float* alog  = (const float*)d_in[7];
    const float* Dp    = (const float*)d_in[8];
    const float* outw  = (const float*)d_in[9];
    float* out = (float*)d_out;

    float *xz, *u, *xdbl, *part, *delta, *y;
    cudaGetSymbolAddress((void**)&xz,    g_xz);
    cudaGetSymbolAddress((void**)&u,     g_u);
    cudaGetSymbolAddress((void**)&xdbl,  g_xdbl);
    cudaGetSymbolAddress((void**)&part,  g_part);
    cudaGetSymbolAddress((void**)&delta, g_delta);
    cudaGetSymbolAddress((void**)&y,     g_y);

    __half *hs_hi, *hs_lo, *inw_hi, *inw_lo, *u_hi, *u_lo, *xpw_hi, *xpw_lo;
    __half *dt_hi, *dt_lo, *dtw_hi, *dtw_lo, *y_hi, *y_lo, *outw_hi, *outw_lo;
    cudaGetSymbolAddress((void**)&hs_hi,  g_hs_hi);   cudaGetSymbolAddress((void**)&hs_lo,  g_hs_lo);
    cudaGetSymbolAddress((void**)&inw_hi, g_inw_hi);  cudaGetSymbolAddress((void**)&inw_lo, g_inw_lo);
    cudaGetSymbolAddress((void**)&u_hi,   g_u_hi);    cudaGetSymbolAddress((void**)&u_lo,   g_u_lo);
    cudaGetSymbolAddress((void**)&xpw_hi, g_xpw_hi);  cudaGetSymbolAddress((void**)&xpw_lo, g_xpw_lo);
    cudaGetSymbolAddress((void**)&dt_hi,  g_dt_hi);   cudaGetSymbolAddress((void**)&dt_lo,  g_dt_lo);
    cudaGetSymbolAddress((void**)&dtw_hi, g_dtw_hi);  cudaGetSymbolAddress((void**)&dtw_lo, g_dtw_lo);
    cudaGetSymbolAddress((void**)&y_hi,   g_y_hi);    cudaGetSymbolAddress((void**)&y_lo,   g_y_lo);
    cudaGetSymbolAddress((void**)&outw_hi,g_outw_hi); cudaGetSymbolAddress((void**)&outw_lo,g_outw_lo);

    cudaFuncSetAttribute((const void*)gemm_mma<0,2>, cudaFuncAttributeMaxDynamicSharedMemorySize, SMEM_P2);
    cudaFuncSetAttribute((const void*)gemm_mma<0,3>, cudaFuncAttributeMaxDynamicSharedMemorySize, SMEM_P3);
    cudaFuncSetAttribute((const void*)gemm_mma<1,3>, cudaFuncAttributeMaxDynamicSharedMemorySize, SMEM_P3);

    const int CT = 256;
    // ---- in_proj (2-pass fp16, 3-stage) ----
    cvt_kernel<<<(NROWS * DMODEL / 4 + CT - 1) / CT, CT>>>(hs,  hs_hi,  hs_lo,  NROWS, DMODEL, DMODEL, NROWS);
    cvt_kernel<<<(2 * DINNER * DMODEL / 4 + CT - 1) / CT, CT>>>(inw, inw_hi, inw_lo, 2 * DINNER, DMODEL, DMODEL, 2 * DINNER);
    gemm_mma<0,2><<<dim3(32, 32), 256, SMEM_P2>>>(hs_hi, hs_lo, inw_hi, inw_lo,
                                                  xz, nullptr, DMODEL, 2 * DINNER, 2 * DINNER, DMODEL, 0);
    // ---- conv + silu (+u split) ----
    conv_silu_kernel<<<(NROWS * DINNER + CT - 1) / CT, CT>>>(xz, convw, convb, u, u_hi, u_lo);
    // ---- x_proj: split-K=4 (3-pass, 2-stage) ----
    cvt_kernel<<<(128 * DINNER / 4 + CT - 1) / CT, CT>>>(xpw, xpw_hi, xpw_lo, 128, DINNER, DINNER, DXL);
    gemm_mma<0,3><<<dim3(1, 32, KSPLIT), 256, SMEM_P3>>>(u_hi, u_lo, xpw_hi, xpw_lo,
                                                         part, nullptr, DINNER, DXL, DXL,
                                                         DINNER / KSPLIT, (size_t)NROWS * DXL);
    reduce_xdbl_kernel<<<(NROWS * DXL + CT - 1) / CT, CT>>>(part, xdbl, dt_hi, dt_lo);
    // ---- dt_proj + softplus (3-pass, 2-stage) ----
    cvt_kernel<<<(DINNER * DTRANK / 4 + CT - 1) / CT, CT>>>(dtw, dtw_hi, dtw_lo, DINNER, DTRANK, DTRANK, DINNER);
    gemm_mma<1,3><<<dim3(16, 32), 256, SMEM_P3>>>(dt_hi, dt_lo, dtw_hi, dtw_lo,
                                                  delta, dtb, DTRANK, DINNER, DINNER, DTRANK, 0);
    // ---- selective scan (+y split) ----
    scan_kernel<<<dim3(DINNER / 8, BATCH), 128>>>(delta, xdbl, u, xz, alog, Dp, y, y_hi, y_lo);
    // ---- out_proj (2-pass fp16, 3-stage) ----
    cvt_kernel<<<(DMODEL * DINNER / 4 + CT - 1) / CT, CT>>>(outw, outw_hi, outw_lo, DMODEL, DINNER, DINNER, DMODEL);
    gemm_mma<0,2><<<dim3(8, 32), 256, SMEM_P2>>>(y_hi, y_lo, outw_hi, outw_lo,
                                                 out, nullptr, DINNER, DMODEL, DMODEL, DINNER, 0);
}

// round 12
// speedup vs baseline: 2.7227x; 1.1556x over previous
#include <cuda_runtime.h>
#include <cuda_bf16.h>
#include <cuda_fp16.h>
#include <math.h>
#include <stdint.h>

#define BATCH 2
#define SEQ 2048
#define DMODEL 1024
#define DINNER 2048
#define DSTATE 16
#define DTRANK 64
#define DXL 96           // DT_RANK + 2*D_STATE
#define NROWS (BATCH*SEQ) // 4096
#define KSPLIT 4

// ---------------- fp32 scratch ----------------
__device__ float g_xz[(size_t)NROWS * 2 * DINNER];
__device__ float g_u[(size_t)NROWS * DINNER];
__device__ float g_xdbl[(size_t)NROWS * DXL];
__device__ float g_part[(size_t)KSPLIT * NROWS * DXL];
__device__ float g_delta[(size_t)NROWS * DINNER];
__device__ float g_y[(size_t)NROWS * DINNER];

// ---------------- fp16 hi/lo scratch ----------------
__device__ __half g_hs_hi[(size_t)NROWS * DMODEL];
__device__ __half g_hs_lo[(size_t)NROWS * DMODEL];
__device__ __half g_inw_hi[(size_t)2 * DINNER * DMODEL];
__device__ __half g_u_hi[(size_t)NROWS * DINNER];
__device__ __half g_u_lo[(size_t)NROWS * DINNER];
__device__ __half g_xpw_hi[(size_t)128 * DINNER];
__device__ __half g_xpw_lo[(size_t)128 * DINNER];
__device__ __half g_dt_hi[(size_t)NROWS * DTRANK];
__device__ __half g_dt_lo[(size_t)NROWS * DTRANK];
__device__ __half g_dtw_hi[(size_t)DINNER * DTRANK];
__device__ __half g_dtw_lo[(size_t)DINNER * DTRANK];
__device__ __half g_y_hi[(size_t)NROWS * DINNER];
__device__ __half g_outw_hi[(size_t)DMODEL * DINNER];

// ---------------- helpers ----------------
__device__ __forceinline__ uint32_t smem_u32(const void* p) {
    uint32_t a;
    asm("{ .reg .u64 t; cvta.to.shared.u64 t, %1; cvt.u32.u64 %0, t; }" : "=r"(a) : "l"(p));
    return a;
}
__device__ __forceinline__ void split_fp16(float v, __half& h, __half& l) {
    h = __float2half(v);
    l = __float2half(v - __half2float(h));
}

// ---------------- fp32 -> fp16 hi(/lo) conversion (vectorized x4) ----------------
__global__ void cvt_kernel(const float* __restrict__ src,
                           __half* __restrict__ hi,
                           __half* __restrict__ lo,
                           int Rp, int Cc, int srcStride, int Rvalid) {
    int idx4 = (blockIdx.x * blockDim.x + threadIdx.x) * 4;
    if (idx4 >= Rp * Cc) return;
    int r = idx4 / Cc, c = idx4 % Cc;
    float4 v;
    if (r < Rvalid) v = *(const float4*)(src + (size_t)r * srcStride + c);
    else            v = make_float4(0.f, 0.f, 0.f, 0.f);
    __half h0, l0, h1, l1, h2, l2, h3, l3;
    split_fp16(v.x, h0, l0); split_fp16(v.y, h1, l1);
    split_fp16(v.z, h2, l2); split_fp16(v.w, h3, l3);
    *(__half2*)(hi + idx4)     = __halves2half2(h0, h1);
    *(__half2*)(hi + idx4 + 2) = __halves2half2(h2, h3);
    if (lo) {
        *(__half2*)(lo + idx4)     = __halves2half2(l0, l1);
        *(__half2*)(lo + idx4 + 2) = __halves2half2(l2, l3);
    }
}

// ---------------- classic mma.sync GEMM, fp16 ----------------
// NPASS==1: C = Ah*Bh            -> 2 tiles/stage, 4-stage pipeline
// NPASS==3: C = Ah*Bh+Ah*Bl+Al*Bh -> 4 tiles/stage, 2-stage pipeline
#define RS 40
#define TILE_ELEMS (128 * RS)
#define TILE_BYTES (TILE_ELEMS * 2)    // 10240
#define SMEM_P1 (4 * 2 * TILE_BYTES)   // 81920  (4 stages x 2 tiles)
#define SMEM_P3 (2 * 4 * TILE_BYTES)   // 81920  (2 stages x 4 tiles)

#define MMA_OP(ACC, AF, BF) \
    asm volatile("mma.sync.aligned.m16n8k16.row.col.f32.f16.f16.f32 " \
                 "{%0,%1,%2,%3}, {%4,%5,%6,%7}, {%8,%9}, {%0,%1,%2,%3};" \
                 : "+f"((ACC)[0]), "+f"((ACC)[1]), "+f"((ACC)[2]), "+f"((ACC)[3]) \
                 : "r"((AF)[0]), "r"((AF)[1]), "r"((AF)[2]), "r"((AF)[3]), \
                   "r"((BF)[0]), "r"((BF)[1]))

#define LDSM_X4(R0, R1, R2, R3, ADDR) \
    asm volatile("ldmatrix.sync.aligned.m8n8.x4.shared.b16 {%0,%1,%2,%3}, [%4];" \
                 : "=r"(R0), "=r"(R1), "=r"(R2), "=r"(R3) : "r"(ADDR))

template <int EPI, int NPASS>
__global__ __launch_bounds__(256, 2)
void gemm_mma(const __half* __restrict__ Ahi, const __half* __restrict__ Alo,
              const __half* __restrict__ Bhi, const __half* __restrict__ Blo,
              float* __restrict__ C, const float* __restrict__ bias,
              int K, int ldc, int Nvalid, int Kloop, size_t partStride) {
    extern __shared__ char smem[];
    const uint32_t sb = smem_u32(smem);
    const int tid = threadIdx.x;
    const int wid = tid >> 5, lane = tid & 31;
    const int warp_m = wid >> 2, warp_n = wid & 3;
    const int bm = blockIdx.y * 128, bn = blockIdx.x * 128;
    const int koff = blockIdx.z * Kloop;
    const int NC = Kloop >> 5;

    constexpr int NT = (NPASS == 1) ? 2 : 4;            // tiles per stage
    constexpr uint32_t SBYTES = (uint32_t)NT * TILE_BYTES;

    // --- precomputed ldmatrix offsets (loop-invariant) ---
    uint32_t offA[4], offB[2];
    {
        const int arow = lane & 15;
        const int acol = (lane >> 4) << 3;
#pragma unroll
        for (int mi = 0; mi < 4; mi++)
            offA[mi] = (uint32_t)((warp_m * 64 + mi * 16 + arow) * (RS * 2) + acol * 2);
        const int bcol = ((lane >> 3) & 1) << 3;
#pragma unroll
        for (int p = 0; p < 2; p++) {
            int r = warp_n * 32 + p * 16 + ((lane >> 4) << 3) + (lane & 7);
            offB[p] = (uint32_t)(r * (RS * 2) + bcol * 2);
        }
    }

    float acc[4][4][4];
#pragma unroll
    for (int i = 0; i < 4; i++)
#pragma unroll
        for (int j = 0; j < 4; j++)
#pragma unroll
            for (int q = 0; q < 4; q++) acc[i][j][q] = 0.f;

    auto load_stage = [&](int c, uint32_t sbase) {
        size_t k0 = (size_t)koff + (size_t)c * 32;
        const int NIT = (NPASS == 1) ? 4 : 8;           // 2 cp.asyncs per tile
#pragma unroll
        for (int it = 0; it < NIT; it++) {
            int t = tid + it * 256;
            int tile = t >> 9;
            int s = t & 511;
            int row = s >> 2, seg = s & 3;
            const char* src;
            if (NPASS == 1) {
                if (tile == 0) src = (const char*)(Ahi + (size_t)(bm + row) * K + k0) + seg * 16;
                else           src = (const char*)(Bhi + (size_t)(bn + row) * K + k0) + seg * 16;
            } else {
                if (tile == 0)      src = (const char*)(Ahi + (size_t)(bm + row) * K + k0) + seg * 16;
                else if (tile == 1) src = (const char*)(Alo + (size_t)(bm + row) * K + k0) + seg * 16;
                else if (tile == 2) src = (const char*)(Bhi + (size_t)(bn + row) * K + k0) + seg * 16;
                else                src = (const char*)(Blo + (size_t)(bn + row) * K + k0) + seg * 16;
            }
            uint32_t dst = sbase + (uint32_t)(tile * TILE_BYTES + row * (RS * 2) + seg * 16);
            asm volatile("cp.async.cg.shared.global [%0], [%1], 16;" :: "r"(dst), "l"(src) : "memory");
        }
        asm volatile("cp.async.commit_group;" ::: "memory");
    };

    auto compute_chunk = [&](uint32_t sbase) {
        const uint32_t aHiB = sbase;
        const uint32_t bHiB = (NPASS == 1) ? (sbase + TILE_BYTES) : (sbase + 2 * TILE_BYTES);
        const uint32_t aLoB = sbase + TILE_BYTES;        // NPASS==3
        const uint32_t bLoB = sbase + 3 * TILE_BYTES;    // NPASS==3
#pragma unroll
        for (int ks = 0; ks < 2; ks++) {
            const uint32_t kb = (uint32_t)(ks * 32);

            uint32_t aH[4][4], bH[4][2];
#pragma unroll
            for (int mi = 0; mi < 4; mi++)
                LDSM_X4(aH[mi][0], aH[mi][1], aH[mi][2], aH[mi][3], aHiB + offA[mi] + kb);
#pragma unroll
            for (int p = 0; p < 2; p++)
                LDSM_X4(bH[2*p][0], bH[2*p][1], bH[2*p+1][0], bH[2*p+1][1], bHiB + offB[p] + kb);

#pragma unroll
            for (int mi = 0; mi < 4; mi++)
#pragma unroll
                for (int ni = 0; ni < 4; ni++) MMA_OP(acc[mi][ni], aH[mi], bH[ni]);

            if (NPASS == 3) {
                {
                    uint32_t bL[4][2];
#pragma unroll
                    for (int p = 0; p < 2; p++)
                        LDSM_X4(bL[2*p][0], bL[2*p][1], bL[2*p+1][0], bL[2*p+1][1], bLoB + offB[p] + kb);
#pragma unroll
                    for (int mi = 0; mi < 4; mi++)
#pragma unroll
                        for (int ni = 0; ni < 4; ni++) MMA_OP(acc[mi][ni], aH[mi], bL[ni]);
                }
                {
                    uint32_t aL[4][4];
#pragma unroll
                    for (int mi = 0; mi < 4; mi++)
                        LDSM_X4(aL[mi][0], aL[mi][1], aL[mi][2], aL[mi][3], aLoB + offA[mi] + kb);
#pragma unroll
                    for (int mi = 0; mi < 4; mi++)
#pragma unroll
                        for (int ni = 0; ni < 4; ni++) MMA_OP(acc[mi][ni], aL[mi], bH[ni]);
                }
            }
        }
    };

    if (NPASS == 1) {
        // ---- 4-stage pipeline, one barrier per chunk, prefetch depth 3 ----
        load_stage(0, sb);
        if (NC > 1) load_stage(1, sb + SBYTES);
        if (NC > 2) load_stage(2, sb + 2 * SBYTES);
        int buf = 0;  // = c % 4
        for (int c = 0; c < NC; c++) {
            int rem = NC - 1 - c;
            if (rem >= 2)      { asm volatile("cp.async.wait_group 2;" ::: "memory"); }
            else if (rem == 1) { asm volatile("cp.async.wait_group 1;" ::: "memory"); }
            else               { asm volatile("cp.async.wait_group 0;" ::: "memory"); }
            __syncthreads();   // publishes stage c; separates chunk c-1 reads from stage c+3 writes
            if (c + 3 < NC) {
                int wb = buf + 3; if (wb >= 4) wb -= 4;
                load_stage(c + 3, sb + (uint32_t)wb * SBYTES);
            }
            compute_chunk(sb + (uint32_t)buf * SBYTES);
            if (++buf == 4) buf = 0;
        }
    } else {
        // ---- 2-stage pipeline ----
        load_stage(0, sb);
        for (int c = 0; c < NC; c++) {
            if (c + 1 < NC) {
                load_stage(c + 1, sb + (uint32_t)((c + 1) & 1) * SBYTES);
                asm volatile("cp.async.wait_group 1;" ::: "memory");
            } else {
                asm volatile("cp.async.wait_group 0;" ::: "memory");
            }
            __syncthreads();
            compute_chunk(sb + (uint32_t)(c & 1) * SBYTES);
            __syncthreads();
        }
    }

    // ---- epilogue ----
    float* Cz = C + partStride * blockIdx.z;
#pragma unroll
    for (int mi = 0; mi < 4; mi++) {
        int row0 = bm + warp_m * 64 + mi * 16 + (lane >> 2);
#pragma unroll
        for (int ni = 0; ni < 4; ni++) {
            int col0 = bn + warp_n * 32 + ni * 8 + ((lane & 3) << 1);
            if (col0 < Nvalid) {
#pragma unroll
                for (int half = 0; half < 2; half++) {
                    int r = row0 + half * 8;
                    float v0 = acc[mi][ni][half * 2 + 0];
                    float v1 = acc[mi][ni][half * 2 + 1];
                    if (EPI == 1) {
                        v0 += bias[col0];
                        v1 += bias[col0 + 1];
                        v0 = (v0 > 20.f) ? v0 : __logf(1.f + __expf(v0));
                        v1 = (v1 > 20.f) ? v1 : __logf(1.f + __expf(v1));
                    }
                    *(float2*)(Cz + (size_t)r * ldc + col0) = make_float2(v0, v1);
                }
            }
        }
    }
}

// ---------------- conv + SiLU + fp16 split -> u, u_hi, u_lo ------------------
__global__ void conv_silu_kernel(const float* __restrict__ xz,
                                 const float* __restrict__ w,
                                 const float* __restrict__ bias,
                                 float* __restrict__ u,
                                 __half* __restrict__ u_hi,
                                 __half* __restrict__ u_lo) {
    int idx = blockIdx.x * blockDim.x + threadIdx.x;
    if (idx >= NROWS * DINNER) return;
    int c = idx % DINNER;
    int row = idx / DINNER;
    int t = row % SEQ;
    int b = row / SEQ;
    float acc = bias[c];
#pragma unroll
    for (int k = 0; k < 4; k++) {
        int tt = t - 3 + k;
        if (tt >= 0)
            acc += xz[((size_t)(b * SEQ + tt)) * (2 * DINNER) + c] * w[c * 4 + k];
    }
    float v = acc / (1.f + __expf(-acc));
    u[idx] = v;
    __half h, l;
    split_fp16(v, h, l);
    u_hi[idx] = h; u_lo[idx] = l;
}

// ---------------- split-K reduce for x_proj + dt split ----------------
__global__ void reduce_xdbl_kernel(const float* __restrict__ part,
                                   float* __restrict__ xdbl,
                                   __half* __restrict__ dt_hi,
                                   __half* __restrict__ dt_lo) {
    int idx = blockIdx.x * blockDim.x + threadIdx.x;
    if (idx >= NROWS * DXL) return;
    float v = 0.f;
#pragma unroll
    for (int z = 0; z < KSPLIT; z++) v += part[(size_t)z * NROWS * DXL + idx];
    xdbl[idx] = v;
    int c = idx % DXL;
    if (c < DTRANK) {
        int r = idx / DXL;
        __half h, l;
        split_fp16(v, h, l);
        dt_hi[r * DTRANK + c] = h;
        dt_lo[r * DTRANK + c] = l;
    }
}

// ---------------- selective scan (+ fused y fp16 hi) ----------------------
#define SCAN_T 64
__global__ __launch_bounds__(128, 8)
void scan_kernel(const float* __restrict__ delta,
                 const float* __restrict__ xdbl,
                 const float* __restrict__ u,
                 const float* __restrict__ xz,
                 const float* __restrict__ A_log,
                 const float* __restrict__ Dp,
                 float* __restrict__ y,
                 __half* __restrict__ y_hi) {
    __shared__ float s_d[SCAN_T][8];
    __shared__ float s_u[SCAN_T][8];
    __shared__ float s_z[SCAN_T][8];
    __shared__ float s_B[SCAN_T][16];
    __shared__ float s_C[SCAN_T][16];

    const int b = blockIdx.y;
    const int d0 = blockIdx.x * 8;
    const int tid = threadIdx.x;
    const int ch = tid >> 4;
    const int n  = tid & 15;
    const int d  = d0 + ch;

    const float Areg = -__expf(A_log[d * DSTATE + n]);
    const float Dreg = Dp[d];
    float h = 0.f;

    for (int t0 = 0; t0 < SEQ; t0 += SCAN_T) {
        for (int i = tid; i < SCAN_T * 8; i += 128) {
            int tt = i >> 3, cc = i & 7;
            size_t base = (size_t)(b * SEQ + t0 + tt);
            s_d[tt][cc] = delta[base * DINNER + d0 + cc];
            s_u[tt][cc] = u[base * DINNER + d0 + cc];
            s_z[tt][cc] = xz[base * (2 * DINNER) + DINNER + d0 + cc];
        }
        for (int i = tid; i < SCAN_T * 16; i += 128) {
            int tt = i >> 4, nn = i & 15;
            size_t base = (size_t)(b * SEQ + t0 + tt);
            s_B[tt][nn] = xdbl[base * DXL + DTRANK + nn];
            s_C[tt][nn] = xdbl[base * DXL + DTRANK + DSTATE + nn];
        }
        __syncthreads();

#pragma unroll 4
        for (int tt = 0; tt < SCAN_T; tt++) {
            float dt = s_d[tt][ch];
            float ut = s_u[tt][ch];
            float dA = __expf(dt * Areg);
            h = dA * h + dt * s_B[tt][n] * ut;
            float part = h * s_C[tt][n];
#pragma unroll
            for (int off = 8; off; off >>= 1)
                part += __shfl_xor_sync(0xFFFFFFFFu, part, off);
            if (n == 0) {
                float yv = part + ut * Dreg;
                float z = s_z[tt][ch];
                yv *= z / (1.f + __expf(-z));
                size_t oidx = ((size_t)(b * SEQ + t0 + tt)) * DINNER + d;
                y[oidx] = yv;
                y_hi[oidx] = __float2half(yv);
            }
        }
        __syncthreads();
    }
}

// ---------------- launch -------------------------------------------------------
extern "C" void kernel_launch(void* const* d_in, const int* in_sizes, int n_in,
                              void* d_out, int out_size) {
    const float* hs    = (const float*)d_in[0];
    const float* inw   = (const float*)d_in[1];
    const float* convw = (const float*)d_in[2];
    const float* convb = (const float*)d_in[3];
    const float* xpw   = (const float*)d_in[4];
    const float* dtw   = (const float*)d_in[5];
    const float* dtb   = (const float*)d_in[6];
    const float* alog  = (const float*)d_in[7];
    const float* Dp    = (const float*)d_in[8];
    const float* outw  = (const float*)d_in[9];
    float* out = (float*)d_out;

    float *xz, *u, *xdbl, *part, *delta, *y;
    cudaGetSymbolAddress((void**)&xz,    g_xz);
    cudaGetSymbolAddress((void**)&u,     g_u);
    cudaGetSymbolAddress((void**)&xdbl,  g_xdbl);
    cudaGetSymbolAddress((void**)&part,  g_part);
    cudaGetSymbolAddress((void**)&delta, g_delta);
    cudaGetSymbolAddress((void**)&y,     g_y);

    __half *hs_hi, *hs_lo, *inw_hi, *u_hi, *u_lo, *xpw_hi, *xpw_lo;
    __half *dt_hi, *dt_lo, *dtw_hi, *dtw_lo, *y_hi, *outw_hi;
    cudaGetSymbolAddress((void**)&hs_hi,  g_hs_hi);   cudaGetSymbolAddress((void**)&hs_lo,  g_hs_lo);
    cudaGetSymbolAddress((void**)&inw_hi, g_inw_hi);
    cudaGetSymbolAddress((void**)&u_hi,   g_u_hi);    cudaGetSymbolAddress((void**)&u_lo,   g_u_lo);
    cudaGetSymbolAddress((void**)&xpw_hi, g_xpw_hi);  cudaGetSymbolAddress((void**)&xpw_lo, g_xpw_lo);
    cudaGetSymbolAddress((void**)&dt_hi,  g_dt_hi);   cudaGetSymbolAddress((void**)&dt_lo,  g_dt_lo);
    cudaGetSymbolAddress((void**)&dtw_hi, g_dtw_hi);  cudaGetSymbolAddress((void**)&dtw_lo, g_dtw_lo);
    cudaGetSymbolAddress((void**)&y_hi,   g_y_hi);
    cudaGetSymbolAddress((void**)&outw_hi,g_outw_hi);

    cudaFuncSetAttribute((const void*)gemm_mma<0,1>, cudaFuncAttributeMaxDynamicSharedMemorySize, SMEM_P1);
    cudaFuncSetAttribute((const void*)gemm_mma<0,3>, cudaFuncAttributeMaxDynamicSharedMemorySize, SMEM_P3);
    cudaFuncSetAttribute((const void*)gemm_mma<1,3>, cudaFuncAttributeMaxDynamicSharedMemorySize, SMEM_P3);

    const int CT = 256;
    // ---- in_proj (1-pass fp16, 4-stage) ----
    cvt_kernel<<<(NROWS * DMODEL / 4 + CT - 1) / CT, CT>>>(hs,  hs_hi,  hs_lo,  NROWS, DMODEL, DMODEL, NROWS);
    cvt_kernel<<<(2 * DINNER * DMODEL / 4 + CT - 1) / CT, CT>>>(inw, inw_hi, nullptr, 2 * DINNER, DMODEL, DMODEL, 2 * DINNER);
    gemm_mma<0,1><<<dim3(32, 32), 256, SMEM_P1>>>(hs_hi, nullptr, inw_hi, nullptr,
                                                  xz, nullptr, DMODEL, 2 * DINNER, 2 * DINNER, DMODEL, 0);
    // ---- conv + silu (+u split) ----
    conv_silu_kernel<<<(NROWS * DINNER + CT - 1) / CT, CT>>>(xz, convw, convb, u, u_hi, u_lo);
    // ---- x_proj: split-K=4 (3-pass, 2-stage) ----
    cvt_kernel<<<(128 * DINNER / 4 + CT - 1) / CT, CT>>>(xpw, xpw_hi, xpw_lo, 128, DINNER, DINNER, DXL);
    gemm_mma<0,3><<<dim3(1, 32, KSPLIT), 256, SMEM_P3>>>(u_hi, u_lo, xpw_hi, xpw_lo,
                                                         part, nullptr, DINNER, DXL, DXL,
                                                         DINNER / KSPLIT, (size_t)NROWS * DXL);
    reduce_xdbl_kernel<<<(NROWS * DXL + CT - 1) / CT, CT>>>(part, xdbl, dt_hi, dt_lo);
    // ---- dt_proj + softplus (3-pass, 2-stage) ----
    cvt_kernel<<<(DINNER * DTRANK / 4 + CT - 1) / CT, CT>>>(dtw, dtw_hi, dtw_lo, DINNER, DTRANK, DTRANK, DINNER);
    gemm_mma<1,3><<<dim3(16, 32), 256, SMEM_P3>>>(dt_hi, dt_lo, dtw_hi, dtw_lo,
                                                  delta, dtb, DTRANK, DINNER, DINNER, DTRANK, 0);
    // ---- selective scan (+y hi) ----
    scan_kernel<<<dim3(DINNER / 8, BATCH), 128>>>(delta, xdbl, u, xz, alog, Dp, y, y_hi);
    // ---- out_proj (1-pass fp16, 4-stage) ----
    cvt_kernel<<<(DMODEL * DINNER / 4 + CT - 1) / CT, CT>>>(outw, outw_hi, nullptr, DMODEL, DINNER, DINNER, DMODEL);
    gemm_mma<0,1><<<dim3(8, 32), 256, SMEM_P1>>>(y_hi, nullptr, outw_hi, nullptr,
                                                 out, nullptr, DINNER, DMODEL, DMODEL, DINNER, 0);
}

// round 14
// speedup vs baseline: 3.1939x; 1.1731x over previous
#include <cuda_runtime.h>
#include <cuda_bf16.h>
#include <cuda_fp16.h>
#include <math.h>
#include <stdint.h>

#define BATCH 2
#define SEQ 2048
#define DMODEL 1024
#define DINNER 2048
#define DSTATE 16
#define DTRANK 64
#define DXL 96           // DT_RANK + 2*D_STATE
#define NROWS (BATCH*SEQ) // 4096
#define KSPLIT 4

// ---------------- fp32 scratch ----------------
__device__ float g_xz[(size_t)NROWS * 2 * DINNER];
__device__ float g_u[(size_t)NROWS * DINNER];
__device__ float g_xdbl[(size_t)NROWS * DXL];
__device__ float g_part[(size_t)KSPLIT * NROWS * DXL];
__device__ float g_delta[(size_t)NROWS * DINNER];

// ---------------- fp16 scratch ----------------
__device__ __half g_hs_hi[(size_t)NROWS * DMODEL];
__device__ __half g_inw_hi[(size_t)2 * DINNER * DMODEL];
__device__ __half g_u_hi[(size_t)NROWS * DINNER];
__device__ __half g_u_lo[(size_t)NROWS * DINNER];
__device__ __half g_xpw_hi[(size_t)128 * DINNER];
__device__ __half g_dt_hi[(size_t)NROWS * DTRANK];
__device__ __half g_dt_lo[(size_t)NROWS * DTRANK];
__device__ __half g_dtw_hi[(size_t)DINNER * DTRANK];
__device__ __half g_y_hi[(size_t)NROWS * DINNER];
__device__ __half g_outw_hi[(size_t)DMODEL * DINNER];

// ---------------- helpers ----------------
__device__ __forceinline__ uint32_t smem_u32(const void* p) {
    uint32_t a;
    asm("{ .reg .u64 t; cvta.to.shared.u64 t, %1; cvt.u32.u64 %0, t; }" : "=r"(a) : "l"(p));
    return a;
}
__device__ __forceinline__ void split_fp16(float v, __half& h, __half& l) {
    h = __float2half(v);
    l = __float2half(v - __half2float(h));
}
__device__ __forceinline__ void store_hi4(__half* hi, int idx4, float4 v) {
    *(__half2*)(hi + idx4)     = __halves2half2(__float2half(v.x), __float2half(v.y));
    *(__half2*)(hi + idx4 + 2) = __halves2half2(__float2half(v.z), __float2half(v.w));
}

// ---------------- fused input conversion: all 5 tensors, hi only ----------------
#define Q_HS   1048576                       // NROWS*DMODEL/4
#define Q_INW  (Q_HS + 1048576)              // + 2*DINNER*DMODEL/4
#define Q_XPW  (Q_INW + 65536)               // + 128*DINNER/4
#define Q_DTW  (Q_XPW + 32768)               // + DINNER*DTRANK/4
#define Q_OUTW (Q_DTW + 524288)              // + DMODEL*DINNER/4
#define CVT_BLOCKS (Q_OUTW / 256)            // 10624

__global__ void cvt_all_kernel(const float* __restrict__ hs, const float* __restrict__ inw,
                               const float* __restrict__ xpw, const float* __restrict__ dtw,
                               const float* __restrict__ outw,
                               __half* __restrict__ hs_hi, __half* __restrict__ inw_hi,
                               __half* __restrict__ xpw_hi, __half* __restrict__ dtw_hi,
                               __half* __restrict__ outw_hi) {
    int q = blockIdx.x * blockDim.x + threadIdx.x;
    if (q < Q_HS) {
        int idx4 = q * 4;
        store_hi4(hs_hi, idx4, *(const float4*)(hs + idx4));
    } else if (q < Q_INW) {
        int idx4 = (q - Q_HS) * 4;
        store_hi4(inw_hi, idx4, *(const float4*)(inw + idx4));
    } else if (q < Q_XPW) {
        int idx4 = (q - Q_INW) * 4;
        int r = idx4 >> 11;   // / DINNER
        float4 v = (r < DXL) ? *(const float4*)(xpw + idx4) : make_float4(0.f, 0.f, 0.f, 0.f);
        store_hi4(xpw_hi, idx4, v);
    } else if (q < Q_DTW) {
        int idx4 = (q - Q_XPW) * 4;
        store_hi4(dtw_hi, idx4, *(const float4*)(dtw + idx4));
    } else {
        int idx4 = (q - Q_DTW) * 4;
        store_hi4(outw_hi, idx4, *(const float4*)(outw + idx4));
    }
}

// ---------------- classic mma.sync GEMM, fp16 ----------------
// NPASS==1: C = Ah*Bh         -> 2 tiles/stage, 4-stage pipeline
// NPASS==2: C = (Ah+Al)*Bh    -> 3 tiles/stage, 2-stage pipeline
#define RS 40
#define TILE_ELEMS (128 * RS)
#define TILE_BYTES (TILE_ELEMS * 2)    // 10240
#define SMEM_P1 (4 * 2 * TILE_BYTES)   // 81920
#define SMEM_P2 (2 * 3 * TILE_BYTES)   // 61440

#define MMA_OP(ACC, AF, BF) \
    asm volatile("mma.sync.aligned.m16n8k16.row.col.f32.f16.f16.f32 " \
                 "{%0,%1,%2,%3}, {%4,%5,%6,%7}, {%8,%9}, {%0,%1,%2,%3};" \
                 : "+f"((ACC)[0]), "+f"((ACC)[1]), "+f"((ACC)[2]), "+f"((ACC)[3]) \
                 : "r"((AF)[0]), "r"((AF)[1]), "r"((AF)[2]), "r"((AF)[3]), \
                   "r"((BF)[0]), "r"((BF)[1]))

#define LDSM_X4(R0, R1, R2, R3, ADDR) \
    asm volatile("ldmatrix.sync.aligned.m8n8.x4.shared.b16 {%0,%1,%2,%3}, [%4];" \
                 : "=r"(R0), "=r"(R1), "=r"(R2), "=r"(R3) : "r"(ADDR))

template <int EPI, int NPASS>
__global__ __launch_bounds__(256, 2)
void gemm_mma(const __half* __restrict__ Ahi, const __half* __restrict__ Alo,
              const __half* __restrict__ Bhi,
              float* __restrict__ C, const float* __restrict__ bias,
              int K, int ldc, int Nvalid, int Kloop, size_t partStride) {
    extern __shared__ char smem[];
    const uint32_t sb = smem_u32(smem);
    const int tid = threadIdx.x;
    const int wid = tid >> 5, lane = tid & 31;
    const int warp_m = wid >> 2, warp_n = wid & 3;
    const int bm = blockIdx.y * 128, bn = blockIdx.x * 128;
    const int koff = blockIdx.z * Kloop;
    const int NC = Kloop >> 5;

    constexpr int NT = (NPASS == 1) ? 2 : 3;
    constexpr uint32_t SBYTES = (uint32_t)NT * TILE_BYTES;

    uint32_t offA[4], offB[2];
    {
        const int arow = lane & 15;
        const int acol = (lane >> 4) << 3;
#pragma unroll
        for (int mi = 0; mi < 4; mi++)
            offA[mi] = (uint32_t)((warp_m * 64 + mi * 16 + arow) * (RS * 2) + acol * 2);
        const int bcol = ((lane >> 3) & 1) << 3;
#pragma unroll
        for (int p = 0; p < 2; p++) {
            int r = warp_n * 32 + p * 16 + ((lane >> 4) << 3) + (lane & 7);
            offB[p] = (uint32_t)(r * (RS * 2) + bcol * 2);
        }
    }

    float acc[4][4][4];
#pragma unroll
    for (int i = 0; i < 4; i++)
#pragma unroll
        for (int j = 0; j < 4; j++)
#pragma unroll
            for (int q = 0; q < 4; q++) acc[i][j][q] = 0.f;

    auto load_stage = [&](int c, uint32_t sbase) {
        size_t k0 = (size_t)koff + (size_t)c * 32;
        const int NIT = (NPASS == 1) ? 4 : 6;   // 2 cp.asyncs per tile
#pragma unroll
        for (int it = 0; it < NIT; it++) {
            int t = tid + it * 256;
            int tile = t >> 9;
            int s = t & 511;
            int row = s >> 2, seg = s & 3;
            const char* src;
            if (NPASS == 1) {
                if (tile == 0) src = (const char*)(Ahi + (size_t)(bm + row) * K + k0) + seg * 16;
                else           src = (const char*)(Bhi + (size_t)(bn + row) * K + k0) + seg * 16;
            } else {
                if (tile == 0)      src = (const char*)(Ahi + (size_t)(bm + row) * K + k0) + seg * 16;
                else if (tile == 1) src = (const char*)(Alo + (size_t)(bm + row) * K + k0) + seg * 16;
                else                src = (const char*)(Bhi + (size_t)(bn + row) * K + k0) + seg * 16;
            }
            uint32_t dst = sbase + (uint32_t)(tile * TILE_BYTES + row * (RS * 2) + seg * 16);
            asm volatile("cp.async.cg.shared.global [%0], [%1], 16;" :: "r"(dst), "l"(src) : "memory");
        }
        asm volatile("cp.async.commit_group;" ::: "memory");
    };

    auto compute_chunk = [&](uint32_t sbase) {
        const uint32_t aHiB = sbase;
        const uint32_t aLoB = sbase + TILE_BYTES;                            // NPASS==2
        const uint32_t bHiB = (NPASS == 1) ? (sbase + TILE_BYTES) : (sbase + 2 * TILE_BYTES);
#pragma unroll
        for (int ks = 0; ks < 2; ks++) {
            const uint32_t kb = (uint32_t)(ks * 32);
            uint32_t aH[4][4], bH[4][2];
#pragma unroll
            for (int mi = 0; mi < 4; mi++)
                LDSM_X4(aH[mi][0], aH[mi][1], aH[mi][2], aH[mi][3], aHiB + offA[mi] + kb);
#pragma unroll
            for (int p = 0; p < 2; p++)
                LDSM_X4(bH[2*p][0], bH[2*p][1], bH[2*p+1][0], bH[2*p+1][1], bHiB + offB[p] + kb);

            if (NPASS == 2) {
                uint32_t aL[4][4];
#pragma unroll
                for (int mi = 0; mi < 4; mi++)
                    LDSM_X4(aL[mi][0], aL[mi][1], aL[mi][2], aL[mi][3], aLoB + offA[mi] + kb);
#pragma unroll
                for (int mi = 0; mi < 4; mi++)
#pragma unroll
                    for (int ni = 0; ni < 4; ni++) MMA_OP(acc[mi][ni], aH[mi], bH[ni]);
#pragma unroll
                for (int mi = 0; mi < 4; mi++)
#pragma unroll
                    for (int ni = 0; ni < 4; ni++) MMA_OP(acc[mi][ni], aL[mi], bH[ni]);
            } else {
#pragma unroll
                for (int mi = 0; mi < 4; mi++)
#pragma unroll
                    for (int ni = 0; ni < 4; ni++) MMA_OP(acc[mi][ni], aH[mi], bH[ni]);
            }
        }
    };

    if (NPASS == 1) {
        // 4-stage pipeline, one barrier per chunk, prefetch depth 3
        load_stage(0, sb);
        if (NC > 1) load_stage(1, sb + SBYTES);
        if (NC > 2) load_stage(2, sb + 2 * SBYTES);
        int buf = 0;
        for (int c = 0; c < NC; c++) {
            int rem = NC - 1 - c;
            if (rem >= 2)      { asm volatile("cp.async.wait_group 2;" ::: "memory"); }
            else if (rem == 1) { asm volatile("cp.async.wait_group 1;" ::: "memory"); }
            else               { asm volatile("cp.async.wait_group 0;" ::: "memory"); }
            __syncthreads();
            if (c + 3 < NC) {
                int wb = buf + 3; if (wb >= 4) wb -= 4;
                load_stage(c + 3, sb + (uint32_t)wb * SBYTES);
            }
            compute_chunk(sb + (uint32_t)buf * SBYTES);
            if (++buf == 4) buf = 0;
        }
    } else {
        // 2-stage pipeline
        load_stage(0, sb);
        for (int c = 0; c < NC; c++) {
            if (c + 1 < NC) {
                load_stage(c + 1, sb + (uint32_t)((c + 1) & 1) * SBYTES);
                asm volatile("cp.async.wait_group 1;" ::: "memory");
            } else {
                asm volatile("cp.async.wait_group 0;" ::: "memory");
            }
            __syncthreads();
            compute_chunk(sb + (uint32_t)(c & 1) * SBYTES);
            __syncthreads();
        }
    }

    // ---- epilogue ----
    float* Cz = C + partStride * blockIdx.z;
#pragma unroll
    for (int mi = 0; mi < 4; mi++) {
        int row0 = bm + warp_m * 64 + mi * 16 + (lane >> 2);
#pragma unroll
        for (int ni = 0; ni < 4; ni++) {
            int col0 = bn + warp_n * 32 + ni * 8 + ((lane & 3) << 1);
            if (col0 < Nvalid) {
#pragma unroll
                for (int half = 0; half < 2; half++) {
                    int r = row0 + half * 8;
                    float v0 = acc[mi][ni][half * 2 + 0];
                    float v1 = acc[mi][ni][half * 2 + 1];
                    if (EPI == 1) {
                        v0 += bias[col0];
                        v1 += bias[col0 + 1];
                        v0 = (v0 > 20.f) ? v0 : __logf(1.f + __expf(v0));
                        v1 = (v1 > 20.f) ? v1 : __logf(1.f + __expf(v1));
                    }
                    *(float2*)(Cz + (size_t)r * ldc + col0) = make_float2(v0, v1);
                }
            }
        }
    }
}

// ---------------- conv + SiLU + fp16 split, 4 channels/thread ------------------
__global__ void conv_silu_kernel(const float* __restrict__ xz,
                                 const float* __restrict__ w,
                                 const float* __restrict__ bias,
                                 float* __restrict__ u,
                                 __half* __restrict__ u_hi,
                                 __half* __restrict__ u_lo) {
    int q = blockIdx.x * blockDim.x + threadIdx.x;
    if (q >= NROWS * DINNER / 4) return;
    int cg = q % (DINNER / 4);
    int row = q / (DINNER / 4);
    int t = row % SEQ;
    int b = row / SEQ;
    int c4 = cg * 4;
    int idx4 = q * 4;

    float4 bv = *(const float4*)(bias + c4);
    float acc[4] = { bv.x, bv.y, bv.z, bv.w };
    float4 wr[4];
#pragma unroll
    for (int j = 0; j < 4; j++) wr[j] = *(const float4*)(w + (c4 + j) * 4);

#pragma unroll
    for (int k = 0; k < 4; k++) {
        int tt = t - 3 + k;
        if (tt >= 0) {
            float4 xv = *(const float4*)(xz + ((size_t)(b * SEQ + tt)) * (2 * DINNER) + c4);
            acc[0] += xv.x * ((const float*)&wr[0])[k];
            acc[1] += xv.y * ((const float*)&wr[1])[k];
            acc[2] += xv.z * ((const float*)&wr[2])[k];
            acc[3] += xv.w * ((const float*)&wr[3])[k];
        }
    }
    float v[4];
    __half h[4], l[4];
#pragma unroll
    for (int j = 0; j < 4; j++) {
        v[j] = acc[j] / (1.f + __expf(-acc[j]));
        split_fp16(v[j], h[j], l[j]);
    }
    *(float4*)(u + idx4) = make_float4(v[0], v[1], v[2], v[3]);
    *(__half2*)(u_hi + idx4)     = __halves2half2(h[0], h[1]);
    *(__half2*)(u_hi + idx4 + 2) = __halves2half2(h[2], h[3]);
    *(__half2*)(u_lo + idx4)     = __halves2half2(l[0], l[1]);
    *(__half2*)(u_lo + idx4 + 2) = __halves2half2(l[2], l[3]);
}

// ---------------- split-K reduce for x_proj + dt split ----------------
__global__ void reduce_xdbl_kernel(const float* __restrict__ part,
                                   float* __restrict__ xdbl,
                                   __half* __restrict__ dt_hi,
                                   __half* __restrict__ dt_lo) {
    int idx = blockIdx.x * blockDim.x + threadIdx.x;
    if (idx >= NROWS * DXL) return;
    float v = 0.f;
#pragma unroll
    for (int z = 0; z < KSPLIT; z++) v += part[(size_t)z * NROWS * DXL + idx];
    xdbl[idx] = v;
    int c = idx % DXL;
    if (c < DTRANK) {
        int r = idx / DXL;
        __half h, l;
        split_fp16(v, h, l);
        dt_hi[r * DTRANK + c] = h;
        dt_lo[r * DTRANK + c] = l;
    }
}

// ---------------- selective scan (writes y_hi only) ----------------------
#define SCAN_T 64
__global__ __launch_bounds__(128, 8)
void scan_kernel(const float* __restrict__ delta,
                 const float* __restrict__ xdbl,
                 const float* __restrict__ u,
                 const float* __restrict__ xz,
                 const float* __restrict__ A_log,
                 const float* __restrict__ Dp,
                 __half* __restrict__ y_hi) {
    __shared__ __align__(16) float s_d[SCAN_T][8];
    __shared__ __align__(16) float s_u[SCAN_T][8];
    __shared__ __align__(16) float s_z[SCAN_T][8];
    __shared__ __align__(16) float s_B[SCAN_T][16];
    __shared__ __align__(16) float s_C[SCAN_T][16];

    const int b = blockIdx.y;
    const int d0 = blockIdx.x * 8;
    const int tid = threadIdx.x;
    const int ch = tid >> 4;
    const int n  = tid & 15;
    const int d  = d0 + ch;

    const float Areg = -__expf(A_log[d * DSTATE + n]);
    const float Dreg = Dp[d];
    float h = 0.f;

    for (int t0 = 0; t0 < SEQ; t0 += SCAN_T) {
        {   // d/u/z staging: 64 rows x 2 quads = 128 float4 tasks
            int tt = tid >> 1, qq = (tid & 1) * 4;
            size_t base = (size_t)(b * SEQ + t0 + tt);
            *(float4*)&s_d[tt][qq] = *(const float4*)(delta + base * DINNER + d0 + qq);
            *(float4*)&s_u[tt][qq] = *(const float4*)(u + base * DINNER + d0 + qq);
            *(float4*)&s_z[tt][qq] = *(const float4*)(xz + base * (2 * DINNER) + DINNER + d0 + qq);
        }
#pragma unroll
        for (int rep = 0; rep < 2; rep++) {   // B/C staging: 64 rows x 4 quads = 256 tasks
            int i = tid + rep * 128;
            int tt = i >> 2, qq = (i & 3) * 4;
            size_t base = (size_t)(b * SEQ + t0 + tt);
            *(float4*)&s_B[tt][qq] = *(const float4*)(xdbl + base * DXL + DTRANK + qq);
            *(float4*)&s_C[tt][qq] = *(const float4*)(xdbl + base * DXL + DTRANK + DSTATE + qq);
        }
        __syncthreads();

#pragma unroll 4
        for (int tt = 0; tt < SCAN_T; tt++) {
            float dt = s_d[tt][ch];
            float ut = s_u[tt][ch];
            float dA = __expf(dt * Areg);
            h = dA * h + dt * s_B[tt][n] * ut;
            float part = h * s_C[tt][n];
#pragma unroll
            for (int off = 8; off; off >>= 1)
                part += __shfl_xor_sync(0xFFFFFFFFu, part, off);
            if (n == 0) {
                float yv = part + ut * Dreg;
                float z = s_z[tt][ch];
                yv *= z / (1.f + __expf(-z));
                y_hi[((size_t)(b * SEQ + t0 + tt)) * DINNER + d] = __float2half(yv);
            }
        }
        __syncthreads();
    }
}

// ---------------- launch -------------------------------------------------------
extern "C" void kernel_launch(void* const* d_in, const int* in_sizes, int n_in,
                              void* d_out, int out_size) {
    const float* hs    = (const float*)d_in[0];
    const float* inw   = (const float*)d_in[1];
    const float* convw = (const float*)d_in[2];
    const float* convb = (const float*)d_in[3];
    const float* xpw   = (const float*)d_in[4];
    const float* dtw   = (const float*)d_in[5];
    const float* dtb   = (const float*)d_in[6];
    const float* alog  = (const float*)d_in[7];
    const float* Dp    = (const float*)d_in[8];
    const float* outw  = (const float*)d_in[9];
    float* out = (float*)d_out;

    float *xz, *u, *xdbl, *part, *delta;
    cudaGetSymbolAddress((void**)&xz,    g_xz);
    cudaGetSymbolAddress((void**)&u,     g_u);
    cudaGetSymbolAddress((void**)&xdbl,  g_xdbl);
    cudaGetSymbolAddress((void**)&part,  g_part);
    cudaGetSymbolAddress((void**)&delta, g_delta);

    __half *hs_hi, *inw_hi, *u_hi, *u_lo, *xpw_hi, *dt_hi, *dt_lo, *dtw_hi, *y_hi, *outw_hi;
    cudaGetSymbolAddress((void**)&hs_hi,  g_hs_hi);
    cudaGetSymbolAddress((void**)&inw_hi, g_inw_hi);
    cudaGetSymbolAddress((void**)&u_hi,   g_u_hi);    cudaGetSymbolAddress((void**)&u_lo,   g_u_lo);
    cudaGetSymbolAddress((void**)&xpw_hi, g_xpw_hi);
    cudaGetSymbolAddress((void**)&dt_hi,  g_dt_hi);   cudaGetSymbolAddress((void**)&dt_lo,  g_dt_lo);
    cudaGetSymbolAddress((void**)&dtw_hi, g_dtw_hi);
    cudaGetSymbolAddress((void**)&y_hi,   g_y_hi);
    cudaGetSymbolAddress((void**)&outw_hi,g_outw_hi);

    cudaFuncSetAttribute((const void*)gemm_mma<0,1>, cudaFuncAttributeMaxDynamicSharedMemorySize, SMEM_P1);
    cudaFuncSetAttribute((const void*)gemm_mma<0,2>, cudaFuncAttributeMaxDynamicSharedMemorySize, SMEM_P2);
    cudaFuncSetAttribute((const void*)gemm_mma<1,2>, cudaFuncAttributeMaxDynamicSharedMemorySize, SMEM_P2);

    const int CT = 256;
    // ---- all input conversions in one kernel ----
    cvt_all_kernel<<<CVT_BLOCKS, CT>>>(hs, inw, xpw, dtw, outw,
                                       hs_hi, inw_hi, xpw_hi, dtw_hi, outw_hi);
    // ---- in_proj (1-pass fp16, 4-stage) ----
    gemm_mma<0,1><<<dim3(32, 32), 256, SMEM_P1>>>(hs_hi, nullptr, inw_hi,
                                                  xz, nullptr, DMODEL, 2 * DINNER, 2 * DINNER, DMODEL, 0);
    // ---- conv + silu (+u split), vectorized ----
    conv_silu_kernel<<<(NROWS * DINNER / 4 + CT - 1) / CT, CT>>>(xz, convw, convb, u, u_hi, u_lo);
    // ---- x_proj: split-K=4 (2-pass) ----
    gemm_mma<0,2><<<dim3(1, 32, KSPLIT), 256, SMEM_P2>>>(u_hi, u_lo, xpw_hi,
                                                         part, nullptr, DINNER, DXL, DXL,
                                                         DINNER / KSPLIT, (size_t)NROWS * DXL);
    reduce_xdbl_kernel<<<(NROWS * DXL + CT - 1) / CT, CT>>>(part, xdbl, dt_hi, dt_lo);
    // ---- dt_proj + softplus (2-pass) ----
    gemm_mma<1,2><<<dim3(16, 32), 256, SMEM_P2>>>(dt_hi, dt_lo, dtw_hi,
                                                  delta, dtb, DTRANK, DINNER, DINNER, DTRANK, 0);
    // ---- selective scan (writes y_hi) ----
    scan_kernel<<<dim3(DINNER / 8, BATCH), 128>>>(delta, xdbl, u, xz, alog, Dp, y_hi);
    // ---- out_proj (1-pass fp16, 4-stage) ----
    gemm_mma<0,1><<<dim3(8, 32), 256, SMEM_P1>>>(y_hi, nullptr, outw_hi,
                                                 out, nullptr, DINNER, DMODEL, DMODEL, DINNER, 0);
}

// round 15
// speedup vs baseline: 3.5730x; 1.1187x over previous
#include <cuda_runtime.h>
#include <cuda_bf16.h>
#include <cuda_fp16.h>
#include <math.h>
#include <stdint.h>

#define BATCH 2
#define SEQ 2048
#define DMODEL 1024
#define DINNER 2048
#define DSTATE 16
#define DTRANK 64
#define DXL 96           // DT_RANK + 2*D_STATE
#define NROWS (BATCH*SEQ) // 4096
#define KSPLIT 4

// ---------------- fp32 scratch ----------------
__device__ float g_xz[(size_t)NROWS * 2 * DINNER];
__device__ float g_u[(size_t)NROWS * DINNER];
__device__ float g_xdbl[(size_t)NROWS * DXL];
__device__ float g_part[(size_t)KSPLIT * NROWS * DXL];
__device__ float g_delta[(size_t)NROWS * DINNER];

// ---------------- fp16 scratch ----------------
__device__ __half g_hs_hi[(size_t)NROWS * DMODEL];
__device__ __half g_inw_hi[(size_t)2 * DINNER * DMODEL];
__device__ __half g_u_hi[(size_t)NROWS * DINNER];
__device__ __half g_u_lo[(size_t)NROWS * DINNER];
__device__ __half g_xpw_hi[(size_t)128 * DINNER];
__device__ __half g_dt_hi[(size_t)NROWS * DTRANK];
__device__ __half g_dt_lo[(size_t)NROWS * DTRANK];
__device__ __half g_dtw_hi[(size_t)DINNER * DTRANK];
__device__ __half g_y_hi[(size_t)NROWS * DINNER];
__device__ __half g_outw_hi[(size_t)DMODEL * DINNER];

// ---------------- helpers ----------------
__device__ __forceinline__ uint32_t smem_u32(const void* p) {
    uint32_t a;
    asm("{ .reg .u64 t; cvta.to.shared.u64 t, %1; cvt.u32.u64 %0, t; }" : "=r"(a) : "l"(p));
    return a;
}
__device__ __forceinline__ void split_fp16(float v, __half& h, __half& l) {
    h = __float2half(v);
    l = __float2half(v - __half2float(h));
}
__device__ __forceinline__ void store_hi4(__half* hi, int idx4, float4 v) {
    *(__half2*)(hi + idx4)     = __halves2half2(__float2half(v.x), __float2half(v.y));
    *(__half2*)(hi + idx4 + 2) = __halves2half2(__float2half(v.z), __float2half(v.w));
}

// ---------------- fused input conversion: all 5 tensors, hi only ----------------
#define Q_HS   1048576                       // NROWS*DMODEL/4
#define Q_INW  (Q_HS + 1048576)              // + 2*DINNER*DMODEL/4
#define Q_XPW  (Q_INW + 65536)               // + 128*DINNER/4
#define Q_DTW  (Q_XPW + 32768)               // + DINNER*DTRANK/4
#define Q_OUTW (Q_DTW + 524288)              // + DMODEL*DINNER/4
#define CVT_BLOCKS (Q_OUTW / 256)            // 10624

__global__ void cvt_all_kernel(const float* __restrict__ hs, const float* __restrict__ inw,
                               const float* __restrict__ xpw, const float* __restrict__ dtw,
                               const float* __restrict__ outw,
                               __half* __restrict__ hs_hi, __half* __restrict__ inw_hi,
                               __half* __restrict__ xpw_hi, __half* __restrict__ dtw_hi,
                               __half* __restrict__ outw_hi) {
    int q = blockIdx.x * blockDim.x + threadIdx.x;
    if (q < Q_HS) {
        int idx4 = q * 4;
        store_hi4(hs_hi, idx4, *(const float4*)(hs + idx4));
    } else if (q < Q_INW) {
        int idx4 = (q - Q_HS) * 4;
        store_hi4(inw_hi, idx4, *(const float4*)(inw + idx4));
    } else if (q < Q_XPW) {
        int idx4 = (q - Q_INW) * 4;
        int r = idx4 >> 11;   // / DINNER
        float4 v = (r < DXL) ? *(const float4*)(xpw + idx4) : make_float4(0.f, 0.f, 0.f, 0.f);
        store_hi4(xpw_hi, idx4, v);
    } else if (q < Q_DTW) {
        int idx4 = (q - Q_XPW) * 4;
        store_hi4(dtw_hi, idx4, *(const float4*)(dtw + idx4));
    } else {
        int idx4 = (q - Q_DTW) * 4;
        store_hi4(outw_hi, idx4, *(const float4*)(outw + idx4));
    }
}

// ---------------- classic mma.sync GEMM, fp16 ----------------
// NPASS==1: C = Ah*Bh         -> 2 tiles/stage, 4-stage pipeline
// NPASS==2: C = (Ah+Al)*Bh    -> 3 tiles/stage, 2-stage pipeline
#define RS 40
#define TILE_ELEMS (128 * RS)
#define TILE_BYTES (TILE_ELEMS * 2)    // 10240
#define SMEM_P1 (4 * 2 * TILE_BYTES)   // 81920
#define SMEM_P2 (2 * 3 * TILE_BYTES)   // 61440

#define MMA_OP(ACC, AF, BF) \
    asm volatile("mma.sync.aligned.m16n8k16.row.col.f32.f16.f16.f32 " \
                 "{%0,%1,%2,%3}, {%4,%5,%6,%7}, {%8,%9}, {%0,%1,%2,%3};" \
                 : "+f"((ACC)[0]), "+f"((ACC)[1]), "+f"((ACC)[2]), "+f"((ACC)[3]) \
                 : "r"((AF)[0]), "r"((AF)[1]), "r"((AF)[2]), "r"((AF)[3]), \
                   "r"((BF)[0]), "r"((BF)[1]))

#define LDSM_X4(R0, R1, R2, R3, ADDR) \
    asm volatile("ldmatrix.sync.aligned.m8n8.x4.shared.b16 {%0,%1,%2,%3}, [%4];" \
                 : "=r"(R0), "=r"(R1), "=r"(R2), "=r"(R3) : "r"(ADDR))

template <int EPI, int NPASS>
__global__ __launch_bounds__(256, 2)
void gemm_mma(const __half* __restrict__ Ahi, const __half* __restrict__ Alo,
              const __half* __restrict__ Bhi,
              float* __restrict__ C, const float* __restrict__ bias,
              int K, int ldc, int Nvalid, int Kloop, size_t partStride) {
    extern __shared__ char smem[];
    const uint32_t sb = smem_u32(smem);
    const int tid = threadIdx.x;
    const int wid = tid >> 5, lane = tid & 31;
    const int warp_m = wid >> 2, warp_n = wid & 3;
    const int bm = blockIdx.y * 128, bn = blockIdx.x * 128;
    const int koff = blockIdx.z * Kloop;
    const int NC = Kloop >> 5;

    constexpr int NT = (NPASS == 1) ? 2 : 3;
    constexpr uint32_t SBYTES = (uint32_t)NT * TILE_BYTES;

    uint32_t offA[4], offB[2];
    {
        const int arow = lane & 15;
        const int acol = (lane >> 4) << 3;
#pragma unroll
        for (int mi = 0; mi < 4; mi++)
            offA[mi] = (uint32_t)((warp_m * 64 + mi * 16 + arow) * (RS * 2) + acol * 2);
        const int bcol = ((lane >> 3) & 1) << 3;
#pragma unroll
        for (int p = 0; p < 2; p++) {
            int r = warp_n * 32 + p * 16 + ((lane >> 4) << 3) + (lane & 7);
            offB[p] = (uint32_t)(r * (RS * 2) + bcol * 2);
        }
    }

    float acc[4][4][4];
#pragma unroll
    for (int i = 0; i < 4; i++)
#pragma unroll
        for (int j = 0; j < 4; j++)
#pragma unroll
            for (int q = 0; q < 4; q++) acc[i][j][q] = 0.f;

    auto load_stage = [&](int c, uint32_t sbase) {
        size_t k0 = (size_t)koff + (size_t)c * 32;
        const int NIT = (NPASS == 1) ? 4 : 6;   // 2 cp.asyncs per tile
#pragma unroll
        for (int it = 0; it < NIT; it++) {
            int t = tid + it * 256;
            int tile = t >> 9;
            int s = t & 511;
            int row = s >> 2, seg = s & 3;
            const char* src;
            if (NPASS == 1) {
                if (tile == 0) src = (const char*)(Ahi + (size_t)(bm + row) * K + k0) + seg * 16;
                else           src = (const char*)(Bhi + (size_t)(bn + row) * K + k0) + seg * 16;
            } else {
                if (tile == 0)      src = (const char*)(Ahi + (size_t)(bm + row) * K + k0) + seg * 16;
                else if (tile == 1) src = (const char*)(Alo + (size_t)(bm + row) * K + k0) + seg * 16;
                else                src = (const char*)(Bhi + (size_t)(bn + row) * K + k0) + seg * 16;
            }
            uint32_t dst = sbase + (uint32_t)(tile * TILE_BYTES + row * (RS * 2) + seg * 16);
            asm volatile("cp.async.cg.shared.global [%0], [%1], 16;" :: "r"(dst), "l"(src) : "memory");
        }
        asm volatile("cp.async.commit_group;" ::: "memory");
    };

    auto compute_chunk = [&](uint32_t sbase) {
        const uint32_t aHiB = sbase;
        const uint32_t aLoB = sbase + TILE_BYTES;                            // NPASS==2
        const uint32_t bHiB = (NPASS == 1) ? (sbase + TILE_BYTES) : (sbase + 2 * TILE_BYTES);
#pragma unroll
        for (int ks = 0; ks < 2; ks++) {
            const uint32_t kb = (uint32_t)(ks * 32);
            uint32_t aH[4][4], bH[4][2];
#pragma unroll
            for (int mi = 0; mi < 4; mi++)
                LDSM_X4(aH[mi][0], aH[mi][1], aH[mi][2], aH[mi][3], aHiB + offA[mi] + kb);
#pragma unroll
            for (int p = 0; p < 2; p++)
                LDSM_X4(bH[2*p][0], bH[2*p][1], bH[2*p+1][0], bH[2*p+1][1], bHiB + offB[p] + kb);

            if (NPASS == 2) {
                uint32_t aL[4][4];
#pragma unroll
                for (int mi = 0; mi < 4; mi++)
                    LDSM_X4(aL[mi][0], aL[mi][1], aL[mi][2], aL[mi][3], aLoB + offA[mi] + kb);
#pragma unroll
                for (int mi = 0; mi < 4; mi++)
#pragma unroll
                    for (int ni = 0; ni < 4; ni++) MMA_OP(acc[mi][ni], aH[mi], bH[ni]);
#pragma unroll
                for (int mi = 0; mi < 4; mi++)
#pragma unroll
                    for (int ni = 0; ni < 4; ni++) MMA_OP(acc[mi][ni], aL[mi], bH[ni]);
            } else {
#pragma unroll
                for (int mi = 0; mi < 4; mi++)
#pragma unroll
                    for (int ni = 0; ni < 4; ni++) MMA_OP(acc[mi][ni], aH[mi], bH[ni]);
            }
        }
    };

    if (NPASS == 1) {
        // 4-stage pipeline, one barrier per chunk, prefetch depth 3
        load_stage(0, sb);
        if (NC > 1) load_stage(1, sb + SBYTES);
        if (NC > 2) load_stage(2, sb + 2 * SBYTES);
        int buf = 0;
        for (int c = 0; c < NC; c++) {
            int rem = NC - 1 - c;
            if (rem >= 2)      { asm volatile("cp.async.wait_group 2;" ::: "memory"); }
            else if (rem == 1) { asm volatile("cp.async.wait_group 1;" ::: "memory"); }
            else               { asm volatile("cp.async.wait_group 0;" ::: "memory"); }
            __syncthreads();
            if (c + 3 < NC) {
                int wb = buf + 3; if (wb >= 4) wb -= 4;
                load_stage(c + 3, sb + (uint32_t)wb * SBYTES);
            }
            compute_chunk(sb + (uint32_t)buf * SBYTES);
            if (++buf == 4) buf = 0;
        }
    } else {
        // 2-stage pipeline
        load_stage(0, sb);
        for (int c = 0; c < NC; c++) {
            if (c + 1 < NC) {
                load_stage(c + 1, sb + (uint32_t)((c + 1) & 1) * SBYTES);
                asm volatile("cp.async.wait_group 1;" ::: "memory");
            } else {
                asm volatile("cp.async.wait_group 0;" ::: "memory");
            }
            __syncthreads();
            compute_chunk(sb + (uint32_t)(c & 1) * SBYTES);
            __syncthreads();
        }
    }

    // ---- epilogue ----
    float* Cz = C + partStride * blockIdx.z;
#pragma unroll
    for (int mi = 0; mi < 4; mi++) {
        int row0 = bm + warp_m * 64 + mi * 16 + (lane >> 2);
#pragma unroll
        for (int ni = 0; ni < 4; ni++) {
            int col0 = bn + warp_n * 32 + ni * 8 + ((lane & 3) << 1);
            if (col0 < Nvalid) {
#pragma unroll
                for (int half = 0; half < 2; half++) {
                    int r = row0 + half * 8;
                    float v0 = acc[mi][ni][half * 2 + 0];
                    float v1 = acc[mi][ni][half * 2 + 1];
                    if (EPI == 1) {
                        v0 += bias[col0];
                        v1 += bias[col0 + 1];
                        v0 = (v0 > 20.f) ? v0 : __logf(1.f + __expf(v0));
                        v1 = (v1 > 20.f) ? v1 : __logf(1.f + __expf(v1));
                    }
                    *(float2*)(Cz + (size_t)r * ldc + col0) = make_float2(v0, v1);
                }
            }
        }
    }
}

// ---------------- conv + SiLU + fp16 split, 4 channels/thread ------------------
__global__ void conv_silu_kernel(const float* __restrict__ xz,
                                 const float* __restrict__ w,
                                 const float* __restrict__ bias,
                                 float* __restrict__ u,
                                 __half* __restrict__ u_hi,
                                 __half* __restrict__ u_lo) {
    int q = blockIdx.x * blockDim.x + threadIdx.x;
    if (q >= NROWS * DINNER / 4) return;
    int cg = q % (DINNER / 4);
    int row = q / (DINNER / 4);
    int t = row % SEQ;
    int b = row / SEQ;
    int c4 = cg * 4;
    int idx4 = q * 4;

    float4 bv = *(const float4*)(bias + c4);
    float acc[4] = { bv.x, bv.y, bv.z, bv.w };
    float4 wr[4];
#pragma unroll
    for (int j = 0; j < 4; j++) wr[j] = *(const float4*)(w + (c4 + j) * 4);

#pragma unroll
    for (int k = 0; k < 4; k++) {
        int tt = t - 3 + k;
        if (tt >= 0) {
            float4 xv = *(const float4*)(xz + ((size_t)(b * SEQ + tt)) * (2 * DINNER) + c4);
            acc[0] += xv.x * ((const float*)&wr[0])[k];
            acc[1] += xv.y * ((const float*)&wr[1])[k];
            acc[2] += xv.z * ((const float*)&wr[2])[k];
            acc[3] += xv.w * ((const float*)&wr[3])[k];
        }
    }
    float v[4];
    __half h[4], l[4];
#pragma unroll
    for (int j = 0; j < 4; j++) {
        v[j] = acc[j] / (1.f + __expf(-acc[j]));
        split_fp16(v[j], h[j], l[j]);
    }
    *(float4*)(u + idx4) = make_float4(v[0], v[1], v[2], v[3]);
    *(__half2*)(u_hi + idx4)     = __halves2half2(h[0], h[1]);
    *(__half2*)(u_hi + idx4 + 2) = __halves2half2(h[2], h[3]);
    *(__half2*)(u_lo + idx4)     = __halves2half2(l[0], l[1]);
    *(__half2*)(u_lo + idx4 + 2) = __halves2half2(l[2], l[3]);
}

// ---------------- split-K reduce for x_proj + dt split ----------------
__global__ void reduce_xdbl_kernel(const float* __restrict__ part,
                                   float* __restrict__ xdbl,
                                   __half* __restrict__ dt_hi,
                                   __half* __restrict__ dt_lo) {
    int idx = blockIdx.x * blockDim.x + threadIdx.x;
    if (idx >= NROWS * DXL) return;
    float v = 0.f;
#pragma unroll
    for (int z = 0; z < KSPLIT; z++) v += part[(size_t)z * NROWS * DXL + idx];
    xdbl[idx] = v;
    int c = idx % DXL;
    if (c < DTRANK) {
        int r = idx / DXL;
        __half h, l;
        split_fp16(v, h, l);
        dt_hi[r * DTRANK + c] = h;
        dt_lo[r * DTRANK + c] = l;
    }
}

// ---------------- selective scan: 4 states/lane, 32 ch/block ----------------
#define SCAN_T 64
#define SCAN_CH 32
__global__ __launch_bounds__(128, 4)
void scan_kernel(const float* __restrict__ delta,
                 const float* __restrict__ xdbl,
                 const float* __restrict__ u,
                 const float* __restrict__ xz,
                 const float* __restrict__ A_log,
                 const float* __restrict__ Dp,
                 __half* __restrict__ y_hi) {
    __shared__ __align__(16) float s_d[SCAN_T][SCAN_CH];
    __shared__ __align__(16) float s_u[SCAN_T][SCAN_CH];
    __shared__ __align__(16) float s_z[SCAN_T][SCAN_CH];
    __shared__ __align__(16) float s_B[SCAN_T][DSTATE];
    __shared__ __align__(16) float s_C[SCAN_T][DSTATE];

    const int b = blockIdx.y;
    const int d0 = blockIdx.x * SCAN_CH;
    const int tid = threadIdx.x;
    const int ch = tid >> 2;      // 0..31: channel within block
    const int q  = tid & 3;       // state quad: n = 4q..4q+3
    const int d  = d0 + ch;

    float4 Al = *(const float4*)(A_log + d * DSTATE + q * 4);
    const float A0 = -__expf(Al.x), A1 = -__expf(Al.y), A2 = -__expf(Al.z), A3 = -__expf(Al.w);
    const float Dreg = Dp[d];
    float h0 = 0.f, h1 = 0.f, h2 = 0.f, h3 = 0.f;

    for (int t0 = 0; t0 < SEQ; t0 += SCAN_T) {
#pragma unroll
        for (int rep = 0; rep < 4; rep++) {   // d/u/z: 512 float4 tasks
            int i = tid + rep * 128;
            int tt = i >> 3, cc = (i & 7) * 4;
            size_t base = (size_t)(b * SEQ + t0 + tt);
            *(float4*)&s_d[tt][cc] = *(const float4*)(delta + base * DINNER + d0 + cc);
            *(float4*)&s_u[tt][cc] = *(const float4*)(u + base * DINNER + d0 + cc);
            *(float4*)&s_z[tt][cc] = *(const float4*)(xz + base * (2 * DINNER) + DINNER + d0 + cc);
        }
#pragma unroll
        for (int rep = 0; rep < 2; rep++) {   // B/C: 256 float4 tasks
            int i = tid + rep * 128;
            int tt = i >> 2, cc = (i & 3) * 4;
            size_t base = (size_t)(b * SEQ + t0 + tt);
            *(float4*)&s_B[tt][cc] = *(const float4*)(xdbl + base * DXL + DTRANK + cc);
            *(float4*)&s_C[tt][cc] = *(const float4*)(xdbl + base * DXL + DTRANK + DSTATE + cc);
        }
        __syncthreads();

#pragma unroll 2
        for (int tt = 0; tt < SCAN_T; tt++) {
            float dt = s_d[tt][ch];
            float ut = s_u[tt][ch];
            float4 Bv = *(const float4*)&s_B[tt][q * 4];
            float4 Cv = *(const float4*)&s_C[tt][q * 4];
            float dtu = dt * ut;
            h0 = __expf(dt * A0) * h0 + dtu * Bv.x;
            h1 = __expf(dt * A1) * h1 + dtu * Bv.y;
            h2 = __expf(dt * A2) * h2 + dtu * Bv.z;
            h3 = __expf(dt * A3) * h3 + dtu * Bv.w;
            float part = h0 * Cv.x + h1 * Cv.y + h2 * Cv.z + h3 * Cv.w;
            part += __shfl_xor_sync(0xFFFFFFFFu, part, 1);
            part += __shfl_xor_sync(0xFFFFFFFFu, part, 2);
            if (q == 0) {
                float yv = part + ut * Dreg;
                float z = s_z[tt][ch];
                yv *= z / (1.f + __expf(-z));
                y_hi[((size_t)(b * SEQ + t0 + tt)) * DINNER + d] = __float2half(yv);
            }
        }
        __syncthreads();
    }
}

// ---------------- launch -------------------------------------------------------
extern "C" void kernel_launch(void* const* d_in, const int* in_sizes, int n_in,
                              void* d_out, int out_size) {
    const float* hs    = (const float*)d_in[0];
    const float* inw   = (const float*)d_in[1];
    const float* convw = (const float*)d_in[2];
    const float* convb = (const float*)d_in[3];
    const float* xpw   = (const float*)d_in[4];
    const float* dtw   = (const float*)d_in[5];
    const float* dtb   = (const float*)d_in[6];
    const float* alog  = (const float*)d_in[7];
    const float* Dp    = (const float*)d_in[8];
    const float* outw  = (const float*)d_in[9];
    float* out = (float*)d_out;

    float *xz, *u, *xdbl, *part, *delta;
    cudaGetSymbolAddress((void**)&xz,    g_xz);
    cudaGetSymbolAddress((void**)&u,     g_u);
    cudaGetSymbolAddress((void**)&xdbl,  g_xdbl);
    cudaGetSymbolAddress((void**)&part,  g_part);
    cudaGetSymbolAddress((void**)&delta, g_delta);

    __half *hs_hi, *inw_hi, *u_hi, *u_lo, *xpw_hi, *dt_hi, *dt_lo, *dtw_hi, *y_hi, *outw_hi;
    cudaGetSymbolAddress((void**)&hs_hi,  g_hs_hi);
    cudaGetSymbolAddress((void**)&inw_hi, g_inw_hi);
    cudaGetSymbolAddress((void**)&u_hi,   g_u_hi);    cudaGetSymbolAddress((void**)&u_lo,   g_u_lo);
    cudaGetSymbolAddress((void**)&xpw_hi, g_xpw_hi);
    cudaGetSymbolAddress((void**)&dt_hi,  g_dt_hi);   cudaGetSymbolAddress((void**)&dt_lo,  g_dt_lo);
    cudaGetSymbolAddress((void**)&dtw_hi, g_dtw_hi);
    cudaGetSymbolAddress((void**)&y_hi,   g_y_hi);
    cudaGetSymbolAddress((void**)&outw_hi,g_outw_hi);

    cudaFuncSetAttribute((const void*)gemm_mma<0,1>, cudaFuncAttributeMaxDynamicSharedMemorySize, SMEM_P1);
    cudaFuncSetAttribute((const void*)gemm_mma<0,2>, cudaFuncAttributeMaxDynamicSharedMemorySize, SMEM_P2);
    cudaFuncSetAttribute((const void*)gemm_mma<1,2>, cudaFuncAttributeMaxDynamicSharedMemorySize, SMEM_P2);

    const int CT = 256;
    // ---- all input conversions in one kernel ----
    cvt_all_kernel<<<CVT_BLOCKS, CT>>>(hs, inw, xpw, dtw, outw,
                                       hs_hi, inw_hi, xpw_hi, dtw_hi, outw_hi);
    // ---- in_proj (1-pass fp16, 4-stage) ----
    gemm_mma<0,1><<<dim3(32, 32), 256, SMEM_P1>>>(hs_hi, nullptr, inw_hi,
                                                  xz, nullptr, DMODEL, 2 * DINNER, 2 * DINNER, DMODEL, 0);
    // ---- conv + silu (+u split), vectorized ----
    conv_silu_kernel<<<(NROWS * DINNER / 4 + CT - 1) / CT, CT>>>(xz, convw, convb, u, u_hi, u_lo);
    // ---- x_proj: split-K=4 (2-pass) ----
    gemm_mma<0,2><<<dim3(1, 32, KSPLIT), 256, SMEM_P2>>>(u_hi, u_lo, xpw_hi,
                                                         part, nullptr, DINNER, DXL, DXL,
                                                         DINNER / KSPLIT, (size_t)NROWS * DXL);
    reduce_xdbl_kernel<<<(NROWS * DXL + CT - 1) / CT, CT>>>(part, xdbl, dt_hi, dt_lo);
    // ---- dt_proj + softplus (2-pass) ----
    gemm_mma<1,2><<<dim3(16, 32), 256, SMEM_P2>>>(dt_hi, dt_lo, dtw_hi,
                                                  delta, dtb, DTRANK, DINNER, DINNER, DTRANK, 0);
    // ---- selective scan (4 states/lane) ----
    scan_kernel<<<dim3(DINNER / SCAN_CH, BATCH), 128>>>(delta, xdbl, u, xz, alog, Dp, y_hi);
    // ---- out_proj (1-pass fp16, 4-stage) ----
    gemm_mma<0,1><<<dim3(8, 32), 256, SMEM_P1>>>(y_hi, nullptr, outw_hi,
                                                 out, nullptr, DINNER, DMODEL, DMODEL, DINNER, 0);
}

// round 16
// speedup vs baseline: 3.7127x; 1.0391x over previous
#include <cuda_runtime.h>
#include <cuda_bf16.h>
#include <cuda_fp16.h>
#include <math.h>
#include <stdint.h>

#define BATCH 2
#define SEQ 2048
#define DMODEL 1024
#define DINNER 2048
#define DSTATE 16
#define DTRANK 64
#define DXL 96           // DT_RANK + 2*D_STATE
#define NROWS (BATCH*SEQ) // 4096
#define KSPLIT 4

// ---------------- fp32 scratch ----------------
__device__ float g_xz[(size_t)NROWS * 2 * DINNER];
__device__ float g_u[(size_t)NROWS * DINNER];
__device__ float g_xdbl[(size_t)NROWS * DXL];
__device__ float g_part[(size_t)KSPLIT * NROWS * DXL];
__device__ float g_delta[(size_t)NROWS * DINNER];

// ---------------- fp16 scratch ----------------
__device__ __half g_hs_hi[(size_t)NROWS * DMODEL];
__device__ __half g_inw_hi[(size_t)2 * DINNER * DMODEL];
__device__ __half g_u_hi[(size_t)NROWS * DINNER];
__device__ __half g_u_lo[(size_t)NROWS * DINNER];
__device__ __half g_xpw_hi[(size_t)128 * DINNER];
__device__ __half g_dt_hi[(size_t)NROWS * DTRANK];
__device__ __half g_dt_lo[(size_t)NROWS * DTRANK];
__device__ __half g_dtw_hi[(size_t)DINNER * DTRANK];
__device__ __half g_y_hi[(size_t)NROWS * DINNER];
__device__ __half g_outw_hi[(size_t)DMODEL * DINNER];

// ---------------- helpers ----------------
__device__ __forceinline__ uint32_t smem_u32(const void* p) {
    uint32_t a;
    asm("{ .reg .u64 t; cvta.to.shared.u64 t, %1; cvt.u32.u64 %0, t; }" : "=r"(a) : "l"(p));
    return a;
}
__device__ __forceinline__ void split_fp16(float v, __half& h, __half& l) {
    h = __float2half(v);
    l = __float2half(v - __half2float(h));
}
__device__ __forceinline__ void store_hi4(__half* hi, int idx4, float4 v) {
    *(__half2*)(hi + idx4)     = __halves2half2(__float2half(v.x), __float2half(v.y));
    *(__half2*)(hi + idx4 + 2) = __halves2half2(__float2half(v.z), __float2half(v.w));
}

// ---------------- fused input conversion: all 5 tensors, hi only ----------------
#define Q_HS   1048576
#define Q_INW  (Q_HS + 1048576)
#define Q_XPW  (Q_INW + 65536)
#define Q_DTW  (Q_XPW + 32768)
#define Q_OUTW (Q_DTW + 524288)
#define CVT_BLOCKS (Q_OUTW / 256)

__global__ void cvt_all_kernel(const float* __restrict__ hs, const float* __restrict__ inw,
                               const float* __restrict__ xpw, const float* __restrict__ dtw,
                               const float* __restrict__ outw,
                               __half* __restrict__ hs_hi, __half* __restrict__ inw_hi,
                               __half* __restrict__ xpw_hi, __half* __restrict__ dtw_hi,
                               __half* __restrict__ outw_hi) {
    int q = blockIdx.x * blockDim.x + threadIdx.x;
    if (q < Q_HS) {
        int idx4 = q * 4;
        store_hi4(hs_hi, idx4, *(const float4*)(hs + idx4));
    } else if (q < Q_INW) {
        int idx4 = (q - Q_HS) * 4;
        store_hi4(inw_hi, idx4, *(const float4*)(inw + idx4));
    } else if (q < Q_XPW) {
        int idx4 = (q - Q_INW) * 4;
        int r = idx4 >> 11;
        float4 v = (r < DXL) ? *(const float4*)(xpw + idx4) : make_float4(0.f, 0.f, 0.f, 0.f);
        store_hi4(xpw_hi, idx4, v);
    } else if (q < Q_DTW) {
        int idx4 = (q - Q_XPW) * 4;
        store_hi4(dtw_hi, idx4, *(const float4*)(dtw + idx4));
    } else {
        int idx4 = (q - Q_DTW) * 4;
        store_hi4(outw_hi, idx4, *(const float4*)(outw + idx4));
    }
}

#define RS 40
#define TILE_ELEMS (128 * RS)
#define TILE_BYTES (TILE_ELEMS * 2)    // 10240

#define MMA_OP(ACC, AF, BF) \
    asm volatile("mma.sync.aligned.m16n8k16.row.col.f32.f16.f16.f32 " \
                 "{%0,%1,%2,%3}, {%4,%5,%6,%7}, {%8,%9}, {%0,%1,%2,%3};" \
                 : "+f"((ACC)[0]), "+f"((ACC)[1]), "+f"((ACC)[2]), "+f"((ACC)[3]) \
                 : "r"((AF)[0]), "r"((AF)[1]), "r"((AF)[2]), "r"((AF)[3]), \
                   "r"((BF)[0]), "r"((BF)[1]))

#define LDSM_X4(R0, R1, R2, R3, ADDR) \
    asm volatile("ldmatrix.sync.aligned.m8n8.x4.shared.b16 {%0,%1,%2,%3}, [%4];" \
                 : "=r"(R0), "=r"(R1), "=r"(R2), "=r"(R3) : "r"(ADDR))

// ======== BIG 1-pass GEMM: 128 thr, 4 warps (2x2), warp tile 64x64 ========
// block tile 128x128, 3-stage pipeline, 1 barrier/chunk
#define BIG_SMEM (3 * 2 * TILE_BYTES)   // 61440

__global__ __launch_bounds__(128, 2)
void gemm_big(const __half* __restrict__ Ahi, const __half* __restrict__ Bhi,
              float* __restrict__ C, int K, int ldc) {
    extern __shared__ char smem[];
    const uint32_t sb = smem_u32(smem);
    const int tid = threadIdx.x;
    const int wid = tid >> 5, lane = tid & 31;
    const int warp_m = wid >> 1, warp_n = wid & 1;   // 2 x 2
    const int bm = blockIdx.y * 128, bn = blockIdx.x * 128;
    const int NC = K >> 5;
    constexpr uint32_t SBYTES = 2 * TILE_BYTES;

    uint32_t offA[4], offB[4];
    {
        const int arow = lane & 15;
        const int acol = (lane >> 4) << 3;
#pragma unroll
        for (int mi = 0; mi < 4; mi++)
            offA[mi] = (uint32_t)((warp_m * 64 + mi * 16 + arow) * (RS * 2) + acol * 2);
        const int bcol = ((lane >> 3) & 1) << 3;
#pragma unroll
        for (int p = 0; p < 4; p++) {
            int r = warp_n * 64 + p * 16 + ((lane >> 4) << 3) + (lane & 7);
            offB[p] = (uint32_t)(r * (RS * 2) + bcol * 2);
        }
    }

    float acc[4][8][4];
#pragma unroll
    for (int i = 0; i < 4; i++)
#pragma unroll
        for (int j = 0; j < 8; j++)
#pragma unroll
            for (int q = 0; q < 4; q++) acc[i][j][q] = 0.f;

    auto load_stage = [&](int c, uint32_t sbase) {
        size_t k0 = (size_t)c * 32;
#pragma unroll
        for (int it = 0; it < 8; it++) {
            int t = tid + it * 128;
            int tile = t >> 9;
            int s = t & 511;
            int row = s >> 2, seg = s & 3;
            const char* src = (tile == 0)
                ? (const char*)(Ahi + (size_t)(bm + row) * K + k0) + seg * 16
                : (const char*)(Bhi + (size_t)(bn + row) * K + k0) + seg * 16;
            uint32_t dst = sbase + (uint32_t)(tile * TILE_BYTES + row * (RS * 2) + seg * 16);
            asm volatile("cp.async.cg.shared.global [%0], [%1], 16;" :: "r"(dst), "l"(src) : "memory");
        }
        asm volatile("cp.async.commit_group;" ::: "memory");
    };

    load_stage(0, sb);
    if (NC > 1) load_stage(1, sb + SBYTES);
    int buf = 0;
    for (int c = 0; c < NC; c++) {
        if (c + 1 < NC) { asm volatile("cp.async.wait_group 1;" ::: "memory"); }
        else            { asm volatile("cp.async.wait_group 0;" ::: "memory"); }
        __syncthreads();
        if (c + 2 < NC) {
            int wb = buf + 2; if (wb >= 3) wb -= 3;
            load_stage(c + 2, sb + (uint32_t)wb * SBYTES);
        }
        uint32_t sbase = sb + (uint32_t)buf * SBYTES;
        const uint32_t aB = sbase, bB = sbase + TILE_BYTES;
#pragma unroll
        for (int ks = 0; ks < 2; ks++) {
            const uint32_t kb = (uint32_t)(ks * 32);
            uint32_t aH[4][4], bH[8][2];
#pragma unroll
            for (int mi = 0; mi < 4; mi++)
                LDSM_X4(aH[mi][0], aH[mi][1], aH[mi][2], aH[mi][3], aB + offA[mi] + kb);
#pragma unroll
            for (int p = 0; p < 4; p++)
                LDSM_X4(bH[2*p][0], bH[2*p][1], bH[2*p+1][0], bH[2*p+1][1], bB + offB[p] + kb);
#pragma unroll
            for (int mi = 0; mi < 4; mi++)
#pragma unroll
                for (int ni = 0; ni < 8; ni++) MMA_OP(acc[mi][ni], aH[mi], bH[ni]);
        }
        if (++buf == 3) buf = 0;
    }

    // ---- epilogue ----
#pragma unroll
    for (int mi = 0; mi < 4; mi++) {
        int row0 = bm + warp_m * 64 + mi * 16 + (lane >> 2);
#pragma unroll
        for (int ni = 0; ni < 8; ni++) {
            int col0 = bn + warp_n * 64 + ni * 8 + ((lane & 3) << 1);
#pragma unroll
            for (int half = 0; half < 2; half++) {
                int r = row0 + half * 8;
                *(float2*)(C + (size_t)r * ldc + col0) =
                    make_float2(acc[mi][ni][half * 2 + 0], acc[mi][ni][half * 2 + 1]);
            }
        }
    }
}

// ======== small GEMM (2-pass), 256 thr, warp tile 64x32, 2-stage ========
#define SMEM_P2 (2 * 3 * TILE_BYTES)   // 61440

template <int EPI>
__global__ __launch_bounds__(256, 2)
void gemm_mma(const __half* __restrict__ Ahi, const __half* __restrict__ Alo,
              const __half* __restrict__ Bhi,
              float* __restrict__ C, const float* __restrict__ bias,
              int K, int ldc, int Nvalid, int Kloop, size_t partStride) {
    extern __shared__ char smem[];
    const uint32_t sb = smem_u32(smem);
    const int tid = threadIdx.x;
    const int wid = tid >> 5, lane = tid & 31;
    const int warp_m = wid >> 2, warp_n = wid & 3;
    const int bm = blockIdx.y * 128, bn = blockIdx.x * 128;
    const int koff = blockIdx.z * Kloop;
    const int NC = Kloop >> 5;
    constexpr uint32_t SBYTES = 3 * TILE_BYTES;

    uint32_t offA[4], offB[2];
    {
        const int arow = lane & 15;
        const int acol = (lane >> 4) << 3;
#pragma unroll
        for (int mi = 0; mi < 4; mi++)
            offA[mi] = (uint32_t)((warp_m * 64 + mi * 16 + arow) * (RS * 2) + acol * 2);
        const int bcol = ((lane >> 3) & 1) << 3;
#pragma unroll
        for (int p = 0; p < 2; p++) {
            int r = warp_n * 32 + p * 16 + ((lane >> 4) << 3) + (lane & 7);
            offB[p] = (uint32_t)(r * (RS * 2) + bcol * 2);
        }
    }

    float acc[4][4][4];
#pragma unroll
    for (int i = 0; i < 4; i++)
#pragma unroll
        for (int j = 0; j < 4; j++)
#pragma unroll
            for (int q = 0; q < 4; q++) acc[i][j][q] = 0.f;

    auto load_stage = [&](int c, uint32_t sbase) {
        size_t k0 = (size_t)koff + (size_t)c * 32;
#pragma unroll
        for (int it = 0; it < 6; it++) {
            int t = tid + it * 256;
            int tile = t >> 9;
            int s = t & 511;
            int row = s >> 2, seg = s & 3;
            const char* src;
            if (tile == 0)      src = (const char*)(Ahi + (size_t)(bm + row) * K + k0) + seg * 16;
            else if (tile == 1) src = (const char*)(Alo + (size_t)(bm + row) * K + k0) + seg * 16;
            else                src = (const char*)(Bhi + (size_t)(bn + row) * K + k0) + seg * 16;
            uint32_t dst = sbase + (uint32_t)(tile * TILE_BYTES + row * (RS * 2) + seg * 16);
            asm volatile("cp.async.cg.shared.global [%0], [%1], 16;" :: "r"(dst), "l"(src) : "memory");
        }
        asm volatile("cp.async.commit_group;" ::: "memory");
    };

    load_stage(0, sb);
    for (int c = 0; c < NC; c++) {
        if (c + 1 < NC) {
            load_stage(c + 1, sb + (uint32_t)((c + 1) & 1) * SBYTES);
            asm volatile("cp.async.wait_group 1;" ::: "memory");
        } else {
            asm volatile("cp.async.wait_group 0;" ::: "memory");
        }
        __syncthreads();
        uint32_t sbase = sb + (uint32_t)(c & 1) * SBYTES;
        const uint32_t aHiB = sbase, aLoB = sbase + TILE_BYTES, bHiB = sbase + 2 * TILE_BYTES;
#pragma unroll
        for (int ks = 0; ks < 2; ks++) {
            const uint32_t kb = (uint32_t)(ks * 32);
            uint32_t aH[4][4], bH[4][2];
#pragma unroll
            for (int mi = 0; mi < 4; mi++)
                LDSM_X4(aH[mi][0], aH[mi][1], aH[mi][2], aH[mi][3], aHiB + offA[mi] + kb);
#pragma unroll
            for (int p = 0; p < 2; p++)
                LDSM_X4(bH[2*p][0], bH[2*p][1], bH[2*p+1][0], bH[2*p+1][1], bHiB + offB[p] + kb);
            uint32_t aL[4][4];
#pragma unroll
            for (int mi = 0; mi < 4; mi++)
                LDSM_X4(aL[mi][0], aL[mi][1], aL[mi][2], aL[mi][3], aLoB + offA[mi] + kb);
#pragma unroll
            for (int mi = 0; mi < 4; mi++)
#pragma unroll
                for (int ni = 0; ni < 4; ni++) MMA_OP(acc[mi][ni], aH[mi], bH[ni]);
#pragma unroll
            for (int mi = 0; mi < 4; mi++)
#pragma unroll
                for (int ni = 0; ni < 4; ni++) MMA_OP(acc[mi][ni], aL[mi], bH[ni]);
        }
        __syncthreads();
    }

    float* Cz = C + partStride * blockIdx.z;
#pragma unroll
    for (int mi = 0; mi < 4; mi++) {
        int row0 = bm + warp_m * 64 + mi * 16 + (lane >> 2);
#pragma unroll
        for (int ni = 0; ni < 4; ni++) {
            int col0 = bn + warp_n * 32 + ni * 8 + ((lane & 3) << 1);
            if (col0 < Nvalid) {
#pragma unroll
                for (int half = 0; half < 2; half++) {
                    int r = row0 + half * 8;
                    float v0 = acc[mi][ni][half * 2 + 0];
                    float v1 = acc[mi][ni][half * 2 + 1];
                    if (EPI == 1) {
                        v0 += bias[col0];
                        v1 += bias[col0 + 1];
                        v0 = (v0 > 20.f) ? v0 : __logf(1.f + __expf(v0));
                        v1 = (v1 > 20.f) ? v1 : __logf(1.f + __expf(v1));
                    }
                    *(float2*)(Cz + (size_t)r * ldc + col0) = make_float2(v0, v1);
                }
            }
        }
    }
}

// ---------------- conv + SiLU + fp16 split, 4 channels/thread ------------------
__global__ void conv_silu_kernel(const float* __restrict__ xz,
                                 const float* __restrict__ w,
                                 const float* __restrict__ bias,
                                 float* __restrict__ u,
                                 __half* __restrict__ u_hi,
                                 __half* __restrict__ u_lo) {
    int q = blockIdx.x * blockDim.x + threadIdx.x;
    if (q >= NROWS * DINNER / 4) return;
    int cg = q % (DINNER / 4);
    int row = q / (DINNER / 4);
    int t = row % SEQ;
    int b = row / SEQ;
    int c4 = cg * 4;
    int idx4 = q * 4;

    float4 bv = *(const float4*)(bias + c4);
    float acc[4] = { bv.x, bv.y, bv.z, bv.w };
    float4 wr[4];
#pragma unroll
    for (int j = 0; j < 4; j++) wr[j] = *(const float4*)(w + (c4 + j) * 4);

#pragma unroll
    for (int k = 0; k < 4; k++) {
        int tt = t - 3 + k;
        if (tt >= 0) {
            float4 xv = *(const float4*)(xz + ((size_t)(b * SEQ + tt)) * (2 * DINNER) + c4);
            acc[0] += xv.x * ((const float*)&wr[0])[k];
            acc[1] += xv.y * ((const float*)&wr[1])[k];
            acc[2] += xv.z * ((const float*)&wr[2])[k];
            acc[3] += xv.w * ((const float*)&wr[3])[k];
        }
    }
    float v[4];
    __half h[4], l[4];
#pragma unroll
    for (int j = 0; j < 4; j++) {
        v[j] = acc[j] / (1.f + __expf(-acc[j]));
        split_fp16(v[j], h[j], l[j]);
    }
    *(float4*)(u + idx4) = make_float4(v[0], v[1], v[2], v[3]);
    *(__half2*)(u_hi + idx4)     = __halves2half2(h[0], h[1]);
    *(__half2*)(u_hi + idx4 + 2) = __halves2half2(h[2], h[3]);
    *(__half2*)(u_lo + idx4)     = __halves2half2(l[0], l[1]);
    *(__half2*)(u_lo + idx4 + 2) = __halves2half2(l[2], l[3]);
}

// ---------------- split-K reduce for x_proj + dt split ----------------
__global__ void reduce_xdbl_kernel(const float* __restrict__ part,
                                   float* __restrict__ xdbl,
                                   __half* __restrict__ dt_hi,
                                   __half* __restrict__ dt_lo) {
    int idx = blockIdx.x * blockDim.x + threadIdx.x;
    if (idx >= NROWS * DXL) return;
    float v = 0.f;
#pragma unroll
    for (int z = 0; z < KSPLIT; z++) v += part[(size_t)z * NROWS * DXL + idx];
    xdbl[idx] = v;
    int c = idx % DXL;
    if (c < DTRANK) {
        int r = idx / DXL;
        __half h, l;
        split_fp16(v, h, l);
        dt_hi[r * DTRANK + c] = h;
        dt_lo[r * DTRANK + c] = l;
    }
}

// ---------------- selective scan: 4 states/lane, 32 ch/block ----------------
#define SCAN_T 64
#define SCAN_CH 32
__global__ __launch_bounds__(128, 4)
void scan_kernel(const float* __restrict__ delta,
                 const float* __restrict__ xdbl,
                 const float* __restrict__ u,
                 const float* __restrict__ xz,
                 const float* __restrict__ A_log,
                 const float* __restrict__ Dp,
                 __half* __restrict__ y_hi) {
    __shared__ __align__(16) float s_d[SCAN_T][SCAN_CH];
    __shared__ __align__(16) float s_u[SCAN_T][SCAN_CH];
    __shared__ __align__(16) float s_z[SCAN_T][SCAN_CH];
    __shared__ __align__(16) float s_B[SCAN_T][DSTATE];
    __shared__ __align__(16) float s_C[SCAN_T][DSTATE];

    const int b = blockIdx.y;
    const int d0 = blockIdx.x * SCAN_CH;
    const int tid = threadIdx.x;
    const int ch = tid >> 2;
    const int q  = tid & 3;
    const int d  = d0 + ch;

    float4 Al = *(const float4*)(A_log + d * DSTATE + q * 4);
    const float A0 = -__expf(Al.x), A1 = -__expf(Al.y), A2 = -__expf(Al.z), A3 = -__expf(Al.w);
    const float Dreg = Dp[d];
    float h0 = 0.f, h1 = 0.f, h2 = 0.f, h3 = 0.f;

    for (int t0 = 0; t0 < SEQ; t0 += SCAN_T) {
#pragma unroll
        for (int rep = 0; rep < 4; rep++) {
            int i = tid + rep * 128;
            int tt = i >> 3, cc = (i & 7) * 4;
            size_t base = (size_t)(b * SEQ + t0 + tt);
            *(float4*)&s_d[tt][cc] = *(const float4*)(delta + base * DINNER + d0 + cc);
            *(float4*)&s_u[tt][cc] = *(const float4*)(u + base * DINNER + d0 + cc);
            *(float4*)&s_z[tt][cc] = *(const float4*)(xz + base * (2 * DINNER) + DINNER + d0 + cc);
        }
#pragma unroll
        for (int rep = 0; rep < 2; rep++) {
            int i = tid + rep * 128;
            int tt = i >> 2, cc = (i & 3) * 4;
            size_t base = (size_t)(b * SEQ + t0 + tt);
            *(float4*)&s_B[tt][cc] = *(const float4*)(xdbl + base * DXL + DTRANK + cc);
            *(float4*)&s_C[tt][cc] = *(const float4*)(xdbl + base * DXL + DTRANK + DSTATE + cc);
        }
        __syncthreads();

#pragma unroll 2
        for (int tt = 0; tt < SCAN_T; tt++) {
            float dt = s_d[tt][ch];
            float ut = s_u[tt][ch];
            float4 Bv = *(const float4*)&s_B[tt][q * 4];
            float4 Cv = *(const float4*)&s_C[tt][q * 4];
            float dtu = dt * ut;
            h0 = __expf(dt * A0) * h0 + dtu * Bv.x;
            h1 = __expf(dt * A1) * h1 + dtu * Bv.y;
            h2 = __expf(dt * A2) * h2 + dtu * Bv.z;
            h3 = __expf(dt * A3) * h3 + dtu * Bv.w;
            float part = h0 * Cv.x + h1 * Cv.y + h2 * Cv.z + h3 * Cv.w;
            part += __shfl_xor_sync(0xFFFFFFFFu, part, 1);
            part += __shfl_xor_sync(0xFFFFFFFFu, part, 2);
            if (q == 0) {
                float yv = part + ut * Dreg;
                float z = s_z[tt][ch];
                yv *= z / (1.f + __expf(-z));
                y_hi[((size_t)(b * SEQ + t0 + tt)) * DINNER + d] = __float2half(yv);
            }
        }
        __syncthreads();
    }
}

// ---------------- launch -------------------------------------------------------
extern "C" void kernel_launch(void* const* d_in, const int* in_sizes, int n_in,
                              void* d_out, int out_size) {
    const float* hs    = (const float*)d_in[0];
    const float* inw   = (const float*)d_in[1];
    const float* convw = (const float*)d_in[2];
    const float* convb = (const float*)d_in[3];
    const float* xpw   = (const float*)d_in[4];
    const float* dtw   = (const float*)d_in[5];
    const float* dtb   = (const float*)d_in[6];
    const float* alog  = (const float*)d_in[7];
    const float* Dp    = (const float*)d_in[8];
    const float* outw  = (const float*)d_in[9];
    float* out = (float*)d_out;

    float *xz, *u, *xdbl, *part, *delta;
    cudaGetSymbolAddress((void**)&xz,    g_xz);
    cudaGetSymbolAddress((void**)&u,     g_u);
    cudaGetSymbolAddress((void**)&xdbl,  g_xdbl);
    cudaGetSymbolAddress((void**)&part,  g_part);
    cudaGetSymbolAddress((void**)&delta, g_delta);

    __half *hs_hi, *inw_hi, *u_hi, *u_lo, *xpw_hi, *dt_hi, *dt_lo, *dtw_hi, *y_hi, *outw_hi;
    cudaGetSymbolAddress((void**)&hs_hi,  g_hs_hi);
    cudaGetSymbolAddress((void**)&inw_hi, g_inw_hi);
    cudaGetSymbolAddress((void**)&u_hi,   g_u_hi);    cudaGetSymbolAddress((void**)&u_lo,   g_u_lo);
    cudaGetSymbolAddress((void**)&xpw_hi, g_xpw_hi);
    cudaGetSymbolAddress((void**)&dt_hi,  g_dt_hi);   cudaGetSymbolAddress((void**)&dt_lo,  g_dt_lo);
    cudaGetSymbolAddress((void**)&dtw_hi, g_dtw_hi);
    cudaGetSymbolAddress((void**)&y_hi,   g_y_hi);
    cudaGetSymbolAddress((void**)&outw_hi,g_outw_hi);

    cudaFuncSetAttribute((const void*)gemm_big,    cudaFuncAttributeMaxDynamicSharedMemorySize, BIG_SMEM);
    cudaFuncSetAttribute((const void*)gemm_mma<0>, cudaFuncAttributeMaxDynamicSharedMemorySize, SMEM_P2);
    cudaFuncSetAttribute((const void*)gemm_mma<1>, cudaFuncAttributeMaxDynamicSharedMemorySize, SMEM_P2);

    const int CT = 256;
    // ---- all input conversions in one kernel ----
    cvt_all_kernel<<<CVT_BLOCKS, CT>>>(hs, inw, xpw, dtw, outw,
                                       hs_hi, inw_hi, xpw_hi, dtw_hi, outw_hi);
    // ---- in_proj (1-pass, 64x64 warp tiles) ----
    gemm_big<<<dim3(32, 32), 128, BIG_SMEM>>>(hs_hi, inw_hi, xz, DMODEL, 2 * DINNER);
    // ---- conv + silu (+u split) ----
    conv_silu_kernel<<<(NROWS * DINNER / 4 + CT - 1) / CT, CT>>>(xz, convw, convb, u, u_hi, u_lo);
    // ---- x_proj: split-K=4 (2-pass) ----
    gemm_mma<0><<<dim3(1, 32, KSPLIT), 256, SMEM_P2>>>(u_hi, u_lo, xpw_hi,
                                                       part, nullptr, DINNER, DXL, DXL,
                                                       DINNER / KSPLIT, (size_t)NROWS * DXL);
    reduce_xdbl_kernel<<<(NROWS * DXL + CT - 1) / CT, CT>>>(part, xdbl, dt_hi, dt_lo);
    // ---- dt_proj + softplus (2-pass) ----
    gemm_mma<1><<<dim3(16, 32), 256, SMEM_P2>>>(dt_hi, dt_lo, dtw_hi,
                                                delta, dtb, DTRANK, DINNER, DINNER, DTRANK, 0);
    // ---- selective scan (4 states/lane) ----
    scan_kernel<<<dim3(DINNER / SCAN_CH, BATCH), 128>>>(delta, xdbl, u, xz, alog, Dp, y_hi);
    // ---- out_proj (1-pass, 64x64 warp tiles) ----
    gemm_big<<<dim3(8, 32), 128, BIG_SMEM>>>(y_hi, outw_hi, out, DINNER, DMODEL);
}